// round 2
// baseline (speedup 1.0000x reference)
#include <cuda_runtime.h>
#include <cuda_bf16.h>
#include <float.h>

#define Bz   8
#define Lz   1024
#define Ez   512
#define Hz   8
#define Dz   64

// ---------------- device scratch ----------------
__device__ float g_mf[Bz*Lz];
__device__ int   g_maskKind;
__device__ float g_act[Lz*Lz];
__device__ float g_Q [Bz*Lz*Ez];
__device__ float g_K [Bz*Lz*Ez];
__device__ float g_V [Bz*Lz*Ez];
__device__ float g_Vm[Bz*Lz*Ez];
__device__ float g_U [Bz*Lz*Ez];
__device__ float g_GAV[Bz*Lz*Ez];
__device__ float g_Spart[Bz*Hz*16];
__device__ float g_Gpart[Bz*Lz];
__device__ float g_S[Bz];
__device__ float g_gs[Bz];
__device__ float g_rs0[Bz*Lz];
__device__ float g_rs1[Bz*Lz];

// ---------------- mask dtype detection + convert ----------------
__global__ void detect_mask(const unsigned char* m) {
    bool isInt32 = true;
    for (int i = 0; i < 64; i++) {
        if (m[4*i] > 1) isInt32 = false;
        if (m[4*i+1] | m[4*i+2] | m[4*i+3]) isInt32 = false;
    }
    if (isInt32) { g_maskKind = 0; return; }
    const unsigned int* w = (const unsigned int*)m;
    bool isFloat = true;
    for (int i = 0; i < 64; i++) {
        unsigned v = w[i];
        if (v != 0u && v != 0x3F800000u) isFloat = false;
    }
    g_maskKind = isFloat ? 2 : 1;
}

__global__ void convert_mask(const void* m) {
    int i = blockIdx.x*256 + threadIdx.x;
    if (i >= Bz*Lz) return;
    int k = g_maskKind;
    float v;
    if (k == 0)      v = ((const int*)m)[i] ? 1.f : 0.f;
    else if (k == 1) v = ((const unsigned char*)m)[i] ? 1.f : 0.f;
    else             v = ((const float*)m)[i];
    g_mf[i] = v;
}

// ---------------- softmax of G rows -> g_act ----------------
__global__ __launch_bounds__(256) void softmax_g(const float* __restrict__ G) {
    int q = blockIdx.x, t = threadIdx.x;
    const float* row = G + (size_t)q*Lz;
    __shared__ float red[256];
    float mx = -FLT_MAX;
    for (int k = t; k < Lz; k += 256) mx = fmaxf(mx, row[k]);
    red[t] = mx; __syncthreads();
    for (int s = 128; s > 0; s >>= 1) { if (t < s) red[t] = fmaxf(red[t], red[t+s]); __syncthreads(); }
    mx = red[0]; __syncthreads();
    float vals[4]; float sum = 0.f;
    for (int k = t, j = 0; k < Lz; k += 256, j++) { float e = __expf(row[k]-mx); vals[j] = e; sum += e; }
    red[t] = sum; __syncthreads();
    for (int s = 128; s > 0; s >>= 1) { if (t < s) red[t] += red[t+s]; __syncthreads(); }
    float inv = 1.f / red[0];
    for (int k = t, j = 0; k < Lz; k += 256, j++) g_act[(size_t)q*Lz + k] = vals[j]*inv;
}

// gsum rows: g_Gpart[b*L+q] = mf[b,q] * sum_k act[q,k]*mf[b,k]
__global__ __launch_bounds__(256) void gsum_rows() {
    int q = blockIdx.x, b = blockIdx.y, t = threadIdx.x;
    __shared__ float red[256];
    const float* arow = g_act + (size_t)q*Lz;
    const float* mf = g_mf + b*Lz;
    float s = 0.f;
    for (int k = t; k < Lz; k += 256) s += arow[k]*mf[k];
    red[t] = s; __syncthreads();
    for (int st = 128; st > 0; st >>= 1) { if (t < st) red[t] += red[t+st]; __syncthreads(); }
    if (t == 0) g_Gpart[b*Lz + q] = red[0] * mf[q];
}

__global__ __launch_bounds__(256) void reduce_parts(int which) {
    int b = blockIdx.x, t = threadIdx.x;
    __shared__ float red[256];
    float s = 0.f;
    if (which == 0) { for (int i = t; i < Hz*16; i += 256) s += g_Spart[b*Hz*16 + i]; }
    else            { for (int i = t; i < Lz;    i += 256) s += g_Gpart[b*Lz + i]; }
    red[t] = s; __syncthreads();
    for (int st = 128; st > 0; st >>= 1) { if (t < st) red[t] += red[t+st]; __syncthreads(); }
    if (t == 0) { if (which == 0) g_S[b] = red[0]; else g_gs[b] = red[0]; }
}

__global__ void rowscales() {
    int i = blockIdx.x*256 + threadIdx.x;
    if (i >= Bz*Lz) return;
    int b = i >> 10;
    const float TINY = 1.175494351e-38f;
    float mf = g_mf[i];
    g_rs0[i] = 0.5f*mf / fmaxf(g_S[b],  TINY);
    g_rs1[i] = 0.5f*mf / fmaxf(g_gs[b], TINY);
}

// Vm = mf_k * V (per row)
__global__ void mask_v() {
    size_t i = (size_t)blockIdx.x*256 + threadIdx.x;       // over float4s
    if (i >= (size_t)Bz*Lz*Ez/4) return;
    float4 v = ((const float4*)g_V)[i];
    float m = g_mf[(i*4) >> 9];
    ((float4*)g_Vm)[i] = make_float4(v.x*m, v.y*m, v.z*m, v.w*m);
}

// ---------------- SGEMM 128x128x8, 256 threads, 8x8/thread ----------------
// C (MxN) = A (MxK, rowmajor) @ B^T (B is NxK rowmajor)
__global__ __launch_bounds__(256) void gemm_abt(const float* __restrict__ A, const float* __restrict__ B,
                                                float* __restrict__ C, int M, int N, int K) {
    __shared__ float As[8][132];
    __shared__ float Bs[8][132];
    int bn = blockIdx.x*128, bm = blockIdx.y*128;
    int tid = threadIdx.x;
    int tx = tid & 15, ty = tid >> 4;
    int lr = tid >> 1, lk = (tid & 1) * 4;
    const float* Ag = A + (size_t)(bm+lr)*K + lk;
    const float* Bg = B + (size_t)(bn+lr)*K + lk;
    float acc[8][8] = {};
    for (int k0 = 0; k0 < K; k0 += 8) {
        float4 a  = *(const float4*)(Ag + k0);
        float4 bv = *(const float4*)(Bg + k0);
        As[lk+0][lr]=a.x;  As[lk+1][lr]=a.y;  As[lk+2][lr]=a.z;  As[lk+3][lr]=a.w;
        Bs[lk+0][lr]=bv.x; Bs[lk+1][lr]=bv.y; Bs[lk+2][lr]=bv.z; Bs[lk+3][lr]=bv.w;
        __syncthreads();
        #pragma unroll
        for (int kk = 0; kk < 8; kk++) {
            float ar[8], br[8];
            *(float4*)ar     = *(const float4*)&As[kk][ty*8];
            *(float4*)(ar+4) = *(const float4*)&As[kk][ty*8+4];
            *(float4*)br     = *(const float4*)&Bs[kk][tx*8];
            *(float4*)(br+4) = *(const float4*)&Bs[kk][tx*8+4];
            #pragma unroll
            for (int i = 0; i < 8; i++)
                #pragma unroll
                for (int j = 0; j < 8; j++) acc[i][j] += ar[i]*br[j];
        }
        __syncthreads();
    }
    #pragma unroll
    for (int i = 0; i < 8; i++) {
        float* Cr = C + (size_t)(bm+ty*8+i)*N + bn + tx*8;
        *(float4*)Cr     = make_float4(acc[i][0],acc[i][1],acc[i][2],acc[i][3]);
        *(float4*)(Cr+4) = make_float4(acc[i][4],acc[i][5],acc[i][6],acc[i][7]);
    }
}

// C_z (MxN) = A (MxK) @ B_z (KxN rowmajor), z = batch
__global__ __launch_bounds__(256) void gemm_ab_batched(const float* __restrict__ A, const float* __restrict__ B,
                                                       float* __restrict__ C, int M, int N, int K) {
    __shared__ float As[8][132];
    __shared__ float Bs[8][132];
    int z = blockIdx.z;
    const float* Bp = B + (size_t)z*K*N;
    float* Cp = C + (size_t)z*M*N;
    int bn = blockIdx.x*128, bm = blockIdx.y*128;
    int tid = threadIdx.x;
    int tx = tid & 15, ty = tid >> 4;
    int lr = tid >> 1, lk = (tid & 1) * 4;
    int bk = tid >> 5, n4 = (tid & 31) * 4;
    const float* Ag = A + (size_t)(bm+lr)*K + lk;
    float acc[8][8] = {};
    for (int k0 = 0; k0 < K; k0 += 8) {
        float4 a = *(const float4*)(Ag + k0);
        As[lk+0][lr]=a.x; As[lk+1][lr]=a.y; As[lk+2][lr]=a.z; As[lk+3][lr]=a.w;
        float4 bv = *(const float4*)(Bp + (size_t)(k0+bk)*N + bn + n4);
        *(float4*)&Bs[bk][n4] = bv;
        __syncthreads();
        #pragma unroll
        for (int kk = 0; kk < 8; kk++) {
            float ar[8], br[8];
            *(float4*)ar     = *(const float4*)&As[kk][ty*8];
            *(float4*)(ar+4) = *(const float4*)&As[kk][ty*8+4];
            *(float4*)br     = *(const float4*)&Bs[kk][tx*8];
            *(float4*)(br+4) = *(const float4*)&Bs[kk][tx*8+4];
            #pragma unroll
            for (int i = 0; i < 8; i++)
                #pragma unroll
                for (int j = 0; j < 8; j++) acc[i][j] += ar[i]*br[j];
        }
        __syncthreads();
    }
    #pragma unroll
    for (int i = 0; i < 8; i++) {
        float* Cr = Cp + (size_t)(bm+ty*8+i)*N + bn + tx*8;
        *(float4*)Cr     = make_float4(acc[i][0],acc[i][1],acc[i][2],acc[i][3]);
        *(float4*)(Cr+4) = make_float4(acc[i][4],acc[i][5],acc[i][6],acc[i][7]);
    }
}

// Out = (rs0*U + rs1*GAV) @ Wo^T, fused A construction
__global__ __launch_bounds__(256) void gemm_out(const float* __restrict__ U, const float* __restrict__ Gv,
                                                const float* __restrict__ B, float* __restrict__ C,
                                                int M, int N, int K) {
    __shared__ float As[8][132];
    __shared__ float Bs[8][132];
    int bn = blockIdx.x*128, bm = blockIdx.y*128;
    int tid = threadIdx.x;
    int tx = tid & 15, ty = tid >> 4;
    int lr = tid >> 1, lk = (tid & 1) * 4;
    float r0 = g_rs0[bm+lr], r1 = g_rs1[bm+lr];
    const float* Ug = U  + (size_t)(bm+lr)*K + lk;
    const float* Gg = Gv + (size_t)(bm+lr)*K + lk;
    const float* Bg = B  + (size_t)(bn+lr)*K + lk;
    float acc[8][8] = {};
    for (int k0 = 0; k0 < K; k0 += 8) {
        float4 u  = *(const float4*)(Ug + k0);
        float4 g  = *(const float4*)(Gg + k0);
        float4 bv = *(const float4*)(Bg + k0);
        As[lk+0][lr]=r0*u.x+r1*g.x; As[lk+1][lr]=r0*u.y+r1*g.y;
        As[lk+2][lr]=r0*u.z+r1*g.z; As[lk+3][lr]=r0*u.w+r1*g.w;
        Bs[lk+0][lr]=bv.x; Bs[lk+1][lr]=bv.y; Bs[lk+2][lr]=bv.z; Bs[lk+3][lr]=bv.w;
        __syncthreads();
        #pragma unroll
        for (int kk = 0; kk < 8; kk++) {
            float ar[8], br[8];
            *(float4*)ar     = *(const float4*)&As[kk][ty*8];
            *(float4*)(ar+4) = *(const float4*)&As[kk][ty*8+4];
            *(float4*)br     = *(const float4*)&Bs[kk][tx*8];
            *(float4*)(br+4) = *(const float4*)&Bs[kk][tx*8+4];
            #pragma unroll
            for (int i = 0; i < 8; i++)
                #pragma unroll
                for (int j = 0; j < 8; j++) acc[i][j] += ar[i]*br[j];
        }
        __syncthreads();
    }
    #pragma unroll
    for (int i = 0; i < 8; i++) {
        float* Cr = C + (size_t)(bm+ty*8+i)*N + bn + tx*8;
        *(float4*)Cr     = make_float4(acc[i][0],acc[i][1],acc[i][2],acc[i][3]);
        *(float4*)(Cr+4) = make_float4(acc[i][4],acc[i][5],acc[i][6],acc[i][7]);
    }
}

// ---------------- fused attention: U += exp(tanh(QK^T/8))*mask_k @ V, + S partials ----------------
#define PITCH 68
#define ATTN_SMEM ((4*64*PITCH + 64 + 64 + 256) * 4)

__global__ __launch_bounds__(256) void attn_kernel() {
    extern __shared__ float sm[];
    float* Qs = sm;
    float* Ks = Qs + 64*PITCH;
    float* Vs = Ks + 64*PITCH;
    float* Ps = Vs + 64*PITCH;
    float* mq = Ps + 64*PITCH;
    float* mk = mq + 64;
    float* red = mk + 64;

    int qt = blockIdx.x, h = blockIdx.y, b = blockIdx.z;
    int tid = threadIdx.x;
    int tx = tid & 15, ty = tid >> 4;
    int q0 = ty*4, k0 = tx*4, d0 = tx*4;

    const float* Qg = g_Q + (size_t)(b*Lz + qt*64)*Ez + h*Dz;
    {
        int q = tid >> 2, dgb = (tid & 3) * 4;
        #pragma unroll
        for (int j = 0; j < 4; j++) {
            int dg = dgb + j;
            float4 v = *(const float4*)(Qg + q*Ez + dg*4);
            int dd = dg*4;
            Qs[(dd+0)*PITCH+q]=v.x; Qs[(dd+1)*PITCH+q]=v.y;
            Qs[(dd+2)*PITCH+q]=v.z; Qs[(dd+3)*PITCH+q]=v.w;
        }
    }
    if (tid < 64) mq[tid] = g_mf[b*Lz + qt*64 + tid];

    float U[4][4] = {};
    float partial = 0.f;

    for (int kt = 0; kt < 16; kt++) {
        const float* Kg = g_K + (size_t)(b*Lz + kt*64)*Ez + h*Dz;
        const float* Vg = g_V + (size_t)(b*Lz + kt*64)*Ez + h*Dz;
        __syncthreads();   // previous phase2 done before overwriting K/V/P tiles
        {
            int r = tid >> 2, dgb = (tid & 3) * 4;
            #pragma unroll
            for (int j = 0; j < 4; j++) {
                int dg = dgb + j;
                float4 kv = *(const float4*)(Kg + r*Ez + dg*4);
                int dd = dg*4;
                Ks[(dd+0)*PITCH+r]=kv.x; Ks[(dd+1)*PITCH+r]=kv.y;
                Ks[(dd+2)*PITCH+r]=kv.z; Ks[(dd+3)*PITCH+r]=kv.w;
                float4 vv = *(const float4*)(Vg + r*Ez + dg*4);
                *(float4*)&Vs[r*PITCH+dd] = vv;
            }
        }
        if (tid < 64) mk[tid] = g_mf[b*Lz + kt*64 + tid];
        __syncthreads();

        float S[4][4] = {};
        #pragma unroll 8
        for (int d = 0; d < 64; d++) {
            float4 a  = *(const float4*)&Qs[d*PITCH + q0];
            float4 bb = *(const float4*)&Ks[d*PITCH + k0];
            float av[4] = {a.x, a.y, a.z, a.w};
            float bv[4] = {bb.x, bb.y, bb.z, bb.w};
            #pragma unroll
            for (int i = 0; i < 4; i++)
                #pragma unroll
                for (int j = 0; j < 4; j++) S[i][j] += av[i]*bv[j];
        }
        #pragma unroll
        for (int i = 0; i < 4; i++) {
            float mqi = mq[q0+i];
            #pragma unroll
            for (int j = 0; j < 4; j++) {
                float sc = S[i][j] * 0.125f;
                float t  = __expf(2.0f*sc);
                float th = __fdividef(t - 1.0f, t + 1.0f);
                float p  = __expf(th) * mk[k0+j];
                partial += mqi * p;
                Ps[(k0+j)*PITCH + q0+i] = p;
            }
        }
        __syncthreads();
        #pragma unroll 8
        for (int k = 0; k < 64; k++) {
            float4 a = *(const float4*)&Ps[k*PITCH + q0];
            float4 v = *(const float4*)&Vs[k*PITCH + d0];
            float av[4] = {a.x, a.y, a.z, a.w};
            float vv[4] = {v.x, v.y, v.z, v.w};
            #pragma unroll
            for (int i = 0; i < 4; i++)
                #pragma unroll
                for (int j = 0; j < 4; j++) U[i][j] += av[i]*vv[j];
        }
    }

    float* Ug = g_U + (size_t)(b*Lz + qt*64)*Ez + h*Dz;
    #pragma unroll
    for (int i = 0; i < 4; i++)
        *(float4*)&Ug[(q0+i)*Ez + d0] = make_float4(U[i][0],U[i][1],U[i][2],U[i][3]);

    red[tid] = partial; __syncthreads();
    for (int s = 128; s > 0; s >>= 1) { if (tid < s) red[tid] += red[tid+s]; __syncthreads(); }
    if (tid == 0) g_Spart[(b*Hz + h)*16 + qt] = red[0];
}

// ---------------- host launcher ----------------
static void* symaddr(const void* s) { void* p = nullptr; cudaGetSymbolAddress(&p, s); return p; }

extern "C" void kernel_launch(void* const* d_in, const int* in_sizes, int n_in,
                              void* d_out, int out_size) {
    const float* x    = (const float*)d_in[0];
    const void*  mask = d_in[1];
    const float* Wq   = (const float*)d_in[2];
    const float* Wk   = (const float*)d_in[3];
    const float* Wv   = (const float*)d_in[4];
    const float* Wo   = (const float*)d_in[5];
    const float* G    = (const float*)d_in[6];
    float* out = (float*)d_out;

    float* Q   = (float*)symaddr(g_Q);
    float* K   = (float*)symaddr(g_K);
    float* V   = (float*)symaddr(g_V);
    float* Vm  = (float*)symaddr(g_Vm);
    float* act = (float*)symaddr(g_act);
    float* U   = (float*)symaddr(g_U);
    float* GAV = (float*)symaddr(g_GAV);

    cudaFuncSetAttribute((const void*)attn_kernel,
                         cudaFuncAttributeMaxDynamicSharedMemorySize, ATTN_SMEM);

    detect_mask<<<1,1>>>((const unsigned char*)mask);
    convert_mask<<<32,256>>>(mask);
    softmax_g<<<1024,256>>>(G);
    gsum_rows<<<dim3(1024,8),256>>>();
    reduce_parts<<<8,256>>>(1);

    gemm_abt<<<dim3(4,64),256>>>(x, Wq, Q, Bz*Lz, Ez, Ez);
    gemm_abt<<<dim3(4,64),256>>>(x, Wk, K, Bz*Lz, Ez, Ez);
    gemm_abt<<<dim3(4,64),256>>>(x, Wv, V, Bz*Lz, Ez, Ez);
    mask_v<<<4096,256>>>();

    attn_kernel<<<dim3(16,Hz,Bz),256,ATTN_SMEM>>>();
    reduce_parts<<<8,256>>>(0);
    rowscales<<<32,256>>>();

    gemm_ab_batched<<<dim3(4,8,Bz),256>>>(act, Vm, GAV, Lz, Ez, Lz);
    gemm_out<<<dim3(4,64),256>>>(U, GAV, Wo, out, Bz*Lz, Ez, Ez);
}

// round 4
// speedup vs baseline: 1.0141x; 1.0141x over previous
#include <cuda_runtime.h>
#include <cuda_bf16.h>
#include <float.h>

#define Bz   8
#define Lz   1024
#define Ez   512
#define Hz   8
#define Dz   64

typedef unsigned long long ull;

// ---------------- packed f32x2 helpers ----------------
__device__ __forceinline__ void ffma2(ull& d, ull a, ull b) {
    asm("fma.rn.f32x2 %0, %1, %2, %0;" : "+l"(d) : "l"(a), "l"(b));
}
__device__ __forceinline__ ull dup2(float x) {
    ull r; asm("mov.b64 %0, {%1, %1};" : "=l"(r) : "f"(x)); return r;
}
__device__ __forceinline__ float2 unpk(ull v) {
    float2 r; asm("mov.b64 {%0, %1}, %2;" : "=f"(r.x), "=f"(r.y) : "l"(v)); return r;
}
__device__ __forceinline__ float tanh_fast(float x) {
    float y; asm("tanh.approx.f32 %0, %1;" : "=f"(y) : "f"(x)); return y;
}
__device__ __forceinline__ float ex2f(float x) {
    float y; asm("ex2.approx.f32 %0, %1;" : "=f"(y) : "f"(x)); return y;
}
#define L2E 1.4426950408889634f

// ---------------- device scratch ----------------
__device__ float g_mf[Bz*Lz];
__device__ int   g_maskKind;
__device__ float g_act[Lz*Lz];
__device__ float g_Q [Bz*Lz*Ez];
__device__ float g_K [Bz*Lz*Ez];
__device__ float g_V [Bz*Lz*Ez];
__device__ float g_Vm[Bz*Lz*Ez];
__device__ float g_U [Bz*Lz*Ez];
__device__ float g_GAV[Bz*Lz*Ez];
__device__ float g_Spart[Bz*Hz*8];
__device__ float g_Gpart[Bz*Lz];
__device__ float g_S[Bz];
__device__ float g_gs[Bz];
__device__ float g_rs0[Bz*Lz];
__device__ float g_rs1[Bz*Lz];

// ---------------- mask dtype detection + convert ----------------
__global__ void detect_mask(const unsigned char* m) {
    bool isInt32 = true;
    for (int i = 0; i < 64; i++) {
        if (m[4*i] > 1) isInt32 = false;
        if (m[4*i+1] | m[4*i+2] | m[4*i+3]) isInt32 = false;
    }
    if (isInt32) { g_maskKind = 0; return; }
    const unsigned int* w = (const unsigned int*)m;
    bool isFloat = true;
    for (int i = 0; i < 64; i++) {
        unsigned v = w[i];
        if (v != 0u && v != 0x3F800000u) isFloat = false;
    }
    g_maskKind = isFloat ? 2 : 1;
}

__global__ void convert_mask(const void* m) {
    int i = blockIdx.x*256 + threadIdx.x;
    if (i >= Bz*Lz) return;
    int k = g_maskKind;
    float v;
    if (k == 0)      v = ((const int*)m)[i] ? 1.f : 0.f;
    else if (k == 1) v = ((const unsigned char*)m)[i] ? 1.f : 0.f;
    else             v = ((const float*)m)[i];
    g_mf[i] = v;
}

// ---------------- softmax of G rows -> g_act ----------------
__global__ __launch_bounds__(256) void softmax_g(const float* __restrict__ G) {
    int q = blockIdx.x, t = threadIdx.x;
    const float* row = G + (size_t)q*Lz;
    __shared__ float red[256];
    float mx = -FLT_MAX;
    for (int k = t; k < Lz; k += 256) mx = fmaxf(mx, row[k]);
    red[t] = mx; __syncthreads();
    for (int s = 128; s > 0; s >>= 1) { if (t < s) red[t] = fmaxf(red[t], red[t+s]); __syncthreads(); }
    mx = red[0]; __syncthreads();
    float vals[4]; float sum = 0.f;
    for (int k = t, j = 0; k < Lz; k += 256, j++) { float e = __expf(row[k]-mx); vals[j] = e; sum += e; }
    red[t] = sum; __syncthreads();
    for (int s = 128; s > 0; s >>= 1) { if (t < s) red[t] += red[t+s]; __syncthreads(); }
    float inv = 1.f / red[0];
    for (int k = t, j = 0; k < Lz; k += 256, j++) g_act[(size_t)q*Lz + k] = vals[j]*inv;
}

// gsum rows: g_Gpart[b*L+q] = mf[b,q] * sum_k act[q,k]*mf[b,k]
__global__ __launch_bounds__(256) void gsum_rows() {
    int q = blockIdx.x, b = blockIdx.y, t = threadIdx.x;
    __shared__ float red[256];
    const float* arow = g_act + (size_t)q*Lz;
    const float* mf = g_mf + b*Lz;
    float s = 0.f;
    for (int k = t; k < Lz; k += 256) s += arow[k]*mf[k];
    red[t] = s; __syncthreads();
    for (int st = 128; st > 0; st >>= 1) { if (t < st) red[t] += red[t+st]; __syncthreads(); }
    if (t == 0) g_Gpart[b*Lz + q] = red[0] * mf[q];
}

__global__ __launch_bounds__(256) void reduce_parts(int which) {
    int b = blockIdx.x, t = threadIdx.x;
    __shared__ float red[256];
    float s = 0.f;
    if (which == 0) { for (int i = t; i < Hz*8; i += 256) s += g_Spart[b*Hz*8 + i]; }
    else            { for (int i = t; i < Lz;   i += 256) s += g_Gpart[b*Lz + i]; }
    red[t] = s; __syncthreads();
    for (int st = 128; st > 0; st >>= 1) { if (t < st) red[t] += red[t+st]; __syncthreads(); }
    if (t == 0) { if (which == 0) g_S[b] = red[0]; else g_gs[b] = red[0]; }
}

__global__ void rowscales() {
    int i = blockIdx.x*256 + threadIdx.x;
    if (i >= Bz*Lz) return;
    int b = i >> 10;
    const float TINY = 1.175494351e-38f;
    float mf = g_mf[i];
    g_rs0[i] = 0.5f*mf / fmaxf(g_S[b],  TINY);
    g_rs1[i] = 0.5f*mf / fmaxf(g_gs[b], TINY);
}

// Vm = mf_k * V (per row)
__global__ void mask_v() {
    size_t i = (size_t)blockIdx.x*256 + threadIdx.x;       // over float4s
    if (i >= (size_t)Bz*Lz*Ez/4) return;
    float4 v = ((const float4*)g_V)[i];
    float m = g_mf[(i*4) >> 9];
    ((float4*)g_Vm)[i] = make_float4(v.x*m, v.y*m, v.z*m, v.w*m);
}

// ---------------- packed inner-product macro (8a x 8b -> acc2[8][4]) ----------------
#define FMA_TILE(acc2, ar, bv)                              \
    _Pragma("unroll")                                       \
    for (int _i = 0; _i < 8; _i++) {                        \
        ull _ad = dup2(ar[_i]);                             \
        ffma2(acc2[_i][0], _ad, bv[0]);                     \
        ffma2(acc2[_i][1], _ad, bv[1]);                     \
        ffma2(acc2[_i][2], _ad, bv[2]);                     \
        ffma2(acc2[_i][3], _ad, bv[3]);                     \
    }

// ---------------- SGEMM 128x128x8, 256 threads, 8x8/thread, f32x2 ----------------
// C (MxN) = A (MxK, rowmajor) @ B^T (B is NxK rowmajor)
__global__ __launch_bounds__(256) void gemm_abt(const float* __restrict__ A, const float* __restrict__ B,
                                                float* __restrict__ C, int M, int N, int K) {
    __shared__ float As[8][132];
    __shared__ float Bs[8][132];
    int bn = blockIdx.x*128, bm = blockIdx.y*128;
    int tid = threadIdx.x;
    int tx = tid & 15, ty = tid >> 4;
    int lr = tid >> 1, lk = (tid & 1) * 4;
    const float* Ag = A + (size_t)(bm+lr)*K + lk;
    const float* Bg = B + (size_t)(bn+lr)*K + lk;
    ull acc2[8][4] = {};
    for (int k0 = 0; k0 < K; k0 += 8) {
        float4 a  = *(const float4*)(Ag + k0);
        float4 bw = *(const float4*)(Bg + k0);
        As[lk+0][lr]=a.x;  As[lk+1][lr]=a.y;  As[lk+2][lr]=a.z;  As[lk+3][lr]=a.w;
        Bs[lk+0][lr]=bw.x; Bs[lk+1][lr]=bw.y; Bs[lk+2][lr]=bw.z; Bs[lk+3][lr]=bw.w;
        __syncthreads();
        #pragma unroll
        for (int kk = 0; kk < 8; kk++) {
            float ar[8];
            *(float4*)ar     = *(const float4*)&As[kk][ty*8];
            *(float4*)(ar+4) = *(const float4*)&As[kk][ty*8+4];
            ulonglong2 b0 = *(const ulonglong2*)&Bs[kk][tx*8];
            ulonglong2 b1 = *(const ulonglong2*)&Bs[kk][tx*8+4];
            ull bv[4] = {b0.x, b0.y, b1.x, b1.y};
            FMA_TILE(acc2, ar, bv);
        }
        __syncthreads();
    }
    #pragma unroll
    for (int i = 0; i < 8; i++) {
        float2 p0 = unpk(acc2[i][0]), p1 = unpk(acc2[i][1]);
        float2 p2 = unpk(acc2[i][2]), p3 = unpk(acc2[i][3]);
        float* Cr = C + (size_t)(bm+ty*8+i)*N + bn + tx*8;
        *(float4*)Cr     = make_float4(p0.x,p0.y,p1.x,p1.y);
        *(float4*)(Cr+4) = make_float4(p2.x,p2.y,p3.x,p3.y);
    }
}

// C_z (MxN) = A (MxK) @ B_z (KxN rowmajor), z = batch
__global__ __launch_bounds__(256) void gemm_ab_batched(const float* __restrict__ A, const float* __restrict__ B,
                                                       float* __restrict__ C, int M, int N, int K) {
    __shared__ float As[8][132];
    __shared__ float Bs[8][132];
    int z = blockIdx.z;
    const float* Bp = B + (size_t)z*K*N;
    float* Cp = C + (size_t)z*M*N;
    int bn = blockIdx.x*128, bm = blockIdx.y*128;
    int tid = threadIdx.x;
    int tx = tid & 15, ty = tid >> 4;
    int lr = tid >> 1, lk = (tid & 1) * 4;
    int bk = tid >> 5, n4 = (tid & 31) * 4;
    const float* Ag = A + (size_t)(bm+lr)*K + lk;
    ull acc2[8][4] = {};
    for (int k0 = 0; k0 < K; k0 += 8) {
        float4 a = *(const float4*)(Ag + k0);
        As[lk+0][lr]=a.x; As[lk+1][lr]=a.y; As[lk+2][lr]=a.z; As[lk+3][lr]=a.w;
        float4 bw = *(const float4*)(Bp + (size_t)(k0+bk)*N + bn + n4);
        *(float4*)&Bs[bk][n4] = bw;
        __syncthreads();
        #pragma unroll
        for (int kk = 0; kk < 8; kk++) {
            float ar[8];
            *(float4*)ar     = *(const float4*)&As[kk][ty*8];
            *(float4*)(ar+4) = *(const float4*)&As[kk][ty*8+4];
            ulonglong2 b0 = *(const ulonglong2*)&Bs[kk][tx*8];
            ulonglong2 b1 = *(const ulonglong2*)&Bs[kk][tx*8+4];
            ull bv[4] = {b0.x, b0.y, b1.x, b1.y};
            FMA_TILE(acc2, ar, bv);
        }
        __syncthreads();
    }
    #pragma unroll
    for (int i = 0; i < 8; i++) {
        float2 p0 = unpk(acc2[i][0]), p1 = unpk(acc2[i][1]);
        float2 p2 = unpk(acc2[i][2]), p3 = unpk(acc2[i][3]);
        float* Cr = Cp + (size_t)(bm+ty*8+i)*N + bn + tx*8;
        *(float4*)Cr     = make_float4(p0.x,p0.y,p1.x,p1.y);
        *(float4*)(Cr+4) = make_float4(p2.x,p2.y,p3.x,p3.y);
    }
}

// Out = (rs0*U + rs1*GAV) @ Wo^T, fused A construction
__global__ __launch_bounds__(256) void gemm_out(const float* __restrict__ U, const float* __restrict__ Gv,
                                                const float* __restrict__ B, float* __restrict__ C,
                                                int M, int N, int K) {
    __shared__ float As[8][132];
    __shared__ float Bs[8][132];
    int bn = blockIdx.x*128, bm = blockIdx.y*128;
    int tid = threadIdx.x;
    int tx = tid & 15, ty = tid >> 4;
    int lr = tid >> 1, lk = (tid & 1) * 4;
    float r0 = g_rs0[bm+lr], r1 = g_rs1[bm+lr];
    const float* Ug = U  + (size_t)(bm+lr)*K + lk;
    const float* Gg = Gv + (size_t)(bm+lr)*K + lk;
    const float* Bg = B  + (size_t)(bn+lr)*K + lk;
    ull acc2[8][4] = {};
    for (int k0 = 0; k0 < K; k0 += 8) {
        float4 u  = *(const float4*)(Ug + k0);
        float4 g  = *(const float4*)(Gg + k0);
        float4 bw = *(const float4*)(Bg + k0);
        As[lk+0][lr]=r0*u.x+r1*g.x; As[lk+1][lr]=r0*u.y+r1*g.y;
        As[lk+2][lr]=r0*u.z+r1*g.z; As[lk+3][lr]=r0*u.w+r1*g.w;
        Bs[lk+0][lr]=bw.x; Bs[lk+1][lr]=bw.y; Bs[lk+2][lr]=bw.z; Bs[lk+3][lr]=bw.w;
        __syncthreads();
        #pragma unroll
        for (int kk = 0; kk < 8; kk++) {
            float ar[8];
            *(float4*)ar     = *(const float4*)&As[kk][ty*8];
            *(float4*)(ar+4) = *(const float4*)&As[kk][ty*8+4];
            ulonglong2 b0 = *(const ulonglong2*)&Bs[kk][tx*8];
            ulonglong2 b1 = *(const ulonglong2*)&Bs[kk][tx*8+4];
            ull bv[4] = {b0.x, b0.y, b1.x, b1.y};
            FMA_TILE(acc2, ar, bv);
        }
        __syncthreads();
    }
    #pragma unroll
    for (int i = 0; i < 8; i++) {
        float2 p0 = unpk(acc2[i][0]), p1 = unpk(acc2[i][1]);
        float2 p2 = unpk(acc2[i][2]), p3 = unpk(acc2[i][3]);
        float* Cr = C + (size_t)(bm+ty*8+i)*N + bn + tx*8;
        *(float4*)Cr     = make_float4(p0.x,p0.y,p1.x,p1.y);
        *(float4*)(Cr+4) = make_float4(p2.x,p2.y,p3.x,p3.y);
    }
}

// ---------------- fused attention v2: 128x128 score tiles ----------------
// U[q,d] = sum_k exp(tanh(qk/8)) * mk[k] * V[k,d];  Spart = sum mq*mk*exp(tanh)
#define QP 132
#define VP 72
#define ATTN_F (64*QP + 64*QP + 128*VP + 128*QP + 128 + 128 + 256)
#define ATTN_SMEM (ATTN_F * 4)

__global__ __launch_bounds__(256, 1) void attn_kernel() {
    extern __shared__ float sm[];
    float* Qs = sm;                 // [64][QP]  (d-major, q cols)
    float* Ks = Qs + 64*QP;         // [64][QP]  (d-major, k cols)
    float* Vs = Ks + 64*QP;         // [128][VP] (k rows, d cols)
    float* Ps = Vs + 128*VP;        // [128][QP] (k rows, q cols)
    float* mq = Ps + 128*QP;
    float* mk = mq + 128;
    float* red = mk + 128;

    int qt = blockIdx.x, h = blockIdx.y, b = blockIdx.z;
    int tid = threadIdx.x;
    // S phase mapping: i-dim = k (ty), j-dim = q packed (tx)
    int tx = tid & 15, ty = tid >> 4;
    int sq0 = tx*8, sk0 = ty*8;
    // PV mapping: 2 groups of 128, thread tile 8q x 8d
    int grp = tid >> 7;
    int t7  = tid & 127;
    int pd0 = (t7 & 7) * 8;
    int pq0 = (t7 >> 3) * 8;

    // load Q tile (transpose) + mq
    const float* Qg = g_Q + (size_t)(b*Lz + qt*128)*Ez + h*Dz;
    {
        int r = tid >> 1, c = (tid & 1) * 32;
        #pragma unroll
        for (int j = 0; j < 8; j++) {
            float4 v = *(const float4*)(Qg + (size_t)r*Ez + c + j*4);
            int d = c + j*4;
            Qs[(d+0)*QP+r]=v.x; Qs[(d+1)*QP+r]=v.y;
            Qs[(d+2)*QP+r]=v.z; Qs[(d+3)*QP+r]=v.w;
        }
    }
    if (tid < 128) mq[tid] = g_mf[b*Lz + qt*128 + tid];

    ull U2[8][4] = {};
    float partial = 0.f;

    for (int kt = 0; kt < 8; kt++) {
        const float* Kg = g_K + (size_t)(b*Lz + kt*128)*Ez + h*Dz;
        const float* Vg = g_V + (size_t)(b*Lz + kt*128)*Ez + h*Dz;
        __syncthreads();   // prev PV done before overwriting K/V/P
        {
            int r = tid >> 1, c = (tid & 1) * 32;
            #pragma unroll
            for (int j = 0; j < 8; j++) {
                float4 kv = *(const float4*)(Kg + (size_t)r*Ez + c + j*4);
                int d = c + j*4;
                Ks[(d+0)*QP+r]=kv.x; Ks[(d+1)*QP+r]=kv.y;
                Ks[(d+2)*QP+r]=kv.z; Ks[(d+3)*QP+r]=kv.w;
                float4 vv = *(const float4*)(Vg + (size_t)r*Ez + c + j*4);
                *(float4*)&Vs[r*VP + d] = vv;
            }
        }
        if (tid < 128) mk[tid] = g_mf[b*Lz + kt*128 + tid];
        __syncthreads();

        // ---- S = K^T Q (i=k from Ks, j=q packed from Qs) ----
        ull S2[8][4] = {};
        #pragma unroll 8
        for (int d = 0; d < 64; d++) {
            float ar[8];
            *(float4*)ar     = *(const float4*)&Ks[d*QP + sk0];
            *(float4*)(ar+4) = *(const float4*)&Ks[d*QP + sk0+4];
            ulonglong2 q0v = *(const ulonglong2*)&Qs[d*QP + sq0];
            ulonglong2 q1v = *(const ulonglong2*)&Qs[d*QP + sq0+4];
            ull bv[4] = {q0v.x, q0v.y, q1v.x, q1v.y};
            FMA_TILE(S2, ar, bv);
        }
        // ---- scores -> P (exp(tanh)), write Ps[k][q] ----
        #pragma unroll
        for (int i = 0; i < 8; i++) {
            float mki = mk[sk0+i];
            float pr[8];
            #pragma unroll
            for (int jp = 0; jp < 4; jp++) {
                float2 s = unpk(S2[i][jp]);
                float p0 = ex2f(tanh_fast(s.x*0.125f)*L2E) * mki;
                float p1 = ex2f(tanh_fast(s.y*0.125f)*L2E) * mki;
                partial += mq[sq0+2*jp]*p0 + mq[sq0+2*jp+1]*p1;
                pr[2*jp] = p0; pr[2*jp+1] = p1;
            }
            float* Pr = &Ps[(sk0+i)*QP + sq0];
            *(float4*)Pr     = make_float4(pr[0],pr[1],pr[2],pr[3]);
            *(float4*)(Pr+4) = make_float4(pr[4],pr[5],pr[6],pr[7]);
        }
        __syncthreads();

        // ---- U += P^T V (split-k: group g handles k in [g*64, g*64+64)) ----
        #pragma unroll 8
        for (int k = 0; k < 64; k++) {
            int kk = grp*64 + k;
            float ar[8];
            *(float4*)ar     = *(const float4*)&Ps[kk*QP + pq0];
            *(float4*)(ar+4) = *(const float4*)&Ps[kk*QP + pq0+4];
            ulonglong2 v0 = *(const ulonglong2*)&Vs[kk*VP + pd0];
            ulonglong2 v1 = *(const ulonglong2*)&Vs[kk*VP + pd0+4];
            ull bv[4] = {v0.x, v0.y, v1.x, v1.y};
            FMA_TILE(U2, ar, bv);
        }
    }

    // ---- reduce the two k-groups and store U ----
    __syncthreads();
    float* buf = Vs;   // [128][VP] reuse
    if (grp == 0) {
        #pragma unroll
        for (int i = 0; i < 8; i++) {
            float2 p0 = unpk(U2[i][0]), p1 = unpk(U2[i][1]);
            float2 p2 = unpk(U2[i][2]), p3 = unpk(U2[i][3]);
            float* Br = &buf[(pq0+i)*VP + pd0];
            *(float4*)Br     = make_float4(p0.x,p0.y,p1.x,p1.y);
            *(float4*)(Br+4) = make_float4(p2.x,p2.y,p3.x,p3.y);
        }
    }
    __syncthreads();
    if (grp == 1) {
        #pragma unroll
        for (int i = 0; i < 8; i++) {
            float2 p0 = unpk(U2[i][0]), p1 = unpk(U2[i][1]);
            float2 p2 = unpk(U2[i][2]), p3 = unpk(U2[i][3]);
            const float* Br = &buf[(pq0+i)*VP + pd0];
            float4 b0 = *(const float4*)Br;
            float4 b1 = *(const float4*)(Br+4);
            float* Ug = g_U + (size_t)(b*Lz + qt*128 + pq0+i)*Ez + h*Dz + pd0;
            *(float4*)Ug     = make_float4(p0.x+b0.x, p0.y+b0.y, p1.x+b0.z, p1.y+b0.w);
            *(float4*)(Ug+4) = make_float4(p2.x+b1.x, p2.y+b1.y, p3.x+b1.z, p3.y+b1.w);
        }
    }

    red[tid] = partial; __syncthreads();
    for (int s = 128; s > 0; s >>= 1) { if (tid < s) red[tid] += red[tid+s]; __syncthreads(); }
    if (tid == 0) g_Spart[(b*Hz + h)*8 + qt] = red[0];
}

// ---------------- host launcher ----------------
static void* symaddr(const void* s) { void* p = nullptr; cudaGetSymbolAddress(&p, s); return p; }

extern "C" void kernel_launch(void* const* d_in, const int* in_sizes, int n_in,
                              void* d_out, int out_size) {
    const float* x    = (const float*)d_in[0];
    const void*  mask = d_in[1];
    const float* Wq   = (const float*)d_in[2];
    const float* Wk   = (const float*)d_in[3];
    const float* Wv   = (const float*)d_in[4];
    const float* Wo   = (const float*)d_in[5];
    const float* G    = (const float*)d_in[6];
    float* out = (float*)d_out;

    float* Q   = (float*)symaddr(g_Q);
    float* K   = (float*)symaddr(g_K);
    float* V   = (float*)symaddr(g_V);
    float* Vm  = (float*)symaddr(g_Vm);
    float* act = (float*)symaddr(g_act);
    float* U   = (float*)symaddr(g_U);
    float* GAV = (float*)symaddr(g_GAV);

    cudaFuncSetAttribute((const void*)attn_kernel,
                         cudaFuncAttributeMaxDynamicSharedMemorySize, ATTN_SMEM);

    detect_mask<<<1,1>>>((const unsigned char*)mask);
    convert_mask<<<32,256>>>(mask);
    softmax_g<<<1024,256>>>(G);
    gsum_rows<<<dim3(1024,8),256>>>();
    reduce_parts<<<8,256>>>(1);

    gemm_abt<<<dim3(4,64),256>>>(x, Wq, Q, Bz*Lz, Ez, Ez);
    gemm_abt<<<dim3(4,64),256>>>(x, Wk, K, Bz*Lz, Ez, Ez);
    gemm_abt<<<dim3(4,64),256>>>(x, Wv, V, Bz*Lz, Ez, Ez);
    mask_v<<<4096,256>>>();

    attn_kernel<<<dim3(8,Hz,Bz),256,ATTN_SMEM>>>();
    reduce_parts<<<8,256>>>(0);
    rowscales<<<32,256>>>();

    gemm_ab_batched<<<dim3(4,8,Bz),256>>>(act, Vm, GAV, Lz, Ez, Lz);
    gemm_out<<<dim3(4,64),256>>>(U, GAV, Wo, out, Bz*Lz, Ez, Ez);
}

// round 6
// speedup vs baseline: 1.4604x; 1.4402x over previous
#include <cuda_runtime.h>
#include <cuda_bf16.h>
#include <float.h>
#include <stdint.h>

#define Bz   8
#define Lz   1024
#define Ez   512
#define Hz   8
#define Dz   64

typedef unsigned long long ull;

// ---------------- packed f32x2 / fast-math helpers ----------------
__device__ __forceinline__ void ffma2(ull& d, ull a, ull b) {
    asm("fma.rn.f32x2 %0, %1, %2, %0;" : "+l"(d) : "l"(a), "l"(b));
}
__device__ __forceinline__ ull dup2(float x) {
    ull r; asm("mov.b64 %0, {%1, %1};" : "=l"(r) : "f"(x)); return r;
}
__device__ __forceinline__ float2 unpk(ull v) {
    float2 r; asm("mov.b64 {%0, %1}, %2;" : "=f"(r.x), "=f"(r.y) : "l"(v)); return r;
}
__device__ __forceinline__ float tanh_fast(float x) {
    float y; asm("tanh.approx.f32 %0, %1;" : "=f"(y) : "f"(x)); return y;
}
__device__ __forceinline__ float ex2f(float x) {
    float y; asm("ex2.approx.f32 %0, %1;" : "=f"(y) : "f"(x)); return y;
}
#define L2E 1.4426950408889634f

__device__ __forceinline__ uint32_t smem_u32(const void* p) {
    uint32_t a;
    asm("{ .reg .u64 t; cvta.to.shared.u64 t, %1; cvt.u32.u64 %0, t; }" : "=r"(a) : "l"(p));
    return a;
}

// ---------------- mma.sync helpers (baseline PTX, works at compute_103) ----------------
__device__ __forceinline__ void ldmat4(uint32_t* r, uint32_t a) {
    asm volatile("ldmatrix.sync.aligned.m8n8.x4.shared.b16 {%0,%1,%2,%3}, [%4];"
                 : "=r"(r[0]), "=r"(r[1]), "=r"(r[2]), "=r"(r[3]) : "r"(a));
}
__device__ __forceinline__ void mma_bf16(float* c, const uint32_t* a, uint32_t b0, uint32_t b1) {
    asm volatile("mma.sync.aligned.m16n8k16.row.col.f32.bf16.bf16.f32 "
                 "{%0,%1,%2,%3}, {%4,%5,%6,%7}, {%8,%9}, {%0,%1,%2,%3};"
                 : "+f"(c[0]), "+f"(c[1]), "+f"(c[2]), "+f"(c[3])
                 : "r"(a[0]), "r"(a[1]), "r"(a[2]), "r"(a[3]), "r"(b0), "r"(b1));
}

// ---------------- device scratch ----------------
__device__ float g_mf[Bz*Lz];
__device__ int   g_maskKind;
__device__ float g_act[Lz*Lz];
__device__ float g_Q [Bz*Lz*Ez];
__device__ float g_K [Bz*Lz*Ez];
__device__ float g_V [Bz*Lz*Ez];
__device__ float g_U [Bz*Lz*Ez];
__device__ float g_GAV[Bz*Lz*Ez];
__device__ float g_Spart[Bz*Hz*8];
__device__ float g_Gpart[Bz*Lz];
__device__ float g_S[Bz];
__device__ float g_gs[Bz];
__device__ float g_rs0[Bz*Lz];
__device__ float g_rs1[Bz*Lz];

// bf16 hi/lo scratch
__device__ __nv_bfloat16 g_xhi[Bz*Lz*Ez],  g_xlo[Bz*Lz*Ez];
__device__ __nv_bfloat16 g_wqhi[Ez*Ez], g_wqlo[Ez*Ez];
__device__ __nv_bfloat16 g_wkhi[Ez*Ez], g_wklo[Ez*Ez];
__device__ __nv_bfloat16 g_wvhi[Ez*Ez], g_wvlo[Ez*Ez];
__device__ __nv_bfloat16 g_wohi[Ez*Ez], g_wolo[Ez*Ez];
__device__ __nv_bfloat16 g_acthi[Lz*Lz], g_actlo[Lz*Lz];
__device__ __nv_bfloat16 g_vthi[Bz*Ez*Lz], g_vtlo[Bz*Ez*Lz];
__device__ __nv_bfloat16 g_aohi[Bz*Lz*Ez], g_aolo[Bz*Lz*Ez];

// ---------------- mask detect / convert ----------------
__global__ void detect_mask(const unsigned char* m) {
    bool isInt32 = true;
    for (int i = 0; i < 64; i++) {
        if (m[4*i] > 1) isInt32 = false;
        if (m[4*i+1] | m[4*i+2] | m[4*i+3]) isInt32 = false;
    }
    if (isInt32) { g_maskKind = 0; return; }
    const unsigned int* w = (const unsigned int*)m;
    bool isFloat = true;
    for (int i = 0; i < 64; i++) {
        unsigned v = w[i];
        if (v != 0u && v != 0x3F800000u) isFloat = false;
    }
    g_maskKind = isFloat ? 2 : 1;
}

__global__ void convert_mask(const void* m) {
    int i = blockIdx.x*256 + threadIdx.x;
    if (i >= Bz*Lz) return;
    int k = g_maskKind;
    float v;
    if (k == 0)      v = ((const int*)m)[i] ? 1.f : 0.f;
    else if (k == 1) v = ((const unsigned char*)m)[i] ? 1.f : 0.f;
    else             v = ((const float*)m)[i];
    g_mf[i] = v;
}

// ---------------- fp32 -> bf16 hi/lo split ----------------
__global__ void split_f32(const float* __restrict__ src, __nv_bfloat16* __restrict__ hi,
                          __nv_bfloat16* __restrict__ lo, int n) {
    int i = blockIdx.x*256 + threadIdx.x;
    if (i >= n) return;
    float v = src[i];
    __nv_bfloat16 h = __float2bfloat16(v);
    hi[i] = h;
    lo[i] = __float2bfloat16(v - __bfloat162float(h));
}

// ---------------- softmax of G rows -> g_act ----------------
__global__ __launch_bounds__(256) void softmax_g(const float* __restrict__ G) {
    int q = blockIdx.x, t = threadIdx.x;
    const float* row = G + (size_t)q*Lz;
    __shared__ float red[256];
    float mx = -FLT_MAX;
    for (int k = t; k < Lz; k += 256) mx = fmaxf(mx, row[k]);
    red[t] = mx; __syncthreads();
    for (int s = 128; s > 0; s >>= 1) { if (t < s) red[t] = fmaxf(red[t], red[t+s]); __syncthreads(); }
    mx = red[0]; __syncthreads();
    float vals[4]; float sum = 0.f;
    for (int k = t, j = 0; k < Lz; k += 256, j++) { float e = __expf(row[k]-mx); vals[j] = e; sum += e; }
    red[t] = sum; __syncthreads();
    for (int s = 128; s > 0; s >>= 1) { if (t < s) red[t] += red[t+s]; __syncthreads(); }
    float inv = 1.f / red[0];
    for (int k = t, j = 0; k < Lz; k += 256, j++) g_act[(size_t)q*Lz + k] = vals[j]*inv;
}

__global__ __launch_bounds__(256) void gsum_rows() {
    int q = blockIdx.x, b = blockIdx.y, t = threadIdx.x;
    __shared__ float red[256];
    const float* arow = g_act + (size_t)q*Lz;
    const float* mf = g_mf + b*Lz;
    float s = 0.f;
    for (int k = t; k < Lz; k += 256) s += arow[k]*mf[k];
    red[t] = s; __syncthreads();
    for (int st = 128; st > 0; st >>= 1) { if (t < st) red[t] += red[t+st]; __syncthreads(); }
    if (t == 0) g_Gpart[b*Lz + q] = red[0] * mf[q];
}

__global__ __launch_bounds__(256) void reduce_parts(int which) {
    int b = blockIdx.x, t = threadIdx.x;
    __shared__ float red[256];
    float s = 0.f;
    if (which == 0) { for (int i = t; i < Hz*8; i += 256) s += g_Spart[b*Hz*8 + i]; }
    else            { for (int i = t; i < Lz;   i += 256) s += g_Gpart[b*Lz + i]; }
    red[t] = s; __syncthreads();
    for (int st = 128; st > 0; st >>= 1) { if (t < st) red[t] += red[t+st]; __syncthreads(); }
    if (t == 0) { if (which == 0) g_S[b] = red[0]; else g_gs[b] = red[0]; }
}

__global__ void rowscales() {
    int i = blockIdx.x*256 + threadIdx.x;
    if (i >= Bz*Lz) return;
    int b = i >> 10;
    const float TINY = 1.175494351e-38f;
    float mf = g_mf[i];
    g_rs0[i] = 0.5f*mf / fmaxf(g_S[b],  TINY);
    g_rs1[i] = 0.5f*mf / fmaxf(g_gs[b], TINY);
}

// masked-V transpose + split: vt[b][e][l] = mf[b,l]*V[b,l,e] (bf16 hi/lo)
__global__ __launch_bounds__(256) void tsplit_v() {
    __shared__ float ts[32][33];
    int b = blockIdx.z;
    int e0 = blockIdx.x*32, l0 = blockIdx.y*32;
    int tx = threadIdx.x & 31, ty = threadIdx.x >> 5;
    #pragma unroll
    for (int r = 0; r < 4; r++) {
        int l = ty*4 + r;
        ts[l][tx] = g_V[(size_t)(b*Lz + l0 + l)*Ez + e0 + tx] * g_mf[b*Lz + l0 + l];
    }
    __syncthreads();
    #pragma unroll
    for (int r = 0; r < 4; r++) {
        int e = ty*4 + r;
        float v = ts[tx][e];
        __nv_bfloat16 h = __float2bfloat16(v);
        size_t o = ((size_t)b*Ez + e0 + e)*Lz + l0 + tx;
        g_vthi[o] = h;
        g_vtlo[o] = __float2bfloat16(v - __bfloat162float(h));
    }
}

// A_out = rs0*U + rs1*GAV  -> bf16 hi/lo
__global__ void prep_out() {
    int i = blockIdx.x*256 + threadIdx.x;
    if (i >= Bz*Lz*Ez) return;
    int row = i >> 9;
    float v = g_rs0[row]*g_U[i] + g_rs1[row]*g_GAV[i];
    __nv_bfloat16 h = __float2bfloat16(v);
    g_aohi[i] = h;
    g_aolo[i] = __float2bfloat16(v - __bfloat162float(h));
}

// ---------------- HMMA bf16-split GEMM: C[M,N] = A[M,K] @ B[N,K]^T ----------------
// 128x128 block, 8 warps (2m x 4n), warp = 64m x 32n, K chunks of 32.
// smem tiles row-stride 80B (conflict-free for ldmatrix row addressing).
#define T_AHI 0
#define T_ALO 10240
#define T_BHI 20480
#define T_BLO 30720

__global__ __launch_bounds__(256, 1)
void mma_gemm(const __nv_bfloat16* __restrict__ Ahi, const __nv_bfloat16* __restrict__ Alo,
              const __nv_bfloat16* __restrict__ Bhi, const __nv_bfloat16* __restrict__ Blo,
              float* __restrict__ C, int M, int N, int K,
              long long aStride, long long bStride, long long cStride) {
    __shared__ char smc[40960];
    uint32_t sb = smem_u32(smc);
    int tid = threadIdx.x, lane = tid & 31, wid = tid >> 5;
    int z = blockIdx.z;
    int bn = blockIdx.x*128, bm = blockIdx.y*128;
    Ahi += (long long)z*aStride; Alo += (long long)z*aStride;
    Bhi += (long long)z*bStride; Blo += (long long)z*bStride;
    C   += (long long)z*cStride;
    int wm = wid & 1, wn = wid >> 1;
    const char* pAh = (const char*)(Ahi + (size_t)bm*K);
    const char* pAl = (const char*)(Alo + (size_t)bm*K);
    const char* pBh = (const char*)(Bhi + (size_t)bn*K);
    const char* pBl = (const char*)(Blo + (size_t)bn*K);

    float acc[4][4][4] = {};

    // ldmatrix addressing
    uint32_t aRow = wm*64 + (lane & 15);
    uint32_t aK8  = (lane >> 4) * 8;                          // k offset 0/8
    uint32_t bRow = wn*32 + (lane & 7) + ((lane >> 4) << 3);  // n row
    uint32_t bK8  = ((lane >> 3) & 1) * 8;                    // k offset 0/8

    int nChunks = K >> 5;
    for (int kc = 0; kc < nChunks; kc++) {
        __syncthreads();
        #pragma unroll
        for (int i = tid; i < 512; i += 256) {
            int r = i >> 2, c = i & 3;
            size_t go = (size_t)r*K*2 + (size_t)kc*64 + c*16;
            uint32_t so = r*80 + c*16;
            *(uint4*)(smc + T_AHI + so) = *(const uint4*)(pAh + go);
            *(uint4*)(smc + T_ALO + so) = *(const uint4*)(pAl + go);
            *(uint4*)(smc + T_BHI + so) = *(const uint4*)(pBh + go);
            *(uint4*)(smc + T_BLO + so) = *(const uint4*)(pBl + go);
        }
        __syncthreads();
        #pragma unroll
        for (int ks = 0; ks < 2; ks++) {
            uint32_t ah[4][4], al[4][4], bh[2][4], bl[2][4];
            #pragma unroll
            for (int mi = 0; mi < 4; mi++) {
                uint32_t ad = sb + T_AHI + ((aRow + mi*16)*40 + ks*16 + aK8)*2;
                ldmat4(ah[mi], ad);
                ldmat4(al[mi], ad + (T_ALO - T_AHI));
            }
            #pragma unroll
            for (int bj = 0; bj < 2; bj++) {
                uint32_t ad = sb + T_BHI + ((bRow + bj*16)*40 + ks*16 + bK8)*2;
                ldmat4(bh[bj], ad);
                ldmat4(bl[bj], ad + (T_BLO - T_BHI));
            }
            #pragma unroll
            for (int mi = 0; mi < 4; mi++)
                #pragma unroll
                for (int nj = 0; nj < 4; nj++) {
                    int bj = nj >> 1, pr = (nj & 1)*2;
                    mma_bf16(acc[mi][nj], ah[mi], bh[bj][pr], bh[bj][pr+1]);
                    mma_bf16(acc[mi][nj], ah[mi], bl[bj][pr], bl[bj][pr+1]);
                    mma_bf16(acc[mi][nj], al[mi], bh[bj][pr], bh[bj][pr+1]);
                }
        }
    }

    // epilogue: c-frag: rows lane/4 (+8), cols 2*(lane%4)
    int r0 = bm + wm*64 + (lane >> 2);
    int c0 = bn + wn*32 + (lane & 3)*2;
    #pragma unroll
    for (int mi = 0; mi < 4; mi++)
        #pragma unroll
        for (int nj = 0; nj < 4; nj++) {
            float* p = C + (size_t)(r0 + mi*16)*N + c0 + nj*8;
            *(float2*)p                 = make_float2(acc[mi][nj][0], acc[mi][nj][1]);
            *(float2*)(p + (size_t)8*N) = make_float2(acc[mi][nj][2], acc[mi][nj][3]);
        }
}

// ---------------- fused attention (SIMT, unchanged from R4) ----------------
#define QP 132
#define VP 72
#define ATTN_F (64*QP + 64*QP + 128*VP + 128*QP + 128 + 128 + 256)
#define ATTN_SMEM (ATTN_F * 4)

#define FMA_TILE(acc2, ar, bv)                              \
    _Pragma("unroll")                                       \
    for (int _i = 0; _i < 8; _i++) {                        \
        ull _ad = dup2(ar[_i]);                             \
        ffma2(acc2[_i][0], _ad, bv[0]);                     \
        ffma2(acc2[_i][1], _ad, bv[1]);                     \
        ffma2(acc2[_i][2], _ad, bv[2]);                     \
        ffma2(acc2[_i][3], _ad, bv[3]);                     \
    }

__global__ __launch_bounds__(256, 1) void attn_kernel() {
    extern __shared__ float sm[];
    float* Qs = sm;
    float* Ks = Qs + 64*QP;
    float* Vs = Ks + 64*QP;
    float* Ps = Vs + 128*VP;
    float* mq = Ps + 128*QP;
    float* mk = mq + 128;
    float* red = mk + 128;

    int qt = blockIdx.x, h = blockIdx.y, b = blockIdx.z;
    int tid = threadIdx.x;
    int tx = tid & 15, ty = tid >> 4;
    int sq0 = tx*8, sk0 = ty*8;
    int grp = tid >> 7;
    int t7  = tid & 127;
    int pd0 = (t7 & 7) * 8;
    int pq0 = (t7 >> 3) * 8;

    const float* Qg = g_Q + (size_t)(b*Lz + qt*128)*Ez + h*Dz;
    {
        int r = tid >> 1, c = (tid & 1) * 32;
        #pragma unroll
        for (int j = 0; j < 8; j++) {
            float4 v = *(const float4*)(Qg + (size_t)r*Ez + c + j*4);
            int d = c + j*4;
            Qs[(d+0)*QP+r]=v.x; Qs[(d+1)*QP+r]=v.y;
            Qs[(d+2)*QP+r]=v.z; Qs[(d+3)*QP+r]=v.w;
        }
    }
    if (tid < 128) mq[tid] = g_mf[b*Lz + qt*128 + tid];

    ull U2[8][4] = {};
    float partial = 0.f;

    for (int kt = 0; kt < 8; kt++) {
        const float* Kg = g_K + (size_t)(b*Lz + kt*128)*Ez + h*Dz;
        const float* Vg = g_V + (size_t)(b*Lz + kt*128)*Ez + h*Dz;
        __syncthreads();
        {
            int r = tid >> 1, c = (tid & 1) * 32;
            #pragma unroll
            for (int j = 0; j < 8; j++) {
                float4 kv = *(const float4*)(Kg + (size_t)r*Ez + c + j*4);
                int d = c + j*4;
                Ks[(d+0)*QP+r]=kv.x; Ks[(d+1)*QP+r]=kv.y;
                Ks[(d+2)*QP+r]=kv.z; Ks[(d+3)*QP+r]=kv.w;
                float4 vv = *(const float4*)(Vg + (size_t)r*Ez + c + j*4);
                *(float4*)&Vs[r*VP + d] = vv;
            }
        }
        if (tid < 128) mk[tid] = g_mf[b*Lz + kt*128 + tid];
        __syncthreads();

        ull S2[8][4] = {};
        #pragma unroll 8
        for (int d = 0; d < 64; d++) {
            float ar[8];
            *(float4*)ar     = *(const float4*)&Ks[d*QP + sk0];
            *(float4*)(ar+4) = *(const float4*)&Ks[d*QP + sk0+4];
            ulonglong2 q0v = *(const ulonglong2*)&Qs[d*QP + sq0];
            ulonglong2 q1v = *(const ulonglong2*)&Qs[d*QP + sq0+4];
            ull bv[4] = {q0v.x, q0v.y, q1v.x, q1v.y};
            FMA_TILE(S2, ar, bv);
        }
        #pragma unroll
        for (int i = 0; i < 8; i++) {
            float mki = mk[sk0+i];
            float pr[8];
            #pragma unroll
            for (int jp = 0; jp < 4; jp++) {
                float2 s = unpk(S2[i][jp]);
                float p0 = ex2f(tanh_fast(s.x*0.125f)*L2E) * mki;
                float p1 = ex2f(tanh_fast(s.y*0.125f)*L2E) * mki;
                partial += mq[sq0+2*jp]*p0 + mq[sq0+2*jp+1]*p1;
                pr[2*jp] = p0; pr[2*jp+1] = p1;
            }
            float* Pr = &Ps[(sk0+i)*QP + sq0];
            *(float4*)Pr     = make_float4(pr[0],pr[1],pr[2],pr[3]);
            *(float4*)(Pr+4) = make_float4(pr[4],pr[5],pr[6],pr[7]);
        }
        __syncthreads();

        #pragma unroll 8
        for (int k = 0; k < 64; k++) {
            int kk = grp*64 + k;
            float ar[8];
            *(float4*)ar     = *(const float4*)&Ps[kk*QP + pq0];
            *(float4*)(ar+4) = *(const float4*)&Ps[kk*QP + pq0+4];
            ulonglong2 v0 = *(const ulonglong2*)&Vs[kk*VP + pd0];
            ulonglong2 v1 = *(const ulonglong2*)&Vs[kk*VP + pd0+4];
            ull bv[4] = {v0.x, v0.y, v1.x, v1.y};
            FMA_TILE(U2, ar, bv);
        }
    }

    __syncthreads();
    float* buf = Vs;
    if (grp == 0) {
        #pragma unroll
        for (int i = 0; i < 8; i++) {
            float2 p0 = unpk(U2[i][0]), p1 = unpk(U2[i][1]);
            float2 p2 = unpk(U2[i][2]), p3 = unpk(U2[i][3]);
            float* Br = &buf[(pq0+i)*VP + pd0];
            *(float4*)Br     = make_float4(p0.x,p0.y,p1.x,p1.y);
            *(float4*)(Br+4) = make_float4(p2.x,p2.y,p3.x,p3.y);
        }
    }
    __syncthreads();
    if (grp == 1) {
        #pragma unroll
        for (int i = 0; i < 8; i++) {
            float2 p0 = unpk(U2[i][0]), p1 = unpk(U2[i][1]);
            float2 p2 = unpk(U2[i][2]), p3 = unpk(U2[i][3]);
            const float* Br = &buf[(pq0+i)*VP + pd0];
            float4 b0 = *(const float4*)Br;
            float4 b1 = *(const float4*)(Br+4);
            float* Ug = g_U + (size_t)(b*Lz + qt*128 + pq0+i)*Ez + h*Dz + pd0;
            *(float4*)Ug     = make_float4(p0.x+b0.x, p0.y+b0.y, p1.x+b0.z, p1.y+b0.w);
            *(float4*)(Ug+4) = make_float4(p2.x+b1.x, p2.y+b1.y, p3.x+b1.z, p3.y+b1.w);
        }
    }

    red[tid] = partial; __syncthreads();
    for (int s = 128; s > 0; s >>= 1) { if (tid < s) red[tid] += red[tid+s]; __syncthreads(); }
    if (tid == 0) g_Spart[(b*Hz + h)*8 + qt] = red[0];
}

// ---------------- host launcher ----------------
static void* symaddr(const void* s) { void* p = nullptr; cudaGetSymbolAddress(&p, s); return p; }

extern "C" void kernel_launch(void* const* d_in, const int* in_sizes, int n_in,
                              void* d_out, int out_size) {
    const float* x    = (const float*)d_in[0];
    const void*  mask = d_in[1];
    const float* Wq   = (const float*)d_in[2];
    const float* Wk   = (const float*)d_in[3];
    const float* Wv   = (const float*)d_in[4];
    const float* Wo   = (const float*)d_in[5];
    const float* G    = (const float*)d_in[6];
    float* out = (float*)d_out;

    float* Q    = (float*)symaddr(g_Q);
    float* K    = (float*)symaddr(g_K);
    float* V    = (float*)symaddr(g_V);
    float* act  = (float*)symaddr(g_act);
    float* GAV  = (float*)symaddr(g_GAV);
    __nv_bfloat16* xhi  = (__nv_bfloat16*)symaddr(g_xhi);
    __nv_bfloat16* xlo  = (__nv_bfloat16*)symaddr(g_xlo);
    __nv_bfloat16* wqhi = (__nv_bfloat16*)symaddr(g_wqhi);
    __nv_bfloat16* wqlo = (__nv_bfloat16*)symaddr(g_wqlo);
    __nv_bfloat16* wkhi = (__nv_bfloat16*)symaddr(g_wkhi);
    __nv_bfloat16* wklo = (__nv_bfloat16*)symaddr(g_wklo);
    __nv_bfloat16* wvhi = (__nv_bfloat16*)symaddr(g_wvhi);
    __nv_bfloat16* wvlo = (__nv_bfloat16*)symaddr(g_wvlo);
    __nv_bfloat16* wohi = (__nv_bfloat16*)symaddr(g_wohi);
    __nv_bfloat16* wolo = (__nv_bfloat16*)symaddr(g_wolo);
    __nv_bfloat16* acthi= (__nv_bfloat16*)symaddr(g_acthi);
    __nv_bfloat16* actlo= (__nv_bfloat16*)symaddr(g_actlo);
    __nv_bfloat16* vthi = (__nv_bfloat16*)symaddr(g_vthi);
    __nv_bfloat16* vtlo = (__nv_bfloat16*)symaddr(g_vtlo);
    __nv_bfloat16* aohi = (__nv_bfloat16*)symaddr(g_aohi);
    __nv_bfloat16* aolo = (__nv_bfloat16*)symaddr(g_aolo);

    cudaFuncSetAttribute((const void*)attn_kernel,
                         cudaFuncAttributeMaxDynamicSharedMemorySize, ATTN_SMEM);

    detect_mask<<<1,1>>>((const unsigned char*)mask);
    convert_mask<<<32,256>>>(mask);
    softmax_g<<<1024,256>>>(G);
    gsum_rows<<<dim3(1024,8),256>>>();
    reduce_parts<<<8,256>>>(1);

    // splits
    split_f32<<<(Bz*Lz*Ez+255)/256,256>>>(x, xhi, xlo, Bz*Lz*Ez);
    split_f32<<<(Ez*Ez+255)/256,256>>>(Wq, wqhi, wqlo, Ez*Ez);
    split_f32<<<(Ez*Ez+255)/256,256>>>(Wk, wkhi, wklo, Ez*Ez);
    split_f32<<<(Ez*Ez+255)/256,256>>>(Wv, wvhi, wvlo, Ez*Ez);
    split_f32<<<(Ez*Ez+255)/256,256>>>(Wo, wohi, wolo, Ez*Ez);
    split_f32<<<(Lz*Lz+255)/256,256>>>(act, acthi, actlo, Lz*Lz);

    // QKV projections (HMMA)
    mma_gemm<<<dim3(4,64,1),256>>>(xhi, xlo, wqhi, wqlo, Q, Bz*Lz, Ez, Ez, 0,0,0);
    mma_gemm<<<dim3(4,64,1),256>>>(xhi, xlo, wkhi, wklo, K, Bz*Lz, Ez, Ez, 0,0,0);
    mma_gemm<<<dim3(4,64,1),256>>>(xhi, xlo, wvhi, wvlo, V, Bz*Lz, Ez, Ez, 0,0,0);

    tsplit_v<<<dim3(16,32,8),256>>>();

    attn_kernel<<<dim3(8,Hz,Bz),256,ATTN_SMEM>>>();
    reduce_parts<<<8,256>>>(0);
    rowscales<<<32,256>>>();

    // GAV_b = act @ VmT_b^T  (batched HMMA)
    mma_gemm<<<dim3(4,8,Bz),256>>>(acthi, actlo, vthi, vtlo, GAV, Lz, Ez, Lz,
                                   0, (long long)Ez*Lz, (long long)Lz*Ez);
    prep_out<<<(Bz*Lz*Ez+255)/256,256>>>();
    // out = Aout @ Wo^T
    mma_gemm<<<dim3(4,64,1),256>>>(aohi, aolo, wohi, wolo, out, Bz*Lz, Ez, Ez, 0,0,0);
}

// round 7
// speedup vs baseline: 2.0205x; 1.3835x over previous
#include <cuda_runtime.h>
#include <cuda_bf16.h>
#include <float.h>
#include <stdint.h>

#define Bz   8
#define Lz   1024
#define Ez   512
#define Hz   8
#define Dz   64

// ---------------- fast-math helpers ----------------
__device__ __forceinline__ float tanh_fast(float x) {
    float y; asm("tanh.approx.f32 %0, %1;" : "=f"(y) : "f"(x)); return y;
}
__device__ __forceinline__ float ex2f(float x) {
    float y; asm("ex2.approx.f32 %0, %1;" : "=f"(y) : "f"(x)); return y;
}
#define L2E 1.4426950408889634f

__device__ __forceinline__ uint32_t smem_u32(const void* p) {
    uint32_t a;
    asm("{ .reg .u64 t; cvta.to.shared.u64 t, %1; cvt.u32.u64 %0, t; }" : "=r"(a) : "l"(p));
    return a;
}
// pack two fp32 -> bf16x2 (lo = first arg)
__device__ __forceinline__ uint32_t pk2f(float lo, float hi) {
    uint32_t r; asm("cvt.rn.bf16x2.f32 %0, %1, %2;" : "=r"(r) : "f"(hi), "f"(lo)); return r;
}
__device__ __forceinline__ float bflo(uint32_t v) { return __uint_as_float(v << 16); }
__device__ __forceinline__ float bfhi(uint32_t v) { return __uint_as_float(v & 0xFFFF0000u); }

// ---------------- mma.sync helpers ----------------
__device__ __forceinline__ void ldmat4(uint32_t* r, uint32_t a) {
    asm volatile("ldmatrix.sync.aligned.m8n8.x4.shared.b16 {%0,%1,%2,%3}, [%4];"
                 : "=r"(r[0]), "=r"(r[1]), "=r"(r[2]), "=r"(r[3]) : "r"(a));
}
__device__ __forceinline__ void mma_bf16(float* c, const uint32_t* a, uint32_t b0, uint32_t b1) {
    asm volatile("mma.sync.aligned.m16n8k16.row.col.f32.bf16.bf16.f32 "
                 "{%0,%1,%2,%3}, {%4,%5,%6,%7}, {%8,%9}, {%0,%1,%2,%3};"
                 : "+f"(c[0]), "+f"(c[1]), "+f"(c[2]), "+f"(c[3])
                 : "r"(a[0]), "r"(a[1]), "r"(a[2]), "r"(a[3]), "r"(b0), "r"(b1));
}

// ---------------- device scratch ----------------
__device__ float g_mf[Bz*Lz];
__device__ int   g_maskKind;
__device__ float g_act[Lz*Lz];
__device__ float g_Q [Bz*Lz*Ez];
__device__ float g_K [Bz*Lz*Ez];
__device__ float g_V [Bz*Lz*Ez];
__device__ float g_U [Bz*Lz*Ez];
__device__ float g_GAV[Bz*Lz*Ez];
__device__ float g_Spart[Bz*Hz*8];
__device__ float g_Gpart[Bz*Lz];
__device__ float g_S[Bz];
__device__ float g_gs[Bz];
__device__ float g_rs0[Bz*Lz];
__device__ float g_rs1[Bz*Lz];

__device__ __nv_bfloat16 g_xhi[Bz*Lz*Ez],  g_xlo[Bz*Lz*Ez];
__device__ __nv_bfloat16 g_wqhi[Ez*Ez], g_wqlo[Ez*Ez];
__device__ __nv_bfloat16 g_wkhi[Ez*Ez], g_wklo[Ez*Ez];
__device__ __nv_bfloat16 g_wvhi[Ez*Ez], g_wvlo[Ez*Ez];
__device__ __nv_bfloat16 g_wohi[Ez*Ez], g_wolo[Ez*Ez];
__device__ __nv_bfloat16 g_acthi[Lz*Lz], g_actlo[Lz*Lz];
__device__ __nv_bfloat16 g_vthi[Bz*Ez*Lz], g_vtlo[Bz*Ez*Lz];
__device__ __nv_bfloat16 g_aohi[Bz*Lz*Ez], g_aolo[Bz*Lz*Ez];

// ---------------- mask detect / convert ----------------
__global__ void detect_mask(const unsigned char* m) {
    bool isInt32 = true;
    for (int i = 0; i < 64; i++) {
        if (m[4*i] > 1) isInt32 = false;
        if (m[4*i+1] | m[4*i+2] | m[4*i+3]) isInt32 = false;
    }
    if (isInt32) { g_maskKind = 0; return; }
    const unsigned int* w = (const unsigned int*)m;
    bool isFloat = true;
    for (int i = 0; i < 64; i++) {
        unsigned v = w[i];
        if (v != 0u && v != 0x3F800000u) isFloat = false;
    }
    g_maskKind = isFloat ? 2 : 1;
}

__global__ void convert_mask(const void* m) {
    int i = blockIdx.x*256 + threadIdx.x;
    if (i >= Bz*Lz) return;
    int k = g_maskKind;
    float v;
    if (k == 0)      v = ((const int*)m)[i] ? 1.f : 0.f;
    else if (k == 1) v = ((const unsigned char*)m)[i] ? 1.f : 0.f;
    else             v = ((const float*)m)[i];
    g_mf[i] = v;
}

// ---------------- fp32 -> bf16 hi/lo split ----------------
__global__ void split_f32(const float* __restrict__ src, __nv_bfloat16* __restrict__ hi,
                          __nv_bfloat16* __restrict__ lo, int n) {
    int i = blockIdx.x*256 + threadIdx.x;
    if (i >= n) return;
    float v = src[i];
    __nv_bfloat16 h = __float2bfloat16(v);
    hi[i] = h;
    lo[i] = __float2bfloat16(v - __bfloat162float(h));
}

// ---------------- softmax of G rows -> g_act ----------------
__global__ __launch_bounds__(256) void softmax_g(const float* __restrict__ G) {
    int q = blockIdx.x, t = threadIdx.x;
    const float* row = G + (size_t)q*Lz;
    __shared__ float red[256];
    float mx = -FLT_MAX;
    for (int k = t; k < Lz; k += 256) mx = fmaxf(mx, row[k]);
    red[t] = mx; __syncthreads();
    for (int s = 128; s > 0; s >>= 1) { if (t < s) red[t] = fmaxf(red[t], red[t+s]); __syncthreads(); }
    mx = red[0]; __syncthreads();
    float vals[4]; float sum = 0.f;
    for (int k = t, j = 0; k < Lz; k += 256, j++) { float e = __expf(row[k]-mx); vals[j] = e; sum += e; }
    red[t] = sum; __syncthreads();
    for (int s = 128; s > 0; s >>= 1) { if (t < s) red[t] += red[t+s]; __syncthreads(); }
    float inv = 1.f / red[0];
    for (int k = t, j = 0; k < Lz; k += 256, j++) g_act[(size_t)q*Lz + k] = vals[j]*inv;
}

__global__ __launch_bounds__(256) void gsum_rows() {
    int q = blockIdx.x, b = blockIdx.y, t = threadIdx.x;
    __shared__ float red[256];
    const float* arow = g_act + (size_t)q*Lz;
    const float* mf = g_mf + b*Lz;
    float s = 0.f;
    for (int k = t; k < Lz; k += 256) s += arow[k]*mf[k];
    red[t] = s; __syncthreads();
    for (int st = 128; st > 0; st >>= 1) { if (t < st) red[t] += red[t+st]; __syncthreads(); }
    if (t == 0) g_Gpart[b*Lz + q] = red[0] * mf[q];
}

__global__ __launch_bounds__(256) void reduce_parts(int which) {
    int b = blockIdx.x, t = threadIdx.x;
    __shared__ float red[256];
    float s = 0.f;
    if (which == 0) { for (int i = t; i < Hz*8; i += 256) s += g_Spart[b*Hz*8 + i]; }
    else            { for (int i = t; i < Lz;   i += 256) s += g_Gpart[b*Lz + i]; }
    red[t] = s; __syncthreads();
    for (int st = 128; st > 0; st >>= 1) { if (t < st) red[t] += red[t+st]; __syncthreads(); }
    if (t == 0) { if (which == 0) g_S[b] = red[0]; else g_gs[b] = red[0]; }
}

__global__ void rowscales() {
    int i = blockIdx.x*256 + threadIdx.x;
    if (i >= Bz*Lz) return;
    int b = i >> 10;
    const float TINY = 1.175494351e-38f;
    float mf = g_mf[i];
    g_rs0[i] = 0.5f*mf / fmaxf(g_S[b],  TINY);
    g_rs1[i] = 0.5f*mf / fmaxf(g_gs[b], TINY);
}

// masked-V transpose + split: vt[b][e][l] = mf[b,l]*V[b,l,e] (bf16 hi/lo)
__global__ __launch_bounds__(256) void tsplit_v() {
    __shared__ float ts[32][33];
    int b = blockIdx.z;
    int e0 = blockIdx.x*32, l0 = blockIdx.y*32;
    int tx = threadIdx.x & 31, ty = threadIdx.x >> 5;
    #pragma unroll
    for (int r = 0; r < 4; r++) {
        int l = ty*4 + r;
        ts[l][tx] = g_V[(size_t)(b*Lz + l0 + l)*Ez + e0 + tx] * g_mf[b*Lz + l0 + l];
    }
    __syncthreads();
    #pragma unroll
    for (int r = 0; r < 4; r++) {
        int e = ty*4 + r;
        float v = ts[tx][e];
        __nv_bfloat16 h = __float2bfloat16(v);
        size_t o = ((size_t)b*Ez + e0 + e)*Lz + l0 + tx;
        g_vthi[o] = h;
        g_vtlo[o] = __float2bfloat16(v - __bfloat162float(h));
    }
}

// A_out = rs0*U + rs1*GAV  -> bf16 hi/lo
__global__ void prep_out() {
    int i = blockIdx.x*256 + threadIdx.x;
    if (i >= Bz*Lz*Ez) return;
    int row = i >> 9;
    float v = g_rs0[row]*g_U[i] + g_rs1[row]*g_GAV[i];
    __nv_bfloat16 h = __float2bfloat16(v);
    g_aohi[i] = h;
    g_aolo[i] = __float2bfloat16(v - __bfloat162float(h));
}

// ---------------- HMMA bf16-split GEMM (unchanged from R6) ----------------
#define T_AHI 0
#define T_ALO 10240
#define T_BHI 20480
#define T_BLO 30720

__global__ __launch_bounds__(256, 1)
void mma_gemm(const __nv_bfloat16* __restrict__ Ahi, const __nv_bfloat16* __restrict__ Alo,
              const __nv_bfloat16* __restrict__ Bhi, const __nv_bfloat16* __restrict__ Blo,
              float* __restrict__ C, int M, int N, int K,
              long long aStride, long long bStride, long long cStride) {
    __shared__ char smc[40960];
    uint32_t sb = smem_u32(smc);
    int tid = threadIdx.x, lane = tid & 31, wid = tid >> 5;
    int z = blockIdx.z;
    int bn = blockIdx.x*128, bm = blockIdx.y*128;
    Ahi += (long long)z*aStride; Alo += (long long)z*aStride;
    Bhi += (long long)z*bStride; Blo += (long long)z*bStride;
    C   += (long long)z*cStride;
    int wm = wid & 1, wn = wid >> 1;
    const char* pAh = (const char*)(Ahi + (size_t)bm*K);
    const char* pAl = (const char*)(Alo + (size_t)bm*K);
    const char* pBh = (const char*)(Bhi + (size_t)bn*K);
    const char* pBl = (const char*)(Blo + (size_t)bn*K);

    float acc[4][4][4] = {};

    uint32_t aRow = wm*64 + (lane & 15);
    uint32_t aK8  = (lane >> 4) * 8;
    uint32_t bRow = wn*32 + (lane & 7) + ((lane >> 4) << 3);
    uint32_t bK8  = ((lane >> 3) & 1) * 8;

    int nChunks = K >> 5;
    for (int kc = 0; kc < nChunks; kc++) {
        __syncthreads();
        #pragma unroll
        for (int i = tid; i < 512; i += 256) {
            int r = i >> 2, c = i & 3;
            size_t go = (size_t)r*K*2 + (size_t)kc*64 + c*16;
            uint32_t so = r*80 + c*16;
            *(uint4*)(smc + T_AHI + so) = *(const uint4*)(pAh + go);
            *(uint4*)(smc + T_ALO + so) = *(const uint4*)(pAl + go);
            *(uint4*)(smc + T_BHI + so) = *(const uint4*)(pBh + go);
            *(uint4*)(smc + T_BLO + so) = *(const uint4*)(pBl + go);
        }
        __syncthreads();
        #pragma unroll
        for (int ks = 0; ks < 2; ks++) {
            uint32_t ah[4][4], al[4][4], bh[2][4], bl[2][4];
            #pragma unroll
            for (int mi = 0; mi < 4; mi++) {
                uint32_t ad = sb + T_AHI + ((aRow + mi*16)*40 + ks*16 + aK8)*2;
                ldmat4(ah[mi], ad);
                ldmat4(al[mi], ad + (T_ALO - T_AHI));
            }
            #pragma unroll
            for (int bj = 0; bj < 2; bj++) {
                uint32_t ad = sb + T_BHI + ((bRow + bj*16)*40 + ks*16 + bK8)*2;
                ldmat4(bh[bj], ad);
                ldmat4(bl[bj], ad + (T_BLO - T_BHI));
            }
            #pragma unroll
            for (int mi = 0; mi < 4; mi++)
                #pragma unroll
                for (int nj = 0; nj < 4; nj++) {
                    int bj = nj >> 1, pr = (nj & 1)*2;
                    mma_bf16(acc[mi][nj], ah[mi], bh[bj][pr], bh[bj][pr+1]);
                    mma_bf16(acc[mi][nj], ah[mi], bl[bj][pr], bl[bj][pr+1]);
                    mma_bf16(acc[mi][nj], al[mi], bh[bj][pr], bh[bj][pr+1]);
                }
        }
    }

    int r0 = bm + wm*64 + (lane >> 2);
    int c0 = bn + wn*32 + (lane & 3)*2;
    #pragma unroll
    for (int mi = 0; mi < 4; mi++)
        #pragma unroll
        for (int nj = 0; nj < 4; nj++) {
            float* p = C + (size_t)(r0 + mi*16)*N + c0 + nj*8;
            *(float2*)p                 = make_float2(acc[mi][nj][0], acc[mi][nj][1]);
            *(float2*)(p + (size_t)8*N) = make_float2(acc[mi][nj][2], acc[mi][nj][3]);
        }
}

// ---------------- tensor-core attention ----------------
// Per block: (qt, h, b); 512 threads.
// S phase: warps (wm 4 x wn 4); S = QK^T 3-product; P = ex2(tanh(S/8)*L2E)*mk -> smem bf16 hi/lo.
// PV phase: warps (wq 8 x wd 2); U += P @ Vt^T (3-product), U in regs, direct store.
#define A_QHI 0
#define A_QLO 18432
#define A_KHI 36864
#define A_KLO 55296
#define A_VHI 73728
#define A_VLO 91136
#define A_PHI 108544
#define A_PLO 143360
#define A_MQ  178176
#define A_MK  178688
#define A_RED 179200
#define AT_SMEM (179200 + 2048)

__global__ __launch_bounds__(512, 1) void attn_mma() {
    extern __shared__ char smc[];
    uint32_t sb = smem_u32(smc);
    float* mqf = (float*)(smc + A_MQ);
    float* mkf = (float*)(smc + A_MK);
    float* red = (float*)(smc + A_RED);

    int tid = threadIdx.x, lane = tid & 31, wid = tid >> 5;
    int qt = blockIdx.x, h = blockIdx.y, b = blockIdx.z;

    // S-phase warp mapping
    int wm = wid & 3, wn = wid >> 2;
    // PV-phase warp mapping
    int wq = wid & 7, wd = wid >> 3;

    const float* Qg = g_Q + ((size_t)(b*Lz + qt*128))*Ez + h*64;
    const float* Kg = g_K + ((size_t)(b*Lz))*Ez + h*64;
    const __nv_bfloat16* Vth = g_vthi + ((size_t)(b*Ez + h*64))*Lz;
    const __nv_bfloat16* Vtl = g_vtlo + ((size_t)(b*Ez + h*64))*Lz;

    // load Q (fp32 -> bf16 hi/lo, rows 128 x 64, stride 144B)
    for (int i = tid; i < 2048; i += 512) {
        int r = i >> 4, c4 = (i & 15)*4;
        float4 v = *(const float4*)(Qg + (size_t)r*Ez + c4);
        uint32_t h01 = pk2f(v.x, v.y), h23 = pk2f(v.z, v.w);
        uint32_t l01 = pk2f(v.x - bflo(h01), v.y - bfhi(h01));
        uint32_t l23 = pk2f(v.z - bflo(h23), v.w - bfhi(h23));
        uint32_t off = r*144 + c4*2;
        *(uint2*)(smc + A_QHI + off) = make_uint2(h01, h23);
        *(uint2*)(smc + A_QLO + off) = make_uint2(l01, l23);
    }
    if (tid < 128) mqf[tid] = g_mf[b*Lz + qt*128 + tid];

    // ldmatrix address components
    uint32_t qRow = wm*32 + (lane & 15);
    uint32_t qK8  = (lane >> 4)*8;
    uint32_t kRowB = wn*32 + (lane & 7) + ((lane >> 4) << 3);
    uint32_t kK8  = ((lane >> 3) & 1)*8;
    uint32_t pRow = wq*16 + (lane & 15);
    uint32_t pK8  = (lane >> 4)*8;
    uint32_t vRowB = wd*32 + (lane & 7) + ((lane >> 4) << 3);
    uint32_t vK8  = ((lane >> 3) & 1)*8;

    float U[4][4] = {};
    float partial = 0.f;

    for (int kt = 0; kt < 8; kt++) {
        __syncthreads();   // prior PV done before overwriting K/V
        // load K tile (fp32 -> hi/lo)
        for (int i = tid; i < 2048; i += 512) {
            int r = i >> 4, c4 = (i & 15)*4;
            float4 v = *(const float4*)(Kg + (size_t)(kt*128 + r)*Ez + c4);
            uint32_t h01 = pk2f(v.x, v.y), h23 = pk2f(v.z, v.w);
            uint32_t l01 = pk2f(v.x - bflo(h01), v.y - bfhi(h01));
            uint32_t l23 = pk2f(v.z - bflo(h23), v.w - bfhi(h23));
            uint32_t off = r*144 + c4*2;
            *(uint2*)(smc + A_KHI + off) = make_uint2(h01, h23);
            *(uint2*)(smc + A_KLO + off) = make_uint2(l01, l23);
        }
        // load Vt tile (bf16, rows d 64 x k 128, stride 272B)
        for (int i = tid; i < 1024; i += 512) {
            int r = i >> 4, c8 = (i & 15)*8;
            uint4 vh = *(const uint4*)(Vth + (size_t)r*Lz + kt*128 + c8);
            uint4 vl = *(const uint4*)(Vtl + (size_t)r*Lz + kt*128 + c8);
            uint32_t off = r*272 + c8*2;
            *(uint4*)(smc + A_VHI + off) = vh;
            *(uint4*)(smc + A_VLO + off) = vl;
        }
        if (tid < 128) mkf[tid] = g_mf[b*Lz + kt*128 + tid];
        __syncthreads();

        // ---- S = Q K^T (3-product) ----
        float S[2][4][4] = {};
        #pragma unroll
        for (int ks = 0; ks < 4; ks++) {
            uint32_t ah[2][4], al[2][4], bh[2][4], bl[2][4];
            #pragma unroll
            for (int mi = 0; mi < 2; mi++) {
                uint32_t ad = sb + A_QHI + (qRow + mi*16)*144 + (ks*16 + qK8)*2;
                ldmat4(ah[mi], ad);
                ldmat4(al[mi], ad + (A_QLO - A_QHI));
            }
            #pragma unroll
            for (int nb = 0; nb < 2; nb++) {
                uint32_t ad = sb + A_KHI + (kRowB + nb*16)*144 + (ks*16 + kK8)*2;
                ldmat4(bh[nb], ad);
                ldmat4(bl[nb], ad + (A_KLO - A_KHI));
            }
            #pragma unroll
            for (int mi = 0; mi < 2; mi++)
                #pragma unroll
                for (int nj = 0; nj < 4; nj++) {
                    int nb = nj >> 1, pr = (nj & 1)*2;
                    mma_bf16(S[mi][nj], ah[mi], bh[nb][pr], bh[nb][pr+1]);
                    mma_bf16(S[mi][nj], ah[mi], bl[nb][pr], bl[nb][pr+1]);
                    mma_bf16(S[mi][nj], al[mi], bh[nb][pr], bh[nb][pr+1]);
                }
        }

        // ---- P = ex2(tanh(S/8)*L2E)*mk -> smem (bf16 hi/lo) ----
        {
            int r0 = wm*32 + (lane >> 2);
            int c0b = wn*32 + (lane & 3)*2;
            #pragma unroll
            for (int mi = 0; mi < 2; mi++) {
                int row0 = r0 + mi*16, row1 = row0 + 8;
                float mq0 = mqf[row0], mq1 = mqf[row1];
                #pragma unroll
                for (int nj = 0; nj < 4; nj++) {
                    int c0 = c0b + nj*8;
                    float mk0 = mkf[c0], mk1 = mkf[c0+1];
                    float p0 = ex2f(tanh_fast(S[mi][nj][0]*0.125f)*L2E)*mk0;
                    float p1 = ex2f(tanh_fast(S[mi][nj][1]*0.125f)*L2E)*mk1;
                    float p2 = ex2f(tanh_fast(S[mi][nj][2]*0.125f)*L2E)*mk0;
                    float p3 = ex2f(tanh_fast(S[mi][nj][3]*0.125f)*L2E)*mk1;
                    partial += mq0*(p0+p1) + mq1*(p2+p3);
                    uint32_t h01 = pk2f(p0, p1), h23 = pk2f(p2, p3);
                    uint32_t l01 = pk2f(p0 - bflo(h01), p1 - bfhi(h01));
                    uint32_t l23 = pk2f(p2 - bflo(h23), p3 - bfhi(h23));
                    uint32_t o0 = row0*272 + c0*2, o1 = row1*272 + c0*2;
                    *(uint32_t*)(smc + A_PHI + o0) = h01;
                    *(uint32_t*)(smc + A_PHI + o1) = h23;
                    *(uint32_t*)(smc + A_PLO + o0) = l01;
                    *(uint32_t*)(smc + A_PLO + o1) = l23;
                }
            }
        }
        __syncthreads();

        // ---- U += P @ Vt^T  (warp = q16 x d32, full k128 contraction) ----
        #pragma unroll
        for (int ch = 0; ch < 8; ch++) {
            uint32_t ph[4], pl[4];
            uint32_t pa = sb + A_PHI + pRow*272 + (ch*16 + pK8)*2;
            ldmat4(ph, pa);
            ldmat4(pl, pa + (A_PLO - A_PHI));
            #pragma unroll
            for (int g = 0; g < 2; g++) {
                uint32_t vh[4], vl[4];
                uint32_t va = sb + A_VHI + (vRowB + g*16)*272 + (ch*16 + vK8)*2;
                ldmat4(vh, va);
                ldmat4(vl, va + (A_VLO - A_VHI));
                mma_bf16(U[g*2],   ph, vh[0], vh[1]);
                mma_bf16(U[g*2],   ph, vl[0], vl[1]);
                mma_bf16(U[g*2],   pl, vh[0], vh[1]);
                mma_bf16(U[g*2+1], ph, vh[2], vh[3]);
                mma_bf16(U[g*2+1], ph, vl[2], vl[3]);
                mma_bf16(U[g*2+1], pl, vh[2], vh[3]);
            }
        }
    }

    // ---- write U ----
    {
        int r = wq*16 + (lane >> 2);
        int cb = wd*32 + (lane & 3)*2;
        float* Ug = g_U + ((size_t)(b*Lz + qt*128))*Ez + h*64;
        #pragma unroll
        for (int dj = 0; dj < 4; dj++) {
            int c = cb + dj*8;
            *(float2*)(Ug + (size_t)r*Ez + c)     = make_float2(U[dj][0], U[dj][1]);
            *(float2*)(Ug + (size_t)(r+8)*Ez + c) = make_float2(U[dj][2], U[dj][3]);
        }
    }

    // ---- Spart reduction ----
    red[tid] = partial; __syncthreads();
    for (int s = 256; s > 0; s >>= 1) { if (tid < s) red[tid] += red[tid+s]; __syncthreads(); }
    if (tid == 0) g_Spart[(b*Hz + h)*8 + qt] = red[0];
}

// ---------------- host launcher ----------------
static void* symaddr(const void* s) { void* p = nullptr; cudaGetSymbolAddress(&p, s); return p; }

extern "C" void kernel_launch(void* const* d_in, const int* in_sizes, int n_in,
                              void* d_out, int out_size) {
    const float* x    = (const float*)d_in[0];
    const void*  mask = d_in[1];
    const float* Wq   = (const float*)d_in[2];
    const float* Wk   = (const float*)d_in[3];
    const float* Wv   = (const float*)d_in[4];
    const float* Wo   = (const float*)d_in[5];
    const float* G    = (const float*)d_in[6];
    float* out = (float*)d_out;

    float* Q    = (float*)symaddr(g_Q);
    float* K    = (float*)symaddr(g_K);
    float* V    = (float*)symaddr(g_V);
    float* act  = (float*)symaddr(g_act);
    float* GAV  = (float*)symaddr(g_GAV);
    __nv_bfloat16* xhi  = (__nv_bfloat16*)symaddr(g_xhi);
    __nv_bfloat16* xlo  = (__nv_bfloat16*)symaddr(g_xlo);
    __nv_bfloat16* wqhi = (__nv_bfloat16*)symaddr(g_wqhi);
    __nv_bfloat16* wqlo = (__nv_bfloat16*)symaddr(g_wqlo);
    __nv_bfloat16* wkhi = (__nv_bfloat16*)symaddr(g_wkhi);
    __nv_bfloat16* wklo = (__nv_bfloat16*)symaddr(g_wklo);
    __nv_bfloat16* wvhi = (__nv_bfloat16*)symaddr(g_wvhi);
    __nv_bfloat16* wvlo = (__nv_bfloat16*)symaddr(g_wvlo);
    __nv_bfloat16* wohi = (__nv_bfloat16*)symaddr(g_wohi);
    __nv_bfloat16* wolo = (__nv_bfloat16*)symaddr(g_wolo);
    __nv_bfloat16* acthi= (__nv_bfloat16*)symaddr(g_acthi);
    __nv_bfloat16* actlo= (__nv_bfloat16*)symaddr(g_actlo);
    __nv_bfloat16* vthi = (__nv_bfloat16*)symaddr(g_vthi);
    __nv_bfloat16* vtlo = (__nv_bfloat16*)symaddr(g_vtlo);
    __nv_bfloat16* aohi = (__nv_bfloat16*)symaddr(g_aohi);
    __nv_bfloat16* aolo = (__nv_bfloat16*)symaddr(g_aolo);

    cudaFuncSetAttribute((const void*)attn_mma,
                         cudaFuncAttributeMaxDynamicSharedMemorySize, AT_SMEM);

    detect_mask<<<1,1>>>((const unsigned char*)mask);
    convert_mask<<<32,256>>>(mask);
    softmax_g<<<1024,256>>>(G);
    gsum_rows<<<dim3(1024,8),256>>>();
    reduce_parts<<<8,256>>>(1);

    split_f32<<<(Bz*Lz*Ez+255)/256,256>>>(x, xhi, xlo, Bz*Lz*Ez);
    split_f32<<<(Ez*Ez+255)/256,256>>>(Wq, wqhi, wqlo, Ez*Ez);
    split_f32<<<(Ez*Ez+255)/256,256>>>(Wk, wkhi, wklo, Ez*Ez);
    split_f32<<<(Ez*Ez+255)/256,256>>>(Wv, wvhi, wvlo, Ez*Ez);
    split_f32<<<(Ez*Ez+255)/256,256>>>(Wo, wohi, wolo, Ez*Ez);
    split_f32<<<(Lz*Lz+255)/256,256>>>(act, acthi, actlo, Lz*Lz);

    mma_gemm<<<dim3(4,64,1),256>>>(xhi, xlo, wqhi, wqlo, Q, Bz*Lz, Ez, Ez, 0,0,0);
    mma_gemm<<<dim3(4,64,1),256>>>(xhi, xlo, wkhi, wklo, K, Bz*Lz, Ez, Ez, 0,0,0);
    mma_gemm<<<dim3(4,64,1),256>>>(xhi, xlo, wvhi, wvlo, V, Bz*Lz, Ez, Ez, 0,0,0);

    tsplit_v<<<dim3(16,32,8),256>>>();

    attn_mma<<<dim3(8,Hz,Bz),512,AT_SMEM>>>();
    reduce_parts<<<8,256>>>(0);
    rowscales<<<32,256>>>();

    mma_gemm<<<dim3(4,8,Bz),256>>>(acthi, actlo, vthi, vtlo, GAV, Lz, Ez, Lz,
                                   0, (long long)Ez*Lz, (long long)Lz*Ez);
    prep_out<<<(Bz*Lz*Ez+255)/256,256>>>();
    mma_gemm<<<dim3(4,64,1),256>>>(aohi, aolo, wohi, wolo, out, Bz*Lz, Ez, Ez, 0,0,0);
}

// round 8
// speedup vs baseline: 2.3159x; 1.1462x over previous
#include <cuda_runtime.h>
#include <cuda_bf16.h>
#include <float.h>
#include <stdint.h>

#define Bz   8
#define Lz   1024
#define Ez   512
#define Hz   8
#define Dz   64

// ---------------- fast-math helpers ----------------
__device__ __forceinline__ float tanh_fast(float x) {
    float y; asm("tanh.approx.f32 %0, %1;" : "=f"(y) : "f"(x)); return y;
}
__device__ __forceinline__ float ex2f(float x) {
    float y; asm("ex2.approx.f32 %0, %1;" : "=f"(y) : "f"(x)); return y;
}
#define L2E 1.4426950408889634f

__device__ __forceinline__ uint32_t smem_u32(const void* p) {
    uint32_t a;
    asm("{ .reg .u64 t; cvta.to.shared.u64 t, %1; cvt.u32.u64 %0, t; }" : "=r"(a) : "l"(p));
    return a;
}
// pack two fp32 -> bf16x2 (lo = first arg)
__device__ __forceinline__ uint32_t pk2f(float lo, float hi) {
    uint32_t r; asm("cvt.rn.bf16x2.f32 %0, %1, %2;" : "=r"(r) : "f"(hi), "f"(lo)); return r;
}
__device__ __forceinline__ float bflo(uint32_t v) { return __uint_as_float(v << 16); }
__device__ __forceinline__ float bfhi(uint32_t v) { return __uint_as_float(v & 0xFFFF0000u); }

// ---------------- mma.sync / cp.async helpers ----------------
__device__ __forceinline__ void ldmat4(uint32_t* r, uint32_t a) {
    asm volatile("ldmatrix.sync.aligned.m8n8.x4.shared.b16 {%0,%1,%2,%3}, [%4];"
                 : "=r"(r[0]), "=r"(r[1]), "=r"(r[2]), "=r"(r[3]) : "r"(a));
}
__device__ __forceinline__ void mma_bf16(float* c, const uint32_t* a, uint32_t b0, uint32_t b1) {
    asm volatile("mma.sync.aligned.m16n8k16.row.col.f32.bf16.bf16.f32 "
                 "{%0,%1,%2,%3}, {%4,%5,%6,%7}, {%8,%9}, {%0,%1,%2,%3};"
                 : "+f"(c[0]), "+f"(c[1]), "+f"(c[2]), "+f"(c[3])
                 : "r"(a[0]), "r"(a[1]), "r"(a[2]), "r"(a[3]), "r"(b0), "r"(b1));
}
__device__ __forceinline__ void cp16(uint32_t s, const void* g) {
    asm volatile("cp.async.cg.shared.global [%0], [%1], 16;" :: "r"(s), "l"(g));
}
__device__ __forceinline__ void cp_commit() { asm volatile("cp.async.commit_group;"); }
template<int N> __device__ __forceinline__ void cp_wait() {
    asm volatile("cp.async.wait_group %0;" :: "n"(N));
}

// ---------------- device scratch ----------------
__device__ float g_mf[Bz*Lz];
__device__ int   g_maskKind;
__device__ float g_act[Lz*Lz];
__device__ float g_V [Bz*Lz*Ez];
__device__ float g_U [Bz*Lz*Ez];
__device__ float g_GAV[Bz*Lz*Ez];
__device__ float g_Spart[Bz*Hz*8];
__device__ float g_Gpart[Bz*Lz];
__device__ float g_S[Bz];
__device__ float g_gs[Bz];
__device__ float g_rs0[Bz*Lz];
__device__ float g_rs1[Bz*Lz];

__device__ __nv_bfloat16 g_xhi[Bz*Lz*Ez],  g_xlo[Bz*Lz*Ez];
__device__ __nv_bfloat16 g_qhi[Bz*Lz*Ez],  g_qlo[Bz*Lz*Ez];
__device__ __nv_bfloat16 g_khi[Bz*Lz*Ez],  g_klo[Bz*Lz*Ez];
__device__ __nv_bfloat16 g_wqhi[Ez*Ez], g_wqlo[Ez*Ez];
__device__ __nv_bfloat16 g_wkhi[Ez*Ez], g_wklo[Ez*Ez];
__device__ __nv_bfloat16 g_wvhi[Ez*Ez], g_wvlo[Ez*Ez];
__device__ __nv_bfloat16 g_wohi[Ez*Ez], g_wolo[Ez*Ez];
__device__ __nv_bfloat16 g_acthi[Lz*Lz], g_actlo[Lz*Lz];
__device__ __nv_bfloat16 g_vthi[Bz*Ez*Lz], g_vtlo[Bz*Ez*Lz];
__device__ __nv_bfloat16 g_aohi[Bz*Lz*Ez], g_aolo[Bz*Lz*Ez];

// ---------------- mask detect / convert ----------------
__global__ void detect_mask(const unsigned char* m) {
    bool isInt32 = true;
    for (int i = 0; i < 64; i++) {
        if (m[4*i] > 1) isInt32 = false;
        if (m[4*i+1] | m[4*i+2] | m[4*i+3]) isInt32 = false;
    }
    if (isInt32) { g_maskKind = 0; return; }
    const unsigned int* w = (const unsigned int*)m;
    bool isFloat = true;
    for (int i = 0; i < 64; i++) {
        unsigned v = w[i];
        if (v != 0u && v != 0x3F800000u) isFloat = false;
    }
    g_maskKind = isFloat ? 2 : 1;
}

__global__ void convert_mask(const void* m) {
    int i = blockIdx.x*256 + threadIdx.x;
    if (i >= Bz*Lz) return;
    int k = g_maskKind;
    float v;
    if (k == 0)      v = ((const int*)m)[i] ? 1.f : 0.f;
    else if (k == 1) v = ((const unsigned char*)m)[i] ? 1.f : 0.f;
    else             v = ((const float*)m)[i];
    g_mf[i] = v;
}

// ---------------- fp32 -> bf16 hi/lo splits ----------------
__global__ void split_f32(const float* __restrict__ src, __nv_bfloat16* __restrict__ hi,
                          __nv_bfloat16* __restrict__ lo, int n) {
    int i = blockIdx.x*256 + threadIdx.x;
    if (i >= n) return;
    float v = src[i];
    __nv_bfloat16 h = __float2bfloat16(v);
    hi[i] = h;
    lo[i] = __float2bfloat16(v - __bfloat162float(h));
}

__global__ void split_w(const float* __restrict__ wq, const float* __restrict__ wk,
                        const float* __restrict__ wv, const float* __restrict__ wo) {
    int which = blockIdx.y;
    int i = blockIdx.x*256 + threadIdx.x;
    if (i >= Ez*Ez) return;
    const float* s; __nv_bfloat16 *hp, *lp;
    if      (which == 0) { s = wq; hp = g_wqhi; lp = g_wqlo; }
    else if (which == 1) { s = wk; hp = g_wkhi; lp = g_wklo; }
    else if (which == 2) { s = wv; hp = g_wvhi; lp = g_wvlo; }
    else                 { s = wo; hp = g_wohi; lp = g_wolo; }
    float v = s[i];
    __nv_bfloat16 h = __float2bfloat16(v);
    hp[i] = h;
    lp[i] = __float2bfloat16(v - __bfloat162float(h));
}

// ---------------- softmax of G rows -> g_act (+ bf16 hi/lo) ----------------
__global__ __launch_bounds__(256) void softmax_g(const float* __restrict__ G) {
    int q = blockIdx.x, t = threadIdx.x;
    const float* row = G + (size_t)q*Lz;
    __shared__ float red[256];
    float mx = -FLT_MAX;
    for (int k = t; k < Lz; k += 256) mx = fmaxf(mx, row[k]);
    red[t] = mx; __syncthreads();
    for (int s = 128; s > 0; s >>= 1) { if (t < s) red[t] = fmaxf(red[t], red[t+s]); __syncthreads(); }
    mx = red[0]; __syncthreads();
    float vals[4]; float sum = 0.f;
    for (int k = t, j = 0; k < Lz; k += 256, j++) { float e = __expf(row[k]-mx); vals[j] = e; sum += e; }
    red[t] = sum; __syncthreads();
    for (int s = 128; s > 0; s >>= 1) { if (t < s) red[t] += red[t+s]; __syncthreads(); }
    float inv = 1.f / red[0];
    for (int k = t, j = 0; k < Lz; k += 256, j++) {
        float v = vals[j]*inv;
        g_act[(size_t)q*Lz + k] = v;
        __nv_bfloat16 h = __float2bfloat16(v);
        g_acthi[(size_t)q*Lz + k] = h;
        g_actlo[(size_t)q*Lz + k] = __float2bfloat16(v - __bfloat162float(h));
    }
}

// gsum v2: 128 blocks x 8 rows; mf staged in smem once per block
__global__ __launch_bounds__(256) void gsum2() {
    __shared__ float smf[Bz*Lz/8*8];     // 8192 floats = 32KB
    __shared__ float part[8][8];
    int t = threadIdx.x;
    for (int i = t; i < Bz*Lz; i += 256) smf[i] = g_mf[i];
    __syncthreads();
    for (int qi = 0; qi < 8; qi++) {
        int q = blockIdx.x*8 + qi;
        const float* arow = g_act + (size_t)q*Lz;
        float s[8] = {};
        for (int k = t; k < Lz; k += 256) {
            float a = arow[k];
            #pragma unroll
            for (int b2 = 0; b2 < 8; b2++) s[b2] += a * smf[b2*Lz + k];
        }
        #pragma unroll
        for (int o = 16; o; o >>= 1)
            #pragma unroll
            for (int b2 = 0; b2 < 8; b2++) s[b2] += __shfl_down_sync(0xffffffffu, s[b2], o);
        if ((t & 31) == 0)
            #pragma unroll
            for (int b2 = 0; b2 < 8; b2++) part[t>>5][b2] = s[b2];
        __syncthreads();
        if (t < 8) {
            float r = 0.f;
            #pragma unroll
            for (int w = 0; w < 8; w++) r += part[w][t];
            g_Gpart[t*Lz + q] = r * smf[t*Lz + q];
        }
        __syncthreads();
    }
}

__global__ __launch_bounds__(256) void reduce_parts(int which) {
    int b = blockIdx.x, t = threadIdx.x;
    __shared__ float red[256];
    float s = 0.f;
    if (which == 0) { for (int i = t; i < Hz*8; i += 256) s += g_Spart[b*Hz*8 + i]; }
    else            { for (int i = t; i < Lz;   i += 256) s += g_Gpart[b*Lz + i]; }
    red[t] = s; __syncthreads();
    for (int st = 128; st > 0; st >>= 1) { if (t < st) red[t] += red[t+st]; __syncthreads(); }
    if (t == 0) { if (which == 0) g_S[b] = red[0]; else g_gs[b] = red[0]; }
}

__global__ void rowscales() {
    int i = blockIdx.x*256 + threadIdx.x;
    if (i >= Bz*Lz) return;
    int b = i >> 10;
    const float TINY = 1.175494351e-38f;
    float mf = g_mf[i];
    g_rs0[i] = 0.5f*mf / fmaxf(g_S[b],  TINY);
    g_rs1[i] = 0.5f*mf / fmaxf(g_gs[b], TINY);
}

// masked-V transpose + split
__global__ __launch_bounds__(256) void tsplit_v() {
    __shared__ float ts[32][33];
    int b = blockIdx.z;
    int e0 = blockIdx.x*32, l0 = blockIdx.y*32;
    int tx = threadIdx.x & 31, ty = threadIdx.x >> 5;
    #pragma unroll
    for (int r = 0; r < 4; r++) {
        int l = ty*4 + r;
        ts[l][tx] = g_V[(size_t)(b*Lz + l0 + l)*Ez + e0 + tx] * g_mf[b*Lz + l0 + l];
    }
    __syncthreads();
    #pragma unroll
    for (int r = 0; r < 4; r++) {
        int e = ty*4 + r;
        float v = ts[tx][e];
        __nv_bfloat16 h = __float2bfloat16(v);
        size_t o = ((size_t)b*Ez + e0 + e)*Lz + l0 + tx;
        g_vthi[o] = h;
        g_vtlo[o] = __float2bfloat16(v - __bfloat162float(h));
    }
}

// A_out = rs0*U + rs1*GAV  -> bf16 hi/lo
__global__ void prep_out() {
    int i = blockIdx.x*256 + threadIdx.x;
    if (i >= Bz*Lz*Ez) return;
    int row = i >> 9;
    float v = g_rs0[row]*g_U[i] + g_rs1[row]*g_GAV[i];
    __nv_bfloat16 h = __float2bfloat16(v);
    g_aohi[i] = h;
    g_aolo[i] = __float2bfloat16(v - __bfloat162float(h));
}

// ---------------- pipelined HMMA bf16-split GEMM core ----------------
// 128x128 block, 8 warps (2m x 4n), K chunks of 32, cp.async double buffer.
// outmode: Chi==nullptr -> fp32 C; else bf16 hi/lo.
#define T_ALO 10240
#define T_BHI 20480
#define T_BLO 30720
#define BUFSZ 40960
#define PIPE_SMEM (2*BUFSZ)

__device__ __forceinline__ void gemm_core(
    char* smc, uint32_t sb,
    const __nv_bfloat16* Ahi, const __nv_bfloat16* Alo,
    const __nv_bfloat16* Bhi, const __nv_bfloat16* Blo,
    float* C, __nv_bfloat16* Chi, __nv_bfloat16* Clo,
    int N, int K, int bm, int bn)
{
    int tid = threadIdx.x, lane = tid & 31, wid = tid >> 5;
    int wm = wid & 1, wn = wid >> 1;
    const char* pAh = (const char*)(Ahi + (size_t)bm*K);
    const char* pAl = (const char*)(Alo + (size_t)bm*K);
    const char* pBh = (const char*)(Bhi + (size_t)bn*K);
    const char* pBl = (const char*)(Blo + (size_t)bn*K);

    float acc[4][4][4] = {};

    uint32_t aRow = wm*64 + (lane & 15);
    uint32_t aK8  = (lane >> 4) * 8;
    uint32_t bRow = wn*32 + (lane & 7) + ((lane >> 4) << 3);
    uint32_t bK8  = ((lane >> 3) & 1) * 8;

    int nChunks = K >> 5;

    // chunk loader via cp.async
    auto load_chunk = [&](int kc, int bsel) {
        uint32_t base = sb + bsel*BUFSZ;
        #pragma unroll
        for (int i = tid; i < 512; i += 256) {
            int r = i >> 2, c = i & 3;
            size_t go = (size_t)r*K*2 + (size_t)kc*64 + c*16;
            uint32_t so = r*80 + c*16;
            cp16(base + so,          pAh + go);
            cp16(base + T_ALO + so,  pAl + go);
            cp16(base + T_BHI + so,  pBh + go);
            cp16(base + T_BLO + so,  pBl + go);
        }
        cp_commit();
    };

    load_chunk(0, 0);

    for (int kc = 0; kc < nChunks; kc++) {
        __syncthreads();   // all reads of buffer (kc+1)&1 (chunk kc-1) complete
        if (kc + 1 < nChunks) { load_chunk(kc+1, (kc+1)&1); cp_wait<1>(); }
        else                  { cp_wait<0>(); }
        __syncthreads();
        uint32_t bofs = sb + (kc&1)*BUFSZ;
        #pragma unroll
        for (int ks = 0; ks < 2; ks++) {
            uint32_t ah[4][4], al[4][4], bh[2][4], bl[2][4];
            #pragma unroll
            for (int mi = 0; mi < 4; mi++) {
                uint32_t ad = bofs + ((aRow + mi*16)*40 + ks*16 + aK8)*2;
                ldmat4(ah[mi], ad);
                ldmat4(al[mi], ad + T_ALO);
            }
            #pragma unroll
            for (int bj = 0; bj < 2; bj++) {
                uint32_t ad = bofs + T_BHI + ((bRow + bj*16)*40 + ks*16 + bK8)*2;
                ldmat4(bh[bj], ad);
                ldmat4(bl[bj], ad + (T_BLO - T_BHI));
            }
            #pragma unroll
            for (int mi = 0; mi < 4; mi++)
                #pragma unroll
                for (int nj = 0; nj < 4; nj++) {
                    int bj = nj >> 1, pr = (nj & 1)*2;
                    mma_bf16(acc[mi][nj], ah[mi], bh[bj][pr], bh[bj][pr+1]);
                    mma_bf16(acc[mi][nj], ah[mi], bl[bj][pr], bl[bj][pr+1]);
                    mma_bf16(acc[mi][nj], al[mi], bh[bj][pr], bh[bj][pr+1]);
                }
        }
    }

    int r0 = bm + wm*64 + (lane >> 2);
    int c0 = bn + wn*32 + (lane & 3)*2;
    if (Chi == nullptr) {
        #pragma unroll
        for (int mi = 0; mi < 4; mi++)
            #pragma unroll
            for (int nj = 0; nj < 4; nj++) {
                float* p = C + (size_t)(r0 + mi*16)*N + c0 + nj*8;
                *(float2*)p                 = make_float2(acc[mi][nj][0], acc[mi][nj][1]);
                *(float2*)(p + (size_t)8*N) = make_float2(acc[mi][nj][2], acc[mi][nj][3]);
            }
    } else {
        #pragma unroll
        for (int mi = 0; mi < 4; mi++)
            #pragma unroll
            for (int nj = 0; nj < 4; nj++) {
                int r = r0 + mi*16, c = c0 + nj*8;
                float v0 = acc[mi][nj][0], v1 = acc[mi][nj][1];
                float v2 = acc[mi][nj][2], v3 = acc[mi][nj][3];
                uint32_t h01 = pk2f(v0, v1), h23 = pk2f(v2, v3);
                uint32_t l01 = pk2f(v0 - bflo(h01), v1 - bfhi(h01));
                uint32_t l23 = pk2f(v2 - bflo(h23), v3 - bfhi(h23));
                *(uint32_t*)(Chi + (size_t)r*N + c)     = h01;
                *(uint32_t*)(Clo + (size_t)r*N + c)     = l01;
                *(uint32_t*)(Chi + (size_t)(r+8)*N + c) = h23;
                *(uint32_t*)(Clo + (size_t)(r+8)*N + c) = l23;
            }
    }
}

// fused QKV: grid (4, 64, 3); z=0 -> Q (bf16), z=1 -> K (bf16), z=2 -> V (fp32)
__global__ __launch_bounds__(256, 1) void qkv_gemm() {
    extern __shared__ char smc[];
    uint32_t sb = smem_u32(smc);
    int z = blockIdx.z;
    const __nv_bfloat16 *Bh, *Bl;
    float* Cf = nullptr; __nv_bfloat16 *Ch = nullptr, *Cl = nullptr;
    if      (z == 0) { Bh = g_wqhi; Bl = g_wqlo; Ch = g_qhi; Cl = g_qlo; }
    else if (z == 1) { Bh = g_wkhi; Bl = g_wklo; Ch = g_khi; Cl = g_klo; }
    else             { Bh = g_wvhi; Bl = g_wvlo; Cf = g_V; }
    gemm_core(smc, sb, g_xhi, g_xlo, Bh, Bl, Cf, Ch, Cl,
              Ez, Ez, blockIdx.y*128, blockIdx.x*128);
}

// generic batched fp32-out GEMM
__global__ __launch_bounds__(256, 1)
void mma_gemm(const __nv_bfloat16* __restrict__ Ahi, const __nv_bfloat16* __restrict__ Alo,
              const __nv_bfloat16* __restrict__ Bhi, const __nv_bfloat16* __restrict__ Blo,
              float* __restrict__ C, int N, int K,
              long long aStride, long long bStride, long long cStride) {
    extern __shared__ char smc[];
    uint32_t sb = smem_u32(smc);
    int z = blockIdx.z;
    gemm_core(smc, sb, Ahi + (long long)z*aStride, Alo + (long long)z*aStride,
              Bhi + (long long)z*bStride, Blo + (long long)z*bStride,
              C + (long long)z*cStride, nullptr, nullptr,
              N, K, blockIdx.y*128, blockIdx.x*128);
}

// ---------------- tensor-core attention (Q/K now bf16 hi/lo inputs) ----------------
#define A_QHI 0
#define A_QLO 18432
#define A_KHI 36864
#define A_KLO 55296
#define A_VHI 73728
#define A_VLO 91136
#define A_PHI 108544
#define A_PLO 143360
#define A_MQ  178176
#define A_MK  178688
#define A_RED 179200
#define AT_SMEM (179200 + 2048)

__global__ __launch_bounds__(512, 1) void attn_mma() {
    extern __shared__ char smc[];
    uint32_t sb = smem_u32(smc);
    float* mqf = (float*)(smc + A_MQ);
    float* mkf = (float*)(smc + A_MK);
    float* red = (float*)(smc + A_RED);

    int tid = threadIdx.x, lane = tid & 31, wid = tid >> 5;
    int qt = blockIdx.x, h = blockIdx.y, b = blockIdx.z;

    int wm = wid & 3, wn = wid >> 2;
    int wq = wid & 7, wd = wid >> 3;

    const __nv_bfloat16* Qh = g_qhi + ((size_t)(b*Lz + qt*128))*Ez + h*64;
    const __nv_bfloat16* Ql = g_qlo + ((size_t)(b*Lz + qt*128))*Ez + h*64;
    const __nv_bfloat16* Kh = g_khi + ((size_t)(b*Lz))*Ez + h*64;
    const __nv_bfloat16* Kl = g_klo + ((size_t)(b*Lz))*Ez + h*64;
    const __nv_bfloat16* Vth = g_vthi + ((size_t)(b*Ez + h*64))*Lz;
    const __nv_bfloat16* Vtl = g_vtlo + ((size_t)(b*Ez + h*64))*Lz;

    // load Q tiles (bf16 copy, rows 128 x 64, stride 144B)
    for (int i = tid; i < 1024; i += 512) {
        int r = i >> 3, c8 = (i & 7)*8;
        uint32_t off = r*144 + c8*2;
        *(uint4*)(smc + A_QHI + off) = *(const uint4*)(Qh + (size_t)r*Ez + c8);
        *(uint4*)(smc + A_QLO + off) = *(const uint4*)(Ql + (size_t)r*Ez + c8);
    }
    if (tid < 128) mqf[tid] = g_mf[b*Lz + qt*128 + tid];

    uint32_t qRow = wm*32 + (lane & 15);
    uint32_t qK8  = (lane >> 4)*8;
    uint32_t kRowB = wn*32 + (lane & 7) + ((lane >> 4) << 3);
    uint32_t kK8  = ((lane >> 3) & 1)*8;
    uint32_t pRow = wq*16 + (lane & 15);
    uint32_t pK8  = (lane >> 4)*8;
    uint32_t vRowB = wd*32 + (lane & 7) + ((lane >> 4) << 3);
    uint32_t vK8  = ((lane >> 3) & 1)*8;

    float U[4][4] = {};
    float partial = 0.f;

    for (int kt = 0; kt < 8; kt++) {
        __syncthreads();
        for (int i = tid; i < 1024; i += 512) {
            int r = i >> 3, c8 = (i & 7)*8;
            uint32_t off = r*144 + c8*2;
            *(uint4*)(smc + A_KHI + off) = *(const uint4*)(Kh + (size_t)(kt*128 + r)*Ez + c8);
            *(uint4*)(smc + A_KLO + off) = *(const uint4*)(Kl + (size_t)(kt*128 + r)*Ez + c8);
        }
        for (int i = tid; i < 1024; i += 512) {
            int r = i >> 4, c8 = (i & 15)*8;
            uint32_t off = r*272 + c8*2;
            *(uint4*)(smc + A_VHI + off) = *(const uint4*)(Vth + (size_t)r*Lz + kt*128 + c8);
            *(uint4*)(smc + A_VLO + off) = *(const uint4*)(Vtl + (size_t)r*Lz + kt*128 + c8);
        }
        if (tid < 128) mkf[tid] = g_mf[b*Lz + kt*128 + tid];
        __syncthreads();

        // ---- S = Q K^T (3-product) ----
        float S[2][4][4] = {};
        #pragma unroll
        for (int ks = 0; ks < 4; ks++) {
            uint32_t ah[2][4], al[2][4], bh[2][4], bl[2][4];
            #pragma unroll
            for (int mi = 0; mi < 2; mi++) {
                uint32_t ad = sb + A_QHI + (qRow + mi*16)*144 + (ks*16 + qK8)*2;
                ldmat4(ah[mi], ad);
                ldmat4(al[mi], ad + (A_QLO - A_QHI));
            }
            #pragma unroll
            for (int nb = 0; nb < 2; nb++) {
                uint32_t ad = sb + A_KHI + (kRowB + nb*16)*144 + (ks*16 + kK8)*2;
                ldmat4(bh[nb], ad);
                ldmat4(bl[nb], ad + (A_KLO - A_KHI));
            }
            #pragma unroll
            for (int mi = 0; mi < 2; mi++)
                #pragma unroll
                for (int nj = 0; nj < 4; nj++) {
                    int nb = nj >> 1, pr = (nj & 1)*2;
                    mma_bf16(S[mi][nj], ah[mi], bh[nb][pr], bh[nb][pr+1]);
                    mma_bf16(S[mi][nj], ah[mi], bl[nb][pr], bl[nb][pr+1]);
                    mma_bf16(S[mi][nj], al[mi], bh[nb][pr], bh[nb][pr+1]);
                }
        }

        // ---- P = ex2(tanh(S/8)*L2E)*mk -> smem (bf16 hi/lo) ----
        {
            int r0 = wm*32 + (lane >> 2);
            int c0b = wn*32 + (lane & 3)*2;
            #pragma unroll
            for (int mi = 0; mi < 2; mi++) {
                int row0 = r0 + mi*16, row1 = row0 + 8;
                float mq0 = mqf[row0], mq1 = mqf[row1];
                #pragma unroll
                for (int nj = 0; nj < 4; nj++) {
                    int c0 = c0b + nj*8;
                    float mk0 = mkf[c0], mk1 = mkf[c0+1];
                    float p0 = ex2f(tanh_fast(S[mi][nj][0]*0.125f)*L2E)*mk0;
                    float p1 = ex2f(tanh_fast(S[mi][nj][1]*0.125f)*L2E)*mk1;
                    float p2 = ex2f(tanh_fast(S[mi][nj][2]*0.125f)*L2E)*mk0;
                    float p3 = ex2f(tanh_fast(S[mi][nj][3]*0.125f)*L2E)*mk1;
                    partial += mq0*(p0+p1) + mq1*(p2+p3);
                    uint32_t h01 = pk2f(p0, p1), h23 = pk2f(p2, p3);
                    uint32_t l01 = pk2f(p0 - bflo(h01), p1 - bfhi(h01));
                    uint32_t l23 = pk2f(p2 - bflo(h23), p3 - bfhi(h23));
                    uint32_t o0 = row0*272 + c0*2, o1 = row1*272 + c0*2;
                    *(uint32_t*)(smc + A_PHI + o0) = h01;
                    *(uint32_t*)(smc + A_PHI + o1) = h23;
                    *(uint32_t*)(smc + A_PLO + o0) = l01;
                    *(uint32_t*)(smc + A_PLO + o1) = l23;
                }
            }
        }
        __syncthreads();

        // ---- U += P @ Vt^T ----
        #pragma unroll
        for (int ch = 0; ch < 8; ch++) {
            uint32_t ph[4], pl[4];
            uint32_t pa = sb + A_PHI + pRow*272 + (ch*16 + pK8)*2;
            ldmat4(ph, pa);
            ldmat4(pl, pa + (A_PLO - A_PHI));
            #pragma unroll
            for (int g = 0; g < 2; g++) {
                uint32_t vh[4], vl[4];
                uint32_t va = sb + A_VHI + (vRowB + g*16)*272 + (ch*16 + vK8)*2;
                ldmat4(vh, va);
                ldmat4(vl, va + (A_VLO - A_VHI));
                mma_bf16(U[g*2],   ph, vh[0], vh[1]);
                mma_bf16(U[g*2],   ph, vl[0], vl[1]);
                mma_bf16(U[g*2],   pl, vh[0], vh[1]);
                mma_bf16(U[g*2+1], ph, vh[2], vh[3]);
                mma_bf16(U[g*2+1], ph, vl[2], vl[3]);
                mma_bf16(U[g*2+1], pl, vh[2], vh[3]);
            }
        }
    }

    // ---- write U ----
    {
        int r = wq*16 + (lane >> 2);
        int cb = wd*32 + (lane & 3)*2;
        float* Ug = g_U + ((size_t)(b*Lz + qt*128))*Ez + h*64;
        #pragma unroll
        for (int dj = 0; dj < 4; dj++) {
            int c = cb + dj*8;
            *(float2*)(Ug + (size_t)r*Ez + c)     = make_float2(U[dj][0], U[dj][1]);
            *(float2*)(Ug + (size_t)(r+8)*Ez + c) = make_float2(U[dj][2], U[dj][3]);
        }
    }

    red[tid] = partial; __syncthreads();
    for (int s = 256; s > 0; s >>= 1) { if (tid < s) red[tid] += red[tid+s]; __syncthreads(); }
    if (tid == 0) g_Spart[(b*Hz + h)*8 + qt] = red[0];
}

// ---------------- host launcher ----------------
static void* symaddr(const void* s) { void* p = nullptr; cudaGetSymbolAddress(&p, s); return p; }

extern "C" void kernel_launch(void* const* d_in, const int* in_sizes, int n_in,
                              void* d_out, int out_size) {
    const float* x    = (const float*)d_in[0];
    const void*  mask = d_in[1];
    const float* Wq   = (const float*)d_in[2];
    const float* Wk   = (const float*)d_in[3];
    const float* Wv   = (const float*)d_in[4];
    const float* Wo   = (const float*)d_in[5];
    const float* G    = (const float*)d_in[6];
    float* out = (float*)d_out;

    float* GAV  = (float*)symaddr(g_GAV);
    __nv_bfloat16* xhi  = (__nv_bfloat16*)symaddr(g_xhi);
    __nv_bfloat16* xlo  = (__nv_bfloat16*)symaddr(g_xlo);
    __nv_bfloat16* acthi= (__nv_bfloat16*)symaddr(g_acthi);
    __nv_bfloat16* actlo= (__nv_bfloat16*)symaddr(g_actlo);
    __nv_bfloat16* vthi = (__nv_bfloat16*)symaddr(g_vthi);
    __nv_bfloat16* vtlo = (__nv_bfloat16*)symaddr(g_vtlo);
    __nv_bfloat16* aohi = (__nv_bfloat16*)symaddr(g_aohi);
    __nv_bfloat16* aolo = (__nv_bfloat16*)symaddr(g_aolo);
    __nv_bfloat16* wohi = (__nv_bfloat16*)symaddr(g_wohi);
    __nv_bfloat16* wolo = (__nv_bfloat16*)symaddr(g_wolo);

    cudaFuncSetAttribute((const void*)attn_mma,
                         cudaFuncAttributeMaxDynamicSharedMemorySize, AT_SMEM);
    cudaFuncSetAttribute((const void*)qkv_gemm,
                         cudaFuncAttributeMaxDynamicSharedMemorySize, PIPE_SMEM);
    cudaFuncSetAttribute((const void*)mma_gemm,
                         cudaFuncAttributeMaxDynamicSharedMemorySize, PIPE_SMEM);

    detect_mask<<<1,1>>>((const unsigned char*)mask);
    convert_mask<<<32,256>>>(mask);
    softmax_g<<<1024,256>>>(G);
    gsum2<<<128,256>>>();
    reduce_parts<<<8,256>>>(1);

    split_f32<<<(Bz*Lz*Ez+255)/256,256>>>(x, xhi, xlo, Bz*Lz*Ez);
    split_w<<<dim3((Ez*Ez+255)/256,4),256>>>(Wq, Wk, Wv, Wo);

    qkv_gemm<<<dim3(4,64,3),256,PIPE_SMEM>>>();

    tsplit_v<<<dim3(16,32,8),256>>>();

    attn_mma<<<dim3(8,Hz,Bz),512,AT_SMEM>>>();
    reduce_parts<<<8,256>>>(0);
    rowscales<<<32,256>>>();

    mma_gemm<<<dim3(4,8,Bz),256,PIPE_SMEM>>>(acthi, actlo, vthi, vtlo, GAV,
                                             Ez, Lz, 0, (long long)Ez*Lz, (long long)Lz*Ez);
    prep_out<<<(Bz*Lz*Ez+255)/256,256>>>();
    mma_gemm<<<dim3(4,64,1),256,PIPE_SMEM>>>(aohi, aolo, wohi, wolo, out,
                                             Ez, Ez, 0, 0, 0);
}

// round 9
// speedup vs baseline: 2.5476x; 1.1000x over previous
#include <cuda_runtime.h>
#include <cuda_bf16.h>
#include <float.h>
#include <stdint.h>

#define Bz   8
#define Lz   1024
#define Ez   512
#define Hz   8
#define Dz   64

// ---------------- fast-math helpers ----------------
__device__ __forceinline__ float tanh_fast(float x) {
    float y; asm("tanh.approx.f32 %0, %1;" : "=f"(y) : "f"(x)); return y;
}
__device__ __forceinline__ float ex2f(float x) {
    float y; asm("ex2.approx.f32 %0, %1;" : "=f"(y) : "f"(x)); return y;
}
#define L2E 1.4426950408889634f

__device__ __forceinline__ uint32_t smem_u32(const void* p) {
    uint32_t a;
    asm("{ .reg .u64 t; cvta.to.shared.u64 t, %1; cvt.u32.u64 %0, t; }" : "=r"(a) : "l"(p));
    return a;
}
__device__ __forceinline__ uint32_t pk2f(float lo, float hi) {
    uint32_t r; asm("cvt.rn.bf16x2.f32 %0, %1, %2;" : "=r"(r) : "f"(hi), "f"(lo)); return r;
}
__device__ __forceinline__ float bflo(uint32_t v) { return __uint_as_float(v << 16); }
__device__ __forceinline__ float bfhi(uint32_t v) { return __uint_as_float(v & 0xFFFF0000u); }

// ---------------- mma.sync / cp.async helpers ----------------
__device__ __forceinline__ void ldmat4(uint32_t* r, uint32_t a) {
    asm volatile("ldmatrix.sync.aligned.m8n8.x4.shared.b16 {%0,%1,%2,%3}, [%4];"
                 : "=r"(r[0]), "=r"(r[1]), "=r"(r[2]), "=r"(r[3]) : "r"(a));
}
__device__ __forceinline__ void mma_bf16(float* c, const uint32_t* a, uint32_t b0, uint32_t b1) {
    asm volatile("mma.sync.aligned.m16n8k16.row.col.f32.bf16.bf16.f32 "
                 "{%0,%1,%2,%3}, {%4,%5,%6,%7}, {%8,%9}, {%0,%1,%2,%3};"
                 : "+f"(c[0]), "+f"(c[1]), "+f"(c[2]), "+f"(c[3])
                 : "r"(a[0]), "r"(a[1]), "r"(a[2]), "r"(a[3]), "r"(b0), "r"(b1));
}
__device__ __forceinline__ void cp16(uint32_t s, const void* g) {
    asm volatile("cp.async.cg.shared.global [%0], [%1], 16;" :: "r"(s), "l"(g));
}
__device__ __forceinline__ void cp_commit() { asm volatile("cp.async.commit_group;"); }
template<int N> __device__ __forceinline__ void cp_wait() {
    asm volatile("cp.async.wait_group %0;" :: "n"(N));
}

// ---------------- device scratch ----------------
__device__ float g_mf[Bz*Lz];
__device__ int   g_maskKind;
__device__ float g_V [Bz*Lz*Ez];
__device__ float g_U [Bz*Lz*Ez];
__device__ float g_GAV[Bz*Lz*Ez];
__device__ float g_Spart[Bz*Hz*8];
__device__ float g_Gpart[Bz*Lz];
__device__ float g_S[Bz];
__device__ float g_gs[Bz];
__device__ float g_rs0[Bz*Lz];
__device__ float g_rs1[Bz*Lz];

__device__ __nv_bfloat16 g_xhi[Bz*Lz*Ez],  g_xlo[Bz*Lz*Ez];
__device__ __nv_bfloat16 g_qhi[Bz*Lz*Ez],  g_qlo[Bz*Lz*Ez];
__device__ __nv_bfloat16 g_khi[Bz*Lz*Ez],  g_klo[Bz*Lz*Ez];
__device__ __nv_bfloat16 g_wqhi[Ez*Ez], g_wqlo[Ez*Ez];
__device__ __nv_bfloat16 g_wkhi[Ez*Ez], g_wklo[Ez*Ez];
__device__ __nv_bfloat16 g_wvhi[Ez*Ez], g_wvlo[Ez*Ez];
__device__ __nv_bfloat16 g_wohi[Ez*Ez], g_wolo[Ez*Ez];
__device__ __nv_bfloat16 g_acthi[Lz*Lz], g_actlo[Lz*Lz];
__device__ __nv_bfloat16 g_vthi[Bz*Ez*Lz], g_vtlo[Bz*Ez*Lz];
__device__ __nv_bfloat16 g_aohi[Bz*Lz*Ez], g_aolo[Bz*Lz*Ez];

// ---------------- mask detect / convert ----------------
__global__ void detect_mask(const unsigned char* m) {
    bool isInt32 = true;
    for (int i = 0; i < 64; i++) {
        if (m[4*i] > 1) isInt32 = false;
        if (m[4*i+1] | m[4*i+2] | m[4*i+3]) isInt32 = false;
    }
    if (isInt32) { g_maskKind = 0; return; }
    const unsigned int* w = (const unsigned int*)m;
    bool isFloat = true;
    for (int i = 0; i < 64; i++) {
        unsigned v = w[i];
        if (v != 0u && v != 0x3F800000u) isFloat = false;
    }
    g_maskKind = isFloat ? 2 : 1;
}

__global__ void convert_mask(const void* m) {
    int i = blockIdx.x*256 + threadIdx.x;
    if (i >= Bz*Lz) return;
    int k = g_maskKind;
    float v;
    if (k == 0)      v = ((const int*)m)[i] ? 1.f : 0.f;
    else if (k == 1) v = ((const unsigned char*)m)[i] ? 1.f : 0.f;
    else             v = ((const float*)m)[i];
    g_mf[i] = v;
}

// ---------------- fp32 -> bf16 hi/lo splits ----------------
__global__ void split_f32(const float* __restrict__ src, __nv_bfloat16* __restrict__ hi,
                          __nv_bfloat16* __restrict__ lo, int n) {
    int i = blockIdx.x*256 + threadIdx.x;
    if (i >= n) return;
    float v = src[i];
    __nv_bfloat16 h = __float2bfloat16(v);
    hi[i] = h;
    lo[i] = __float2bfloat16(v - __bfloat162float(h));
}

__global__ void split_w(const float* __restrict__ wq, const float* __restrict__ wk,
                        const float* __restrict__ wv, const float* __restrict__ wo) {
    int which = blockIdx.y;
    int i = blockIdx.x*256 + threadIdx.x;
    if (i >= Ez*Ez) return;
    const float* s; __nv_bfloat16 *hp, *lp;
    if      (which == 0) { s = wq; hp = g_wqhi; lp = g_wqlo; }
    else if (which == 1) { s = wk; hp = g_wkhi; lp = g_wklo; }
    else if (which == 2) { s = wv; hp = g_wvhi; lp = g_wvlo; }
    else                 { s = wo; hp = g_wohi; lp = g_wolo; }
    float v = s[i];
    __nv_bfloat16 h = __float2bfloat16(v);
    hp[i] = h;
    lp[i] = __float2bfloat16(v - __bfloat162float(h));
}

// ---------------- softmax of G rows -> bf16 hi/lo + fused gsum partials ----------------
__global__ __launch_bounds__(256) void softmax_g(const float* __restrict__ G) {
    int q = blockIdx.x, t = threadIdx.x;
    const float* row = G + (size_t)q*Lz;
    __shared__ float red[256];
    __shared__ float part[8][8];
    float mx = -FLT_MAX;
    for (int k = t; k < Lz; k += 256) mx = fmaxf(mx, row[k]);
    red[t] = mx; __syncthreads();
    for (int s = 128; s > 0; s >>= 1) { if (t < s) red[t] = fmaxf(red[t], red[t+s]); __syncthreads(); }
    mx = red[0]; __syncthreads();
    float vals[4]; float sum = 0.f;
    for (int k = t, j = 0; k < Lz; k += 256, j++) { float e = __expf(row[k]-mx); vals[j] = e; sum += e; }
    red[t] = sum; __syncthreads();
    for (int s = 128; s > 0; s >>= 1) { if (t < s) red[t] += red[t+s]; __syncthreads(); }
    float inv = 1.f / red[0];
    float gs[8] = {};
    for (int k = t, j = 0; k < Lz; k += 256, j++) {
        float v = vals[j]*inv;
        __nv_bfloat16 h = __float2bfloat16(v);
        g_acthi[(size_t)q*Lz + k] = h;
        g_actlo[(size_t)q*Lz + k] = __float2bfloat16(v - __bfloat162float(h));
        #pragma unroll
        for (int b2 = 0; b2 < 8; b2++) gs[b2] += v * __ldg(g_mf + b2*Lz + k);
    }
    #pragma unroll
    for (int o = 16; o; o >>= 1)
        #pragma unroll
        for (int b2 = 0; b2 < 8; b2++) gs[b2] += __shfl_down_sync(0xffffffffu, gs[b2], o);
    if ((t & 31) == 0)
        #pragma unroll
        for (int b2 = 0; b2 < 8; b2++) part[t>>5][b2] = gs[b2];
    __syncthreads();
    if (t < 8) {
        float r = 0.f;
        #pragma unroll
        for (int w = 0; w < 8; w++) r += part[w][t];
        g_Gpart[t*Lz + q] = r * __ldg(g_mf + t*Lz + q);
    }
}

__global__ __launch_bounds__(256) void reduce_parts(int which) {
    int b = blockIdx.x, t = threadIdx.x;
    __shared__ float red[256];
    float s = 0.f;
    if (which == 0) { for (int i = t; i < Hz*8; i += 256) s += g_Spart[b*Hz*8 + i]; }
    else            { for (int i = t; i < Lz;   i += 256) s += g_Gpart[b*Lz + i]; }
    red[t] = s; __syncthreads();
    for (int st = 128; st > 0; st >>= 1) { if (t < st) red[t] += red[t+st]; __syncthreads(); }
    if (t == 0) { if (which == 0) g_S[b] = red[0]; else g_gs[b] = red[0]; }
}

__global__ void rowscales() {
    int i = blockIdx.x*256 + threadIdx.x;
    if (i >= Bz*Lz) return;
    int b = i >> 10;
    const float TINY = 1.175494351e-38f;
    float mf = g_mf[i];
    g_rs0[i] = 0.5f*mf / fmaxf(g_S[b],  TINY);
    g_rs1[i] = 0.5f*mf / fmaxf(g_gs[b], TINY);
}

// masked-V transpose + split
__global__ __launch_bounds__(256) void tsplit_v() {
    __shared__ float ts[32][33];
    int b = blockIdx.z;
    int e0 = blockIdx.x*32, l0 = blockIdx.y*32;
    int tx = threadIdx.x & 31, ty = threadIdx.x >> 5;
    #pragma unroll
    for (int r = 0; r < 4; r++) {
        int l = ty*4 + r;
        ts[l][tx] = g_V[(size_t)(b*Lz + l0 + l)*Ez + e0 + tx] * g_mf[b*Lz + l0 + l];
    }
    __syncthreads();
    #pragma unroll
    for (int r = 0; r < 4; r++) {
        int e = ty*4 + r;
        float v = ts[tx][e];
        __nv_bfloat16 h = __float2bfloat16(v);
        size_t o = ((size_t)b*Ez + e0 + e)*Lz + l0 + tx;
        g_vthi[o] = h;
        g_vtlo[o] = __float2bfloat16(v - __bfloat162float(h));
    }
}

// A_out = rs0*U + rs1*GAV  -> bf16 hi/lo
__global__ void prep_out() {
    int i = blockIdx.x*256 + threadIdx.x;
    if (i >= Bz*Lz*Ez) return;
    int row = i >> 9;
    float v = g_rs0[row]*g_U[i] + g_rs1[row]*g_GAV[i];
    __nv_bfloat16 h = __float2bfloat16(v);
    g_aohi[i] = h;
    g_aolo[i] = __float2bfloat16(v - __bfloat162float(h));
}

// ---------------- pipelined HMMA bf16-split GEMM core ----------------
#define T_ALO 10240
#define T_BHI 20480
#define T_BLO 30720
#define BUFSZ 40960
#define PIPE_SMEM (2*BUFSZ)

__device__ __forceinline__ void gemm_core(
    char* smc, uint32_t sb,
    const __nv_bfloat16* Ahi, const __nv_bfloat16* Alo,
    const __nv_bfloat16* Bhi, const __nv_bfloat16* Blo,
    float* C, __nv_bfloat16* Chi, __nv_bfloat16* Clo,
    int N, int K, int bm, int bn)
{
    int tid = threadIdx.x, lane = tid & 31, wid = tid >> 5;
    int wm = wid & 1, wn = wid >> 1;
    const char* pAh = (const char*)(Ahi + (size_t)bm*K);
    const char* pAl = (const char*)(Alo + (size_t)bm*K);
    const char* pBh = (const char*)(Bhi + (size_t)bn*K);
    const char* pBl = (const char*)(Blo + (size_t)bn*K);

    float acc[4][4][4] = {};

    uint32_t aRow = wm*64 + (lane & 15);
    uint32_t aK8  = (lane >> 4) * 8;
    uint32_t bRow = wn*32 + (lane & 7) + ((lane >> 4) << 3);
    uint32_t bK8  = ((lane >> 3) & 1) * 8;

    int nChunks = K >> 5;

    auto load_chunk = [&](int kc, int bsel) {
        uint32_t base = sb + bsel*BUFSZ;
        #pragma unroll
        for (int i = tid; i < 512; i += 256) {
            int r = i >> 2, c = i & 3;
            size_t go = (size_t)r*K*2 + (size_t)kc*64 + c*16;
            uint32_t so = r*80 + c*16;
            cp16(base + so,          pAh + go);
            cp16(base + T_ALO + so,  pAl + go);
            cp16(base + T_BHI + so,  pBh + go);
            cp16(base + T_BLO + so,  pBl + go);
        }
        cp_commit();
    };

    load_chunk(0, 0);

    for (int kc = 0; kc < nChunks; kc++) {
        __syncthreads();
        if (kc + 1 < nChunks) { load_chunk(kc+1, (kc+1)&1); cp_wait<1>(); }
        else                  { cp_wait<0>(); }
        __syncthreads();
        uint32_t bofs = sb + (kc&1)*BUFSZ;
        #pragma unroll
        for (int ks = 0; ks < 2; ks++) {
            uint32_t ah[4][4], al[4][4], bh[2][4], bl[2][4];
            #pragma unroll
            for (int mi = 0; mi < 4; mi++) {
                uint32_t ad = bofs + ((aRow + mi*16)*40 + ks*16 + aK8)*2;
                ldmat4(ah[mi], ad);
                ldmat4(al[mi], ad + T_ALO);
            }
            #pragma unroll
            for (int bj = 0; bj < 2; bj++) {
                uint32_t ad = bofs + T_BHI + ((bRow + bj*16)*40 + ks*16 + bK8)*2;
                ldmat4(bh[bj], ad);
                ldmat4(bl[bj], ad + (T_BLO - T_BHI));
            }
            #pragma unroll
            for (int mi = 0; mi < 4; mi++)
                #pragma unroll
                for (int nj = 0; nj < 4; nj++) {
                    int bj = nj >> 1, pr = (nj & 1)*2;
                    mma_bf16(acc[mi][nj], ah[mi], bh[bj][pr], bh[bj][pr+1]);
                    mma_bf16(acc[mi][nj], ah[mi], bl[bj][pr], bl[bj][pr+1]);
                    mma_bf16(acc[mi][nj], al[mi], bh[bj][pr], bh[bj][pr+1]);
                }
        }
    }

    int r0 = bm + wm*64 + (lane >> 2);
    int c0 = bn + wn*32 + (lane & 3)*2;
    if (Chi == nullptr) {
        #pragma unroll
        for (int mi = 0; mi < 4; mi++)
            #pragma unroll
            for (int nj = 0; nj < 4; nj++) {
                float* p = C + (size_t)(r0 + mi*16)*N + c0 + nj*8;
                *(float2*)p                 = make_float2(acc[mi][nj][0], acc[mi][nj][1]);
                *(float2*)(p + (size_t)8*N) = make_float2(acc[mi][nj][2], acc[mi][nj][3]);
            }
    } else {
        #pragma unroll
        for (int mi = 0; mi < 4; mi++)
            #pragma unroll
            for (int nj = 0; nj < 4; nj++) {
                int r = r0 + mi*16, c = c0 + nj*8;
                float v0 = acc[mi][nj][0], v1 = acc[mi][nj][1];
                float v2 = acc[mi][nj][2], v3 = acc[mi][nj][3];
                uint32_t h01 = pk2f(v0, v1), h23 = pk2f(v2, v3);
                uint32_t l01 = pk2f(v0 - bflo(h01), v1 - bfhi(h01));
                uint32_t l23 = pk2f(v2 - bflo(h23), v3 - bfhi(h23));
                *(uint32_t*)(Chi + (size_t)r*N + c)     = h01;
                *(uint32_t*)(Clo + (size_t)r*N + c)     = l01;
                *(uint32_t*)(Chi + (size_t)(r+8)*N + c) = h23;
                *(uint32_t*)(Clo + (size_t)(r+8)*N + c) = l23;
            }
    }
}

__global__ __launch_bounds__(256, 1) void qkv_gemm() {
    extern __shared__ char smc[];
    uint32_t sb = smem_u32(smc);
    int z = blockIdx.z;
    const __nv_bfloat16 *Bh, *Bl;
    float* Cf = nullptr; __nv_bfloat16 *Ch = nullptr, *Cl = nullptr;
    if      (z == 0) { Bh = g_wqhi; Bl = g_wqlo; Ch = g_qhi; Cl = g_qlo; }
    else if (z == 1) { Bh = g_wkhi; Bl = g_wklo; Ch = g_khi; Cl = g_klo; }
    else             { Bh = g_wvhi; Bl = g_wvlo; Cf = g_V; }
    gemm_core(smc, sb, g_xhi, g_xlo, Bh, Bl, Cf, Ch, Cl,
              Ez, Ez, blockIdx.y*128, blockIdx.x*128);
}

__global__ __launch_bounds__(256, 1)
void mma_gemm(const __nv_bfloat16* __restrict__ Ahi, const __nv_bfloat16* __restrict__ Alo,
              const __nv_bfloat16* __restrict__ Bhi, const __nv_bfloat16* __restrict__ Blo,
              float* __restrict__ C, int N, int K,
              long long aStride, long long bStride, long long cStride) {
    extern __shared__ char smc[];
    uint32_t sb = smem_u32(smc);
    int z = blockIdx.z;
    gemm_core(smc, sb, Ahi + (long long)z*aStride, Alo + (long long)z*aStride,
              Bhi + (long long)z*bStride, Blo + (long long)z*bStride,
              C + (long long)z*cStride, nullptr, nullptr,
              N, K, blockIdx.y*128, blockIdx.x*128);
}

// ---------------- tensor-core attention: cp.async pipelined ----------------
// smem layout (bytes):
//  Q hi/lo: 0 / 18432          (128 x 64 bf16, stride 144)
//  K buf0: 36864 (hi +0, lo +18432); K buf1: 73728
//  V hi/lo: 110592 / 128000    (64 x 128 bf16, stride 272)
//  P hi/lo: 145408 / 180224    (128 x 128 bf16, stride 272)
//  mq: 215040; mk(double): 215552 (+512); red: 216576
#define A_QHI 0
#define A_QLO 18432
#define A_K0  36864
#define A_KLOD 18432
#define A_KBUF 36864
#define A_VHI 110592
#define A_VLO 128000
#define A_PHI 145408
#define A_PLO 180224
#define A_MQ  215040
#define A_MK  215552
#define A_RED 216576
#define AT_SMEM (216576 + 2048)

__global__ __launch_bounds__(512, 1) void attn_mma() {
    extern __shared__ char smc[];
    uint32_t sb = smem_u32(smc);
    float* mqf = (float*)(smc + A_MQ);
    float* red = (float*)(smc + A_RED);

    int tid = threadIdx.x, lane = tid & 31, wid = tid >> 5;
    int qt = blockIdx.x, h = blockIdx.y, b = blockIdx.z;

    int wm = wid & 3, wn = wid >> 2;
    int wq = wid & 7, wd = wid >> 3;

    const __nv_bfloat16* Qh = g_qhi + ((size_t)(b*Lz + qt*128))*Ez + h*64;
    const __nv_bfloat16* Ql = g_qlo + ((size_t)(b*Lz + qt*128))*Ez + h*64;
    const __nv_bfloat16* Kh = g_khi + ((size_t)(b*Lz))*Ez + h*64;
    const __nv_bfloat16* Kl = g_klo + ((size_t)(b*Lz))*Ez + h*64;
    const __nv_bfloat16* Vth = g_vthi + ((size_t)(b*Ez + h*64))*Lz;
    const __nv_bfloat16* Vtl = g_vtlo + ((size_t)(b*Ez + h*64))*Lz;

    // K tile loader (cp.async): 128 rows x 64 cols hi+lo, + mask slice
    auto issue_K = [&](int kt, int bsel) {
        uint32_t base = sb + A_K0 + bsel*A_KBUF;
        #pragma unroll
        for (int i = tid; i < 1024; i += 512) {
            int r = i >> 3, c8 = (i & 7)*8;
            uint32_t off = r*144 + c8*2;
            cp16(base + off,           Kh + (size_t)(kt*128 + r)*Ez + c8);
            cp16(base + A_KLOD + off,  Kl + (size_t)(kt*128 + r)*Ez + c8);
        }
        if (tid < 32) cp16(sb + A_MK + bsel*512 + tid*16, g_mf + b*Lz + kt*128 + tid*4);
        cp_commit();
    };
    // V tile loader
    auto issue_V = [&](int kt) {
        #pragma unroll
        for (int i = tid; i < 1024; i += 512) {
            int r = i >> 4, c8 = (i & 15)*8;
            uint32_t off = r*272 + c8*2;
            cp16(sb + A_VHI + off, Vth + (size_t)r*Lz + kt*128 + c8);
            cp16(sb + A_VLO + off, Vtl + (size_t)r*Lz + kt*128 + c8);
        }
        cp_commit();
    };

    // Q load (plain) + mq
    for (int i = tid; i < 1024; i += 512) {
        int r = i >> 3, c8 = (i & 7)*8;
        uint32_t off = r*144 + c8*2;
        *(uint4*)(smc + A_QHI + off) = *(const uint4*)(Qh + (size_t)r*Ez + c8);
        *(uint4*)(smc + A_QLO + off) = *(const uint4*)(Ql + (size_t)r*Ez + c8);
    }
    if (tid < 128) mqf[tid] = g_mf[b*Lz + qt*128 + tid];

    issue_K(0, 0);
    issue_V(0);

    uint32_t qRow = wm*32 + (lane & 15);
    uint32_t qK8  = (lane >> 4)*8;
    uint32_t kRowB = wn*32 + (lane & 7) + ((lane >> 4) << 3);
    uint32_t kK8  = ((lane >> 3) & 1)*8;
    uint32_t pRow = wq*16 + (lane & 15);
    uint32_t pK8  = (lane >> 4)*8;
    uint32_t vRowB = wd*32 + (lane & 7) + ((lane >> 4) << 3);
    uint32_t vK8  = ((lane >> 3) & 1)*8;

    float U[4][4] = {};
    float partial = 0.f;

    cp_wait<0>();
    __syncthreads();

    for (int kt = 0; kt < 8; kt++) {
        if (kt + 1 < 8) issue_K(kt+1, (kt+1)&1);

        uint32_t kbase = sb + A_K0 + (kt&1)*A_KBUF;
        const float* mkf = (const float*)(smc + A_MK + (kt&1)*512);

        // ---- S = Q K^T (3-product) ----
        float S[2][4][4] = {};
        #pragma unroll
        for (int ks = 0; ks < 4; ks++) {
            uint32_t ah[2][4], al[2][4], bh[2][4], bl[2][4];
            #pragma unroll
            for (int mi = 0; mi < 2; mi++) {
                uint32_t ad = sb + A_QHI + (qRow + mi*16)*144 + (ks*16 + qK8)*2;
                ldmat4(ah[mi], ad);
                ldmat4(al[mi], ad + (A_QLO - A_QHI));
            }
            #pragma unroll
            for (int nb = 0; nb < 2; nb++) {
                uint32_t ad = kbase + (kRowB + nb*16)*144 + (ks*16 + kK8)*2;
                ldmat4(bh[nb], ad);
                ldmat4(bl[nb], ad + A_KLOD);
            }
            #pragma unroll
            for (int mi = 0; mi < 2; mi++)
                #pragma unroll
                for (int nj = 0; nj < 4; nj++) {
                    int nb = nj >> 1, pr = (nj & 1)*2;
                    mma_bf16(S[mi][nj], ah[mi], bh[nb][pr], bh[nb][pr+1]);
                    mma_bf16(S[mi][nj], ah[mi], bl[nb][pr], bl[nb][pr+1]);
                    mma_bf16(S[mi][nj], al[mi], bh[nb][pr], bh[nb][pr+1]);
                }
        }

        // ---- P = ex2(tanh(S/8)*L2E)*mk -> smem (bf16 hi/lo) ----
        {
            int r0 = wm*32 + (lane >> 2);
            int c0b = wn*32 + (lane & 3)*2;
            #pragma unroll
            for (int mi = 0; mi < 2; mi++) {
                int row0 = r0 + mi*16, row1 = row0 + 8;
                float mq0 = mqf[row0], mq1 = mqf[row1];
                #pragma unroll
                for (int nj = 0; nj < 4; nj++) {
                    int c0 = c0b + nj*8;
                    float mk0 = mkf[c0], mk1 = mkf[c0+1];
                    float p0 = ex2f(tanh_fast(S[mi][nj][0]*0.125f)*L2E)*mk0;
                    float p1 = ex2f(tanh_fast(S[mi][nj][1]*0.125f)*L2E)*mk1;
                    float p2 = ex2f(tanh_fast(S[mi][nj][2]*0.125f)*L2E)*mk0;
                    float p3 = ex2f(tanh_fast(S[mi][nj][3]*0.125f)*L2E)*mk1;
                    partial += mq0*(p0+p1) + mq1*(p2+p3);
                    uint32_t h01 = pk2f(p0, p1), h23 = pk2f(p2, p3);
                    uint32_t l01 = pk2f(p0 - bflo(h01), p1 - bfhi(h01));
                    uint32_t l23 = pk2f(p2 - bflo(h23), p3 - bfhi(h23));
                    uint32_t o0 = row0*272 + c0*2, o1 = row1*272 + c0*2;
                    *(uint32_t*)(smc + A_PHI + o0) = h01;
                    *(uint32_t*)(smc + A_PHI + o1) = h23;
                    *(uint32_t*)(smc + A_PLO + o0) = l01;
                    *(uint32_t*)(smc + A_PLO + o1) = l23;
                }
            }
        }
        __syncthreads();              // P visible to all
        if (kt < 7) cp_wait<1>();     // V[kt] done (committed before K[kt+1])
        else        cp_wait<0>();

        // ---- U += P @ Vt^T ----
        #pragma unroll
        for (int ch = 0; ch < 8; ch++) {
            uint32_t ph[4], pl[4];
            uint32_t pa = sb + A_PHI + pRow*272 + (ch*16 + pK8)*2;
            ldmat4(ph, pa);
            ldmat4(pl, pa + (A_PLO - A_PHI));
            #pragma unroll
            for (int g = 0; g < 2; g++) {
                uint32_t vh[4], vl[4];
                uint32_t va = sb + A_VHI + (vRowB + g*16)*272 + (ch*16 + vK8)*2;
                ldmat4(vh, va);
                ldmat4(vl, va + (A_VLO - A_VHI));
                mma_bf16(U[g*2],   ph, vh[0], vh[1]);
                mma_bf16(U[g*2],   ph, vl[0], vl[1]);
                mma_bf16(U[g*2],   pl, vh[0], vh[1]);
                mma_bf16(U[g*2+1], ph, vh[2], vh[3]);
                mma_bf16(U[g*2+1], ph, vl[2], vl[3]);
                mma_bf16(U[g*2+1], pl, vh[2], vh[3]);
            }
        }
        __syncthreads();              // all reads of V done before overwrite
        if (kt + 1 < 8) {
            issue_V(kt+1);
            cp_wait<1>();             // K[kt+1] done (its group precedes V[kt+1])
            __syncthreads();
        }
    }

    // ---- write U ----
    {
        int r = wq*16 + (lane >> 2);
        int cb = wd*32 + (lane & 3)*2;
        float* Ug = g_U + ((size_t)(b*Lz + qt*128))*Ez + h*64;
        #pragma unroll
        for (int dj = 0; dj < 4; dj++) {
            int c = cb + dj*8;
            *(float2*)(Ug + (size_t)r*Ez + c)     = make_float2(U[dj][0], U[dj][1]);
            *(float2*)(Ug + (size_t)(r+8)*Ez + c) = make_float2(U[dj][2], U[dj][3]);
        }
    }

    red[tid] = partial; __syncthreads();
    for (int s = 256; s > 0; s >>= 1) { if (tid < s) red[tid] += red[tid+s]; __syncthreads(); }
    if (tid == 0) g_Spart[(b*Hz + h)*8 + qt] = red[0];
}

// ---------------- host launcher ----------------
static void* symaddr(const void* s) { void* p = nullptr; cudaGetSymbolAddress(&p, s); return p; }

extern "C" void kernel_launch(void* const* d_in, const int* in_sizes, int n_in,
                              void* d_out, int out_size) {
    const float* x    = (const float*)d_in[0];
    const void*  mask = d_in[1];
    const float* Wq   = (const float*)d_in[2];
    const float* Wk   = (const float*)d_in[3];
    const float* Wv   = (const float*)d_in[4];
    const float* Wo   = (const float*)d_in[5];
    const float* G    = (const float*)d_in[6];
    float* out = (float*)d_out;

    float* GAV  = (float*)symaddr(g_GAV);
    __nv_bfloat16* xhi  = (__nv_bfloat16*)symaddr(g_xhi);
    __nv_bfloat16* xlo  = (__nv_bfloat16*)symaddr(g_xlo);
    __nv_bfloat16* acthi= (__nv_bfloat16*)symaddr(g_acthi);
    __nv_bfloat16* actlo= (__nv_bfloat16*)symaddr(g_actlo);
    __nv_bfloat16* vthi = (__nv_bfloat16*)symaddr(g_vthi);
    __nv_bfloat16* vtlo = (__nv_bfloat16*)symaddr(g_vtlo);
    __nv_bfloat16* aohi = (__nv_bfloat16*)symaddr(g_aohi);
    __nv_bfloat16* aolo = (__nv_bfloat16*)symaddr(g_aolo);
    __nv_bfloat16* wohi = (__nv_bfloat16*)symaddr(g_wohi);
    __nv_bfloat16* wolo = (__nv_bfloat16*)symaddr(g_wolo);

    cudaFuncSetAttribute((const void*)attn_mma,
                         cudaFuncAttributeMaxDynamicSharedMemorySize, AT_SMEM);
    cudaFuncSetAttribute((const void*)qkv_gemm,
                         cudaFuncAttributeMaxDynamicSharedMemorySize, PIPE_SMEM);
    cudaFuncSetAttribute((const void*)mma_gemm,
                         cudaFuncAttributeMaxDynamicSharedMemorySize, PIPE_SMEM);

    detect_mask<<<1,1>>>((const unsigned char*)mask);
    convert_mask<<<32,256>>>(mask);
    softmax_g<<<1024,256>>>(G);
    reduce_parts<<<8,256>>>(1);

    split_f32<<<(Bz*Lz*Ez+255)/256,256>>>(x, xhi, xlo, Bz*Lz*Ez);
    split_w<<<dim3((Ez*Ez+255)/256,4),256>>>(Wq, Wk, Wv, Wo);

    qkv_gemm<<<dim3(4,64,3),256,PIPE_SMEM>>>();

    tsplit_v<<<dim3(16,32,8),256>>>();

    attn_mma<<<dim3(8,Hz,Bz),512,AT_SMEM>>>();
    reduce_parts<<<8,256>>>(0);
    rowscales<<<32,256>>>();

    mma_gemm<<<dim3(4,8,Bz),256,PIPE_SMEM>>>(acthi, actlo, vthi, vtlo, GAV,
                                             Ez, Lz, 0, (long long)Ez*Lz, (long long)Lz*Ez);
    prep_out<<<(Bz*Lz*Ez+255)/256,256>>>();
    mma_gemm<<<dim3(4,64,1),256,PIPE_SMEM>>>(aohi, aolo, wohi, wolo, out,
                                             Ez, Ez, 0, 0, 0);
}

// round 10
// speedup vs baseline: 2.5766x; 1.0114x over previous
#include <cuda_runtime.h>
#include <cuda_bf16.h>
#include <float.h>
#include <stdint.h>

#define Bz   8
#define Lz   1024
#define Ez   512
#define Hz   8
#define Dz   64

// ---------------- fast-math helpers ----------------
__device__ __forceinline__ float tanh_fast(float x) {
    float y; asm("tanh.approx.f32 %0, %1;" : "=f"(y) : "f"(x)); return y;
}
__device__ __forceinline__ float ex2f(float x) {
    float y; asm("ex2.approx.f32 %0, %1;" : "=f"(y) : "f"(x)); return y;
}
#define L2E 1.4426950408889634f

__device__ __forceinline__ uint32_t smem_u32(const void* p) {
    uint32_t a;
    asm("{ .reg .u64 t; cvta.to.shared.u64 t, %1; cvt.u32.u64 %0, t; }" : "=r"(a) : "l"(p));
    return a;
}
__device__ __forceinline__ uint32_t pk2f(float lo, float hi) {
    uint32_t r; asm("cvt.rn.bf16x2.f32 %0, %1, %2;" : "=r"(r) : "f"(hi), "f"(lo)); return r;
}
__device__ __forceinline__ float bflo(uint32_t v) { return __uint_as_float(v << 16); }
__device__ __forceinline__ float bfhi(uint32_t v) { return __uint_as_float(v & 0xFFFF0000u); }

// ---------------- mma.sync / cp.async helpers ----------------
__device__ __forceinline__ void ldmat4(uint32_t* r, uint32_t a) {
    asm volatile("ldmatrix.sync.aligned.m8n8.x4.shared.b16 {%0,%1,%2,%3}, [%4];"
                 : "=r"(r[0]), "=r"(r[1]), "=r"(r[2]), "=r"(r[3]) : "r"(a));
}
__device__ __forceinline__ void mma_bf16(float* c, const uint32_t* a, uint32_t b0, uint32_t b1) {
    asm volatile("mma.sync.aligned.m16n8k16.row.col.f32.bf16.bf16.f32 "
                 "{%0,%1,%2,%3}, {%4,%5,%6,%7}, {%8,%9}, {%0,%1,%2,%3};"
                 : "+f"(c[0]), "+f"(c[1]), "+f"(c[2]), "+f"(c[3])
                 : "r"(a[0]), "r"(a[1]), "r"(a[2]), "r"(a[3]), "r"(b0), "r"(b1));
}
__device__ __forceinline__ void cp16(uint32_t s, const void* g) {
    asm volatile("cp.async.cg.shared.global [%0], [%1], 16;" :: "r"(s), "l"(g));
}
__device__ __forceinline__ void cp_commit() { asm volatile("cp.async.commit_group;"); }
template<int N> __device__ __forceinline__ void cp_wait() {
    asm volatile("cp.async.wait_group %0;" :: "n"(N));
}

// ---------------- device scratch ----------------
__device__ float g_mf[Bz*Lz];
__device__ float g_U [Bz*Lz*Ez];
__device__ float g_Spart[Bz*Hz*8];
__device__ float g_Gpart[Bz*Lz];
__device__ float g_gs[Bz];
__device__ float g_rs0[Bz*Lz];
__device__ float g_rs1[Bz*Lz];

__device__ __nv_bfloat16 g_xhi[Bz*Lz*Ez],  g_xlo[Bz*Lz*Ez];
__device__ __nv_bfloat16 g_qhi[Bz*Lz*Ez],  g_qlo[Bz*Lz*Ez];
__device__ __nv_bfloat16 g_khi[Bz*Lz*Ez],  g_klo[Bz*Lz*Ez];
__device__ __nv_bfloat16 g_wqhi[Ez*Ez], g_wqlo[Ez*Ez];
__device__ __nv_bfloat16 g_wkhi[Ez*Ez], g_wklo[Ez*Ez];
__device__ __nv_bfloat16 g_wvhi[Ez*Ez], g_wvlo[Ez*Ez];
__device__ __nv_bfloat16 g_wohi[Ez*Ez], g_wolo[Ez*Ez];
__device__ __nv_bfloat16 g_acthi[Lz*Lz], g_actlo[Lz*Lz];
__device__ __nv_bfloat16 g_vthi[Bz*Ez*Lz], g_vtlo[Bz*Ez*Lz];
__device__ __nv_bfloat16 g_aohi[Bz*Lz*Ez], g_aolo[Bz*Lz*Ez];

// ---------------- mask convert (detection fused, per-block) ----------------
__global__ void convert_mask(const void* mv) {
    __shared__ int skind;
    const unsigned char* m = (const unsigned char*)mv;
    if (threadIdx.x == 0) {
        bool isInt32 = true;
        for (int i = 0; i < 64; i++) {
            if (m[4*i] > 1) isInt32 = false;
            if (m[4*i+1] | m[4*i+2] | m[4*i+3]) isInt32 = false;
        }
        int kind;
        if (isInt32) kind = 0;
        else {
            const unsigned int* w = (const unsigned int*)m;
            bool isFloat = true;
            for (int i = 0; i < 64; i++) {
                unsigned v = w[i];
                if (v != 0u && v != 0x3F800000u) isFloat = false;
            }
            kind = isFloat ? 2 : 1;
        }
        skind = kind;
    }
    __syncthreads();
    int i = blockIdx.x*256 + threadIdx.x;
    if (i >= Bz*Lz) return;
    int k = skind;
    float v;
    if (k == 0)      v = ((const int*)mv)[i] ? 1.f : 0.f;
    else if (k == 1) v = m[i] ? 1.f : 0.f;
    else             v = ((const float*)mv)[i];
    g_mf[i] = v;
}

// ---------------- fused hi/lo split of x + 4 weights ----------------
#define NXS (Bz*Lz*Ez)
#define NWS (Ez*Ez)
__global__ void split_all(const float* __restrict__ x,
                          const float* __restrict__ wq, const float* __restrict__ wk,
                          const float* __restrict__ wv, const float* __restrict__ wo) {
    int i = blockIdx.x*256 + threadIdx.x;
    const float* s; __nv_bfloat16 *hp, *lp; int idx;
    if (i < NXS) { s = x; hp = g_xhi; lp = g_xlo; idx = i; }
    else {
        int j = i - NXS;
        int w = j >> 18;          // / NWS (262144)
        idx = j & (NWS-1);
        if      (w == 0) { s = wq; hp = g_wqhi; lp = g_wqlo; }
        else if (w == 1) { s = wk; hp = g_wkhi; lp = g_wklo; }
        else if (w == 2) { s = wv; hp = g_wvhi; lp = g_wvlo; }
        else             { s = wo; hp = g_wohi; lp = g_wolo; }
    }
    float v = s[idx];
    __nv_bfloat16 h = __float2bfloat16(v);
    hp[idx] = h;
    lp[idx] = __float2bfloat16(v - __bfloat162float(h));
}

// ---------------- softmax of G rows -> bf16 hi/lo + fused gsum partials ----------------
__global__ __launch_bounds__(256) void softmax_g(const float* __restrict__ G) {
    int q = blockIdx.x, t = threadIdx.x;
    const float* row = G + (size_t)q*Lz;
    __shared__ float red[256];
    __shared__ float part[8][8];
    float mx = -FLT_MAX;
    for (int k = t; k < Lz; k += 256) mx = fmaxf(mx, row[k]);
    red[t] = mx; __syncthreads();
    for (int s = 128; s > 0; s >>= 1) { if (t < s) red[t] = fmaxf(red[t], red[t+s]); __syncthreads(); }
    mx = red[0]; __syncthreads();
    float vals[4]; float sum = 0.f;
    for (int k = t, j = 0; k < Lz; k += 256, j++) { float e = __expf(row[k]-mx); vals[j] = e; sum += e; }
    red[t] = sum; __syncthreads();
    for (int s = 128; s > 0; s >>= 1) { if (t < s) red[t] += red[t+s]; __syncthreads(); }
    float inv = 1.f / red[0];
    float gs[8] = {};
    for (int k = t, j = 0; k < Lz; k += 256, j++) {
        float v = vals[j]*inv;
        __nv_bfloat16 h = __float2bfloat16(v);
        g_acthi[(size_t)q*Lz + k] = h;
        g_actlo[(size_t)q*Lz + k] = __float2bfloat16(v - __bfloat162float(h));
        #pragma unroll
        for (int b2 = 0; b2 < 8; b2++) gs[b2] += v * __ldg(g_mf + b2*Lz + k);
    }
    #pragma unroll
    for (int o = 16; o; o >>= 1)
        #pragma unroll
        for (int b2 = 0; b2 < 8; b2++) gs[b2] += __shfl_down_sync(0xffffffffu, gs[b2], o);
    if ((t & 31) == 0)
        #pragma unroll
        for (int b2 = 0; b2 < 8; b2++) part[t>>5][b2] = gs[b2];
    __syncthreads();
    if (t < 8) {
        float r = 0.f;
        #pragma unroll
        for (int w = 0; w < 8; w++) r += part[w][t];
        g_Gpart[t*Lz + q] = r * __ldg(g_mf + t*Lz + q);
    }
}

// reduce Gpart -> g_gs
__global__ __launch_bounds__(256) void reduce_g() {
    int b = blockIdx.x, t = threadIdx.x;
    __shared__ float red[256];
    float s = 0.f;
    for (int i = t; i < Lz; i += 256) s += g_Gpart[b*Lz + i];
    red[t] = s; __syncthreads();
    for (int st = 128; st > 0; st >>= 1) { if (t < st) red[t] += red[t+st]; __syncthreads(); }
    if (t == 0) g_gs[b] = red[0];
}

// reduce Spart -> S, then rowscales (fused)
__global__ __launch_bounds__(256) void reduce_s_rowscales() {
    int b = blockIdx.x, t = threadIdx.x;
    __shared__ float red[256];
    float s = 0.f;
    for (int i = t; i < Hz*8; i += 256) s += g_Spart[b*Hz*8 + i];
    red[t] = s; __syncthreads();
    for (int st = 128; st > 0; st >>= 1) { if (t < st) red[t] += red[t+st]; __syncthreads(); }
    __syncthreads();
    const float TINY = 1.175494351e-38f;
    float Sv  = fmaxf(red[0], TINY);
    float gsv = fmaxf(g_gs[b], TINY);
    float i0 = 0.5f / Sv, i1 = 0.5f / gsv;
    for (int i = t; i < Lz; i += 256) {
        float mf = g_mf[b*Lz + i];
        g_rs0[b*Lz + i] = mf * i0;
        g_rs1[b*Lz + i] = mf * i1;
    }
}

// ---------------- pipelined HMMA bf16-split GEMM mainloop ----------------
#define T_ALO 10240
#define T_BHI 20480
#define T_BLO 30720
#define BUFSZ 40960
#define PIPE_SMEM (2*BUFSZ)

__device__ __forceinline__ void gemm_main(
    char* smc, uint32_t sb,
    const __nv_bfloat16* Ahi, const __nv_bfloat16* Alo,
    const __nv_bfloat16* Bhi, const __nv_bfloat16* Blo,
    int K, int bm, int bn, float acc[4][4][4])
{
    int tid = threadIdx.x, lane = tid & 31, wid = tid >> 5;
    int wm = wid & 1, wn = wid >> 1;
    const char* pAh = (const char*)(Ahi + (size_t)bm*K);
    const char* pAl = (const char*)(Alo + (size_t)bm*K);
    const char* pBh = (const char*)(Bhi + (size_t)bn*K);
    const char* pBl = (const char*)(Blo + (size_t)bn*K);

    uint32_t aRow = wm*64 + (lane & 15);
    uint32_t aK8  = (lane >> 4) * 8;
    uint32_t bRow = wn*32 + (lane & 7) + ((lane >> 4) << 3);
    uint32_t bK8  = ((lane >> 3) & 1) * 8;

    int nChunks = K >> 5;

    auto load_chunk = [&](int kc, int bsel) {
        uint32_t base = sb + bsel*BUFSZ;
        #pragma unroll
        for (int i = tid; i < 512; i += 256) {
            int r = i >> 2, c = i & 3;
            size_t go = (size_t)r*K*2 + (size_t)kc*64 + c*16;
            uint32_t so = r*80 + c*16;
            cp16(base + so,          pAh + go);
            cp16(base + T_ALO + so,  pAl + go);
            cp16(base + T_BHI + so,  pBh + go);
            cp16(base + T_BLO + so,  pBl + go);
        }
        cp_commit();
    };

    load_chunk(0, 0);

    for (int kc = 0; kc < nChunks; kc++) {
        __syncthreads();
        if (kc + 1 < nChunks) { load_chunk(kc+1, (kc+1)&1); cp_wait<1>(); }
        else                  { cp_wait<0>(); }
        __syncthreads();
        uint32_t bofs = sb + (kc&1)*BUFSZ;
        #pragma unroll
        for (int ks = 0; ks < 2; ks++) {
            uint32_t ah[4][4], al[4][4], bh[2][4], bl[2][4];
            #pragma unroll
            for (int mi = 0; mi < 4; mi++) {
                uint32_t ad = bofs + ((aRow + mi*16)*40 + ks*16 + aK8)*2;
                ldmat4(ah[mi], ad);
                ldmat4(al[mi], ad + T_ALO);
            }
            #pragma unroll
            for (int bj = 0; bj < 2; bj++) {
                uint32_t ad = bofs + T_BHI + ((bRow + bj*16)*40 + ks*16 + bK8)*2;
                ldmat4(bh[bj], ad);
                ldmat4(bl[bj], ad + (T_BLO - T_BHI));
            }
            #pragma unroll
            for (int mi = 0; mi < 4; mi++)
                #pragma unroll
                for (int nj = 0; nj < 4; nj++) {
                    int bj = nj >> 1, pr = (nj & 1)*2;
                    mma_bf16(acc[mi][nj], ah[mi], bh[bj][pr], bh[bj][pr+1]);
                    mma_bf16(acc[mi][nj], ah[mi], bl[bj][pr], bl[bj][pr+1]);
                    mma_bf16(acc[mi][nj], al[mi], bh[bj][pr], bh[bj][pr+1]);
                }
        }
    }
}

// fused QKV: z=0 -> Q (bf16 hi/lo), z=1 -> K (bf16 hi/lo), z=2 -> masked+transposed V split
__global__ __launch_bounds__(256, 1) void qkv_gemm() {
    extern __shared__ char smc[];
    uint32_t sb = smem_u32(smc);
    int z = blockIdx.z;
    int bm = blockIdx.y*128, bn = blockIdx.x*128;
    const __nv_bfloat16 *Bh, *Bl;
    if      (z == 0) { Bh = g_wqhi; Bl = g_wqlo; }
    else if (z == 1) { Bh = g_wkhi; Bl = g_wklo; }
    else             { Bh = g_wvhi; Bl = g_wvlo; }
    float acc[4][4][4] = {};
    gemm_main(smc, sb, g_xhi, g_xlo, Bh, Bl, Ez, bm, bn, acc);

    int lane = threadIdx.x & 31, wid = threadIdx.x >> 5;
    int wm = wid & 1, wn = wid >> 1;
    int r0l = wm*64 + (lane >> 2);
    int c0l = wn*32 + (lane & 3)*2;

    if (z < 2) {
        __nv_bfloat16* Ch = (z == 0) ? g_qhi : g_khi;
        __nv_bfloat16* Cl = (z == 0) ? g_qlo : g_klo;
        #pragma unroll
        for (int mi = 0; mi < 4; mi++)
            #pragma unroll
            for (int nj = 0; nj < 4; nj++) {
                int r = bm + r0l + mi*16, c = bn + c0l + nj*8;
                float v0 = acc[mi][nj][0], v1 = acc[mi][nj][1];
                float v2 = acc[mi][nj][2], v3 = acc[mi][nj][3];
                uint32_t h01 = pk2f(v0, v1), h23 = pk2f(v2, v3);
                uint32_t l01 = pk2f(v0 - bflo(h01), v1 - bfhi(h01));
                uint32_t l23 = pk2f(v2 - bflo(h23), v3 - bfhi(h23));
                *(uint32_t*)(Ch + (size_t)r*Ez + c)     = h01;
                *(uint32_t*)(Cl + (size_t)r*Ez + c)     = l01;
                *(uint32_t*)(Ch + (size_t)(r+8)*Ez + c) = h23;
                *(uint32_t*)(Cl + (size_t)(r+8)*Ez + c) = l23;
            }
    } else {
        // masked transpose split: vt[b][e][l] = mf[bm+l] * V[l][e]
        __syncthreads();   // mainloop smem reads done; reuse buffers
        // smem: hi at 0, lo at BUFSZ; row=e (128), stride 272B, col=l (128) bf16
        #pragma unroll
        for (int mi = 0; mi < 4; mi++) {
            int r = r0l + mi*16;
            float m0 = g_mf[bm + r], m1 = g_mf[bm + r + 8];
            #pragma unroll
            for (int nj = 0; nj < 4; nj++) {
                int c = c0l + nj*8;
                #pragma unroll
                for (int e2 = 0; e2 < 2; e2++) {
                    float v0 = acc[mi][nj][e2]   * m0;       // row r,   col c+e2
                    float v1 = acc[mi][nj][2+e2] * m1;       // row r+8, col c+e2
                    __nv_bfloat16 h0 = __float2bfloat16(v0);
                    __nv_bfloat16 h1 = __float2bfloat16(v1);
                    __nv_bfloat16 l0 = __float2bfloat16(v0 - __bfloat162float(h0));
                    __nv_bfloat16 l1 = __float2bfloat16(v1 - __bfloat162float(h1));
                    uint32_t o0 = (c+e2)*272 + r*2;
                    uint32_t o1 = (c+e2)*272 + (r+8)*2;
                    *(__nv_bfloat16*)(smc + o0) = h0;
                    *(__nv_bfloat16*)(smc + o1) = h1;
                    *(__nv_bfloat16*)(smc + BUFSZ + o0) = l0;
                    *(__nv_bfloat16*)(smc + BUFSZ + o1) = l1;
                }
            }
        }
        __syncthreads();
        int b = bm >> 10;
        int l0g = bm & 1023;
        for (int i = threadIdx.x; i < 2048; i += 256) {
            int e = i >> 4, l8 = (i & 15)*8;
            size_t go = ((size_t)b*Ez + bn + e)*Lz + l0g + l8;
            *(uint4*)(g_vthi + go) = *(const uint4*)(smc + e*272 + l8*2);
            *(uint4*)(g_vtlo + go) = *(const uint4*)(smc + BUFSZ + e*272 + l8*2);
        }
    }
}

// GAV with fused aout epilogue: aout = rs0*U + rs1*acc -> bf16 hi/lo
__global__ __launch_bounds__(256, 1) void gav_gemm() {
    extern __shared__ char smc[];
    uint32_t sb = smem_u32(smc);
    int z = blockIdx.z;
    int bm = blockIdx.y*128, bn = blockIdx.x*128;
    float acc[4][4][4] = {};
    gemm_main(smc, sb, g_acthi, g_actlo,
              g_vthi + (size_t)z*Ez*Lz, g_vtlo + (size_t)z*Ez*Lz,
              Lz, bm, bn, acc);

    int lane = threadIdx.x & 31, wid = threadIdx.x >> 5;
    int wm = wid & 1, wn = wid >> 1;
    int r0 = bm + wm*64 + (lane >> 2);
    int c0 = bn + wn*32 + (lane & 3)*2;
    #pragma unroll
    for (int mi = 0; mi < 4; mi++)
        #pragma unroll
        for (int nj = 0; nj < 4; nj++) {
            int c = c0 + nj*8;
            #pragma unroll
            for (int half = 0; half < 2; half++) {
                size_t R = (size_t)z*Lz + r0 + mi*16 + half*8;
                float rs0 = g_rs0[R], rs1 = g_rs1[R];
                float2 u = *(const float2*)(g_U + R*Ez + c);
                float v0 = rs0*u.x + rs1*acc[mi][nj][half*2];
                float v1 = rs0*u.y + rs1*acc[mi][nj][half*2+1];
                uint32_t h01 = pk2f(v0, v1);
                uint32_t l01 = pk2f(v0 - bflo(h01), v1 - bfhi(h01));
                *(uint32_t*)(g_aohi + R*Ez + c) = h01;
                *(uint32_t*)(g_aolo + R*Ez + c) = l01;
            }
        }
}

// out = Aout @ Wo^T (fp32 epilogue)
__global__ __launch_bounds__(256, 1) void out_gemm(float* __restrict__ C) {
    extern __shared__ char smc[];
    uint32_t sb = smem_u32(smc);
    int bm = blockIdx.y*128, bn = blockIdx.x*128;
    float acc[4][4][4] = {};
    gemm_main(smc, sb, g_aohi, g_aolo, g_wohi, g_wolo, Ez, bm, bn, acc);

    int lane = threadIdx.x & 31, wid = threadIdx.x >> 5;
    int wm = wid & 1, wn = wid >> 1;
    int r0 = bm + wm*64 + (lane >> 2);
    int c0 = bn + wn*32 + (lane & 3)*2;
    #pragma unroll
    for (int mi = 0; mi < 4; mi++)
        #pragma unroll
        for (int nj = 0; nj < 4; nj++) {
            float* p = C + (size_t)(r0 + mi*16)*Ez + c0 + nj*8;
            *(float2*)p                  = make_float2(acc[mi][nj][0], acc[mi][nj][1]);
            *(float2*)(p + (size_t)8*Ez) = make_float2(acc[mi][nj][2], acc[mi][nj][3]);
        }
}

// ---------------- tensor-core attention: cp.async pipelined (unchanged R9) ----------------
#define A_QHI 0
#define A_QLO 18432
#define A_K0  36864
#define A_KLOD 18432
#define A_KBUF 36864
#define A_VHI 110592
#define A_VLO 128000
#define A_PHI 145408
#define A_PLO 180224
#define A_MQ  215040
#define A_MK  215552
#define A_RED 216576
#define AT_SMEM (216576 + 2048)

__global__ __launch_bounds__(512, 1) void attn_mma() {
    extern __shared__ char smc[];
    uint32_t sb = smem_u32(smc);
    float* mqf = (float*)(smc + A_MQ);
    float* red = (float*)(smc + A_RED);

    int tid = threadIdx.x, lane = tid & 31, wid = tid >> 5;
    int qt = blockIdx.x, h = blockIdx.y, b = blockIdx.z;

    int wm = wid & 3, wn = wid >> 2;
    int wq = wid & 7, wd = wid >> 3;

    const __nv_bfloat16* Qh = g_qhi + ((size_t)(b*Lz + qt*128))*Ez + h*64;
    const __nv_bfloat16* Ql = g_qlo + ((size_t)(b*Lz + qt*128))*Ez + h*64;
    const __nv_bfloat16* Kh = g_khi + ((size_t)(b*Lz))*Ez + h*64;
    const __nv_bfloat16* Kl = g_klo + ((size_t)(b*Lz))*Ez + h*64;
    const __nv_bfloat16* Vth = g_vthi + ((size_t)(b*Ez + h*64))*Lz;
    const __nv_bfloat16* Vtl = g_vtlo + ((size_t)(b*Ez + h*64))*Lz;

    auto issue_K = [&](int kt, int bsel) {
        uint32_t base = sb + A_K0 + bsel*A_KBUF;
        #pragma unroll
        for (int i = tid; i < 1024; i += 512) {
            int r = i >> 3, c8 = (i & 7)*8;
            uint32_t off = r*144 + c8*2;
            cp16(base + off,           Kh + (size_t)(kt*128 + r)*Ez + c8);
            cp16(base + A_KLOD + off,  Kl + (size_t)(kt*128 + r)*Ez + c8);
        }
        if (tid < 32) cp16(sb + A_MK + bsel*512 + tid*16, g_mf + b*Lz + kt*128 + tid*4);
        cp_commit();
    };
    auto issue_V = [&](int kt) {
        #pragma unroll
        for (int i = tid; i < 1024; i += 512) {
            int r = i >> 4, c8 = (i & 15)*8;
            uint32_t off = r*272 + c8*2;
            cp16(sb + A_VHI + off, Vth + (size_t)r*Lz + kt*128 + c8);
            cp16(sb + A_VLO + off, Vtl + (size_t)r*Lz + kt*128 + c8);
        }
        cp_commit();
    };

    for (int i = tid; i < 1024; i += 512) {
        int r = i >> 3, c8 = (i & 7)*8;
        uint32_t off = r*144 + c8*2;
        *(uint4*)(smc + A_QHI + off) = *(const uint4*)(Qh + (size_t)r*Ez + c8);
        *(uint4*)(smc + A_QLO + off) = *(const uint4*)(Ql + (size_t)r*Ez + c8);
    }
    if (tid < 128) mqf[tid] = g_mf[b*Lz + qt*128 + tid];

    issue_K(0, 0);
    issue_V(0);

    uint32_t qRow = wm*32 + (lane & 15);
    uint32_t qK8  = (lane >> 4)*8;
    uint32_t kRowB = wn*32 + (lane & 7) + ((lane >> 4) << 3);
    uint32_t kK8  = ((lane >> 3) & 1)*8;
    uint32_t pRow = wq*16 + (lane & 15);
    uint32_t pK8  = (lane >> 4)*8;
    uint32_t vRowB = wd*32 + (lane & 7) + ((lane >> 4) << 3);
    uint32_t vK8  = ((lane >> 3) & 1)*8;

    float U[4][4] = {};
    float partial = 0.f;

    cp_wait<0>();
    __syncthreads();

    for (int kt = 0; kt < 8; kt++) {
        if (kt + 1 < 8) issue_K(kt+1, (kt+1)&1);

        uint32_t kbase = sb + A_K0 + (kt&1)*A_KBUF;
        const float* mkf = (const float*)(smc + A_MK + (kt&1)*512);

        float S[2][4][4] = {};
        #pragma unroll
        for (int ks = 0; ks < 4; ks++) {
            uint32_t ah[2][4], al[2][4], bh[2][4], bl[2][4];
            #pragma unroll
            for (int mi = 0; mi < 2; mi++) {
                uint32_t ad = sb + A_QHI + (qRow + mi*16)*144 + (ks*16 + qK8)*2;
                ldmat4(ah[mi], ad);
                ldmat4(al[mi], ad + (A_QLO - A_QHI));
            }
            #pragma unroll
            for (int nb = 0; nb < 2; nb++) {
                uint32_t ad = kbase + (kRowB + nb*16)*144 + (ks*16 + kK8)*2;
                ldmat4(bh[nb], ad);
                ldmat4(bl[nb], ad + A_KLOD);
            }
            #pragma unroll
            for (int mi = 0; mi < 2; mi++)
                #pragma unroll
                for (int nj = 0; nj < 4; nj++) {
                    int nb = nj >> 1, pr = (nj & 1)*2;
                    mma_bf16(S[mi][nj], ah[mi], bh[nb][pr], bh[nb][pr+1]);
                    mma_bf16(S[mi][nj], ah[mi], bl[nb][pr], bl[nb][pr+1]);
                    mma_bf16(S[mi][nj], al[mi], bh[nb][pr], bh[nb][pr+1]);
                }
        }

        {
            int r0 = wm*32 + (lane >> 2);
            int c0b = wn*32 + (lane & 3)*2;
            #pragma unroll
            for (int mi = 0; mi < 2; mi++) {
                int row0 = r0 + mi*16, row1 = row0 + 8;
                float mq0 = mqf[row0], mq1 = mqf[row1];
                #pragma unroll
                for (int nj = 0; nj < 4; nj++) {
                    int c0 = c0b + nj*8;
                    float mk0 = mkf[c0], mk1 = mkf[c0+1];
                    float p0 = ex2f(tanh_fast(S[mi][nj][0]*0.125f)*L2E)*mk0;
                    float p1 = ex2f(tanh_fast(S[mi][nj][1]*0.125f)*L2E)*mk1;
                    float p2 = ex2f(tanh_fast(S[mi][nj][2]*0.125f)*L2E)*mk0;
                    float p3 = ex2f(tanh_fast(S[mi][nj][3]*0.125f)*L2E)*mk1;
                    partial += mq0*(p0+p1) + mq1*(p2+p3);
                    uint32_t h01 = pk2f(p0, p1), h23 = pk2f(p2, p3);
                    uint32_t l01 = pk2f(p0 - bflo(h01), p1 - bfhi(h01));
                    uint32_t l23 = pk2f(p2 - bflo(h23), p3 - bfhi(h23));
                    uint32_t o0 = row0*272 + c0*2, o1 = row1*272 + c0*2;
                    *(uint32_t*)(smc + A_PHI + o0) = h01;
                    *(uint32_t*)(smc + A_PHI + o1) = h23;
                    *(uint32_t*)(smc + A_PLO + o0) = l01;
                    *(uint32_t*)(smc + A_PLO + o1) = l23;
                }
            }
        }
        __syncthreads();
        if (kt < 7) cp_wait<1>();
        else        cp_wait<0>();

        #pragma unroll
        for (int ch = 0; ch < 8; ch++) {
            uint32_t ph[4], pl[4];
            uint32_t pa = sb + A_PHI + pRow*272 + (ch*16 + pK8)*2;
            ldmat4(ph, pa);
            ldmat4(pl, pa + (A_PLO - A_PHI));
            #pragma unroll
            for (int g = 0; g < 2; g++) {
                uint32_t vh[4], vl[4];
                uint32_t va = sb + A_VHI + (vRowB + g*16)*272 + (ch*16 + vK8)*2;
                ldmat4(vh, va);
                ldmat4(vl, va + (A_VLO - A_VHI));
                mma_bf16(U[g*2],   ph, vh[0], vh[1]);
                mma_bf16(U[g*2],   ph, vl[0], vl[1]);
                mma_bf16(U[g*2],   pl, vh[0], vh[1]);
                mma_bf16(U[g*2+1], ph, vh[2], vh[3]);
                mma_bf16(U[g*2+1], ph, vl[2], vl[3]);
                mma_bf16(U[g*2+1], pl, vh[2], vh[3]);
            }
        }
        __syncthreads();
        if (kt + 1 < 8) {
            issue_V(kt+1);
            cp_wait<1>();
            __syncthreads();
        }
    }

    {
        int r = wq*16 + (lane >> 2);
        int cb = wd*32 + (lane & 3)*2;
        float* Ug = g_U + ((size_t)(b*Lz + qt*128))*Ez + h*64;
        #pragma unroll
        for (int dj = 0; dj < 4; dj++) {
            int c = cb + dj*8;
            *(float2*)(Ug + (size_t)r*Ez + c)     = make_float2(U[dj][0], U[dj][1]);
            *(float2*)(Ug + (size_t)(r+8)*Ez + c) = make_float2(U[dj][2], U[dj][3]);
        }
    }

    red[tid] = partial; __syncthreads();
    for (int s = 256; s > 0; s >>= 1) { if (tid < s) red[tid] += red[tid+s]; __syncthreads(); }
    if (tid == 0) g_Spart[(b*Hz + h)*8 + qt] = red[0];
}

// ---------------- host launcher ----------------
extern "C" void kernel_launch(void* const* d_in, const int* in_sizes, int n_in,
                              void* d_out, int out_size) {
    const float* x    = (const float*)d_in[0];
    const void*  mask = d_in[1];
    const float* Wq   = (const float*)d_in[2];
    const float* Wk   = (const float*)d_in[3];
    const float* Wv   = (const float*)d_in[4];
    const float* Wo   = (const float*)d_in[5];
    const float* G    = (const float*)d_in[6];
    float* out = (float*)d_out;

    cudaFuncSetAttribute((const void*)attn_mma,
                         cudaFuncAttributeMaxDynamicSharedMemorySize, AT_SMEM);
    cudaFuncSetAttribute((const void*)qkv_gemm,
                         cudaFuncAttributeMaxDynamicSharedMemorySize, PIPE_SMEM);
    cudaFuncSetAttribute((const void*)gav_gemm,
                         cudaFuncAttributeMaxDynamicSharedMemorySize, PIPE_SMEM);
    cudaFuncSetAttribute((const void*)out_gemm,
                         cudaFuncAttributeMaxDynamicSharedMemorySize, PIPE_SMEM);

    convert_mask<<<32,256>>>(mask);
    softmax_g<<<1024,256>>>(G);
    reduce_g<<<8,256>>>();

    split_all<<<(NXS + 4*NWS)/256,256>>>(x, Wq, Wk, Wv, Wo);

    qkv_gemm<<<dim3(4,64,3),256,PIPE_SMEM>>>();

    attn_mma<<<dim3(8,Hz,Bz),512,AT_SMEM>>>();
    reduce_s_rowscales<<<8,256>>>();

    gav_gemm<<<dim3(4,8,Bz),256,PIPE_SMEM>>>();
    out_gemm<<<dim3(4,64),256,PIPE_SMEM>>>(out);
}

// round 11
// speedup vs baseline: 2.6624x; 1.0333x over previous
#include <cuda_runtime.h>
#include <cuda_bf16.h>
#include <float.h>
#include <stdint.h>

#define Bz   8
#define Lz   1024
#define Ez   512
#define Hz   8
#define Dz   64

// ---------------- fast-math helpers ----------------
__device__ __forceinline__ float tanh_fast(float x) {
    float y; asm("tanh.approx.f32 %0, %1;" : "=f"(y) : "f"(x)); return y;
}
__device__ __forceinline__ float ex2f(float x) {
    float y; asm("ex2.approx.f32 %0, %1;" : "=f"(y) : "f"(x)); return y;
}
#define L2E 1.4426950408889634f

__device__ __forceinline__ uint32_t smem_u32(const void* p) {
    uint32_t a;
    asm("{ .reg .u64 t; cvta.to.shared.u64 t, %1; cvt.u32.u64 %0, t; }" : "=r"(a) : "l"(p));
    return a;
}
__device__ __forceinline__ uint32_t pk2f(float lo, float hi) {
    uint32_t r; asm("cvt.rn.bf16x2.f32 %0, %1, %2;" : "=r"(r) : "f"(hi), "f"(lo)); return r;
}
__device__ __forceinline__ float bflo(uint32_t v) { return __uint_as_float(v << 16); }
__device__ __forceinline__ float bfhi(uint32_t v) { return __uint_as_float(v & 0xFFFF0000u); }

// ---------------- mma.sync / cp.async helpers ----------------
__device__ __forceinline__ void ldmat4(uint32_t* r, uint32_t a) {
    asm volatile("ldmatrix.sync.aligned.m8n8.x4.shared.b16 {%0,%1,%2,%3}, [%4];"
                 : "=r"(r[0]), "=r"(r[1]), "=r"(r[2]), "=r"(r[3]) : "r"(a));
}
__device__ __forceinline__ void mma_bf16(float* c, const uint32_t* a, uint32_t b0, uint32_t b1) {
    asm volatile("mma.sync.aligned.m16n8k16.row.col.f32.bf16.bf16.f32 "
                 "{%0,%1,%2,%3}, {%4,%5,%6,%7}, {%8,%9}, {%0,%1,%2,%3};"
                 : "+f"(c[0]), "+f"(c[1]), "+f"(c[2]), "+f"(c[3])
                 : "r"(a[0]), "r"(a[1]), "r"(a[2]), "r"(a[3]), "r"(b0), "r"(b1));
}
__device__ __forceinline__ void cp16(uint32_t s, const void* g) {
    asm volatile("cp.async.cg.shared.global [%0], [%1], 16;" :: "r"(s), "l"(g));
}
__device__ __forceinline__ void cp_commit() { asm volatile("cp.async.commit_group;"); }
template<int N> __device__ __forceinline__ void cp_wait() {
    asm volatile("cp.async.wait_group %0;" :: "n"(N));
}

// ---------------- device scratch ----------------
__device__ float g_mf[Bz*Lz];
__device__ float g_U [Bz*Lz*Ez];
__device__ float g_Spart[Bz*Hz*8];
__device__ float g_Gpart[Bz*Lz];
__device__ float g_gs[Bz];
__device__ float g_rs0[Bz*Lz];
__device__ float g_rs1[Bz*Lz];

__device__ __nv_bfloat16 g_xhi[Bz*Lz*Ez],  g_xlo[Bz*Lz*Ez];
__device__ __nv_bfloat16 g_qhi[Bz*Lz*Ez],  g_qlo[Bz*Lz*Ez];
__device__ __nv_bfloat16 g_khi[Bz*Lz*Ez],  g_klo[Bz*Lz*Ez];
__device__ __nv_bfloat16 g_wqhi[Ez*Ez], g_wqlo[Ez*Ez];
__device__ __nv_bfloat16 g_wkhi[Ez*Ez], g_wklo[Ez*Ez];
__device__ __nv_bfloat16 g_wvhi[Ez*Ez], g_wvlo[Ez*Ez];
__device__ __nv_bfloat16 g_wohi[Ez*Ez], g_wolo[Ez*Ez];
__device__ __nv_bfloat16 g_acthi[Lz*Lz], g_actlo[Lz*Lz];
__device__ __nv_bfloat16 g_vthi[Bz*Ez*Lz], g_vtlo[Bz*Ez*Lz];
__device__ __nv_bfloat16 g_aohi[Bz*Lz*Ez], g_aolo[Bz*Lz*Ez];

// ---------------- mask convert (detection fused, per-block) ----------------
__global__ void convert_mask(const void* mv) {
    __shared__ int skind;
    const unsigned char* m = (const unsigned char*)mv;
    if (threadIdx.x == 0) {
        bool isInt32 = true;
        for (int i = 0; i < 64; i++) {
            if (m[4*i] > 1) isInt32 = false;
            if (m[4*i+1] | m[4*i+2] | m[4*i+3]) isInt32 = false;
        }
        int kind;
        if (isInt32) kind = 0;
        else {
            const unsigned int* w = (const unsigned int*)m;
            bool isFloat = true;
            for (int i = 0; i < 64; i++) {
                unsigned v = w[i];
                if (v != 0u && v != 0x3F800000u) isFloat = false;
            }
            kind = isFloat ? 2 : 1;
        }
        skind = kind;
    }
    __syncthreads();
    int i = blockIdx.x*256 + threadIdx.x;
    if (i >= Bz*Lz) return;
    int k = skind;
    float v;
    if (k == 0)      v = ((const int*)mv)[i] ? 1.f : 0.f;
    else if (k == 1) v = m[i] ? 1.f : 0.f;
    else             v = ((const float*)mv)[i];
    g_mf[i] = v;
}

// ---------------- fused hi/lo split of x + 4 weights (float4 vectorized) ----------------
#define NXS4 (Bz*Lz*Ez/4)
#define NWS4 (Ez*Ez/4)
__global__ void split_all(const float4* __restrict__ x,
                          const float4* __restrict__ wq, const float4* __restrict__ wk,
                          const float4* __restrict__ wv, const float4* __restrict__ wo) {
    int i = blockIdx.x*256 + threadIdx.x;
    const float4* s; uint2 *hp, *lp; int idx;
    if (i < NXS4) { s = x; hp = (uint2*)g_xhi; lp = (uint2*)g_xlo; idx = i; }
    else {
        int j = i - NXS4;
        int w = j >> 16;          // / NWS4 (65536)
        idx = j & (NWS4-1);
        if      (w == 0) { s = wq; hp = (uint2*)g_wqhi; lp = (uint2*)g_wqlo; }
        else if (w == 1) { s = wk; hp = (uint2*)g_wkhi; lp = (uint2*)g_wklo; }
        else if (w == 2) { s = wv; hp = (uint2*)g_wvhi; lp = (uint2*)g_wvlo; }
        else             { s = wo; hp = (uint2*)g_wohi; lp = (uint2*)g_wolo; }
    }
    float4 v = s[idx];
    uint32_t h01 = pk2f(v.x, v.y), h23 = pk2f(v.z, v.w);
    uint32_t l01 = pk2f(v.x - bflo(h01), v.y - bfhi(h01));
    uint32_t l23 = pk2f(v.z - bflo(h23), v.w - bfhi(h23));
    hp[idx] = make_uint2(h01, h23);
    lp[idx] = make_uint2(l01, l23);
}

// ---------------- softmax of G rows -> bf16 hi/lo + fused gsum partials ----------------
__global__ __launch_bounds__(256) void softmax_g(const float* __restrict__ G) {
    int q = blockIdx.x, t = threadIdx.x;
    const float* row = G + (size_t)q*Lz;
    __shared__ float red[256];
    __shared__ float part[8][8];
    float mx = -FLT_MAX;
    for (int k = t; k < Lz; k += 256) mx = fmaxf(mx, row[k]);
    red[t] = mx; __syncthreads();
    for (int s = 128; s > 0; s >>= 1) { if (t < s) red[t] = fmaxf(red[t], red[t+s]); __syncthreads(); }
    mx = red[0]; __syncthreads();
    float vals[4]; float sum = 0.f;
    for (int k = t, j = 0; k < Lz; k += 256, j++) { float e = __expf(row[k]-mx); vals[j] = e; sum += e; }
    red[t] = sum; __syncthreads();
    for (int s = 128; s > 0; s >>= 1) { if (t < s) red[t] += red[t+s]; __syncthreads(); }
    float inv = 1.f / red[0];
    float gs[8] = {};
    for (int k = t, j = 0; k < Lz; k += 256, j++) {
        float v = vals[j]*inv;
        __nv_bfloat16 h = __float2bfloat16(v);
        g_acthi[(size_t)q*Lz + k] = h;
        g_actlo[(size_t)q*Lz + k] = __float2bfloat16(v - __bfloat162float(h));
        #pragma unroll
        for (int b2 = 0; b2 < 8; b2++) gs[b2] += v * __ldg(g_mf + b2*Lz + k);
    }
    #pragma unroll
    for (int o = 16; o; o >>= 1)
        #pragma unroll
        for (int b2 = 0; b2 < 8; b2++) gs[b2] += __shfl_down_sync(0xffffffffu, gs[b2], o);
    if ((t & 31) == 0)
        #pragma unroll
        for (int b2 = 0; b2 < 8; b2++) part[t>>5][b2] = gs[b2];
    __syncthreads();
    if (t < 8) {
        float r = 0.f;
        #pragma unroll
        for (int w = 0; w < 8; w++) r += part[w][t];
        g_Gpart[t*Lz + q] = r * __ldg(g_mf + t*Lz + q);
    }
}

// reduce Gpart -> g_gs
__global__ __launch_bounds__(256) void reduce_g() {
    int b = blockIdx.x, t = threadIdx.x;
    __shared__ float red[256];
    float s = 0.f;
    for (int i = t; i < Lz; i += 256) s += g_Gpart[b*Lz + i];
    red[t] = s; __syncthreads();
    for (int st = 128; st > 0; st >>= 1) { if (t < st) red[t] += red[t+st]; __syncthreads(); }
    if (t == 0) g_gs[b] = red[0];
}

// reduce Spart -> S, then rowscales (fused)
__global__ __launch_bounds__(256) void reduce_s_rowscales() {
    int b = blockIdx.x, t = threadIdx.x;
    __shared__ float red[256];
    float s = 0.f;
    for (int i = t; i < Hz*8; i += 256) s += g_Spart[b*Hz*8 + i];
    red[t] = s; __syncthreads();
    for (int st = 128; st > 0; st >>= 1) { if (t < st) red[t] += red[t+st]; __syncthreads(); }
    __syncthreads();
    const float TINY = 1.175494351e-38f;
    float Sv  = fmaxf(red[0], TINY);
    float gsv = fmaxf(g_gs[b], TINY);
    float i0 = 0.5f / Sv, i1 = 0.5f / gsv;
    for (int i = t; i < Lz; i += 256) {
        float mf = g_mf[b*Lz + i];
        g_rs0[b*Lz + i] = mf * i0;
        g_rs1[b*Lz + i] = mf * i1;
    }
}

// ---------------- pipelined HMMA bf16-split GEMM mainloop ----------------
#define T_ALO 10240
#define T_BHI 20480
#define T_BLO 30720
#define BUFSZ 40960
#define PIPE_SMEM (2*BUFSZ)

__device__ __forceinline__ void gemm_main(
    char* smc, uint32_t sb,
    const __nv_bfloat16* Ahi, const __nv_bfloat16* Alo,
    const __nv_bfloat16* Bhi, const __nv_bfloat16* Blo,
    int K, int bm, int bn, float acc[4][4][4])
{
    int tid = threadIdx.x, lane = tid & 31, wid = tid >> 5;
    int wm = wid & 1, wn = wid >> 1;
    const char* pAh = (const char*)(Ahi + (size_t)bm*K);
    const char* pAl = (const char*)(Alo + (size_t)bm*K);
    const char* pBh = (const char*)(Bhi + (size_t)bn*K);
    const char* pBl = (const char*)(Blo + (size_t)bn*K);

    uint32_t aRow = wm*64 + (lane & 15);
    uint32_t aK8  = (lane >> 4) * 8;
    uint32_t bRow = wn*32 + (lane & 7) + ((lane >> 4) << 3);
    uint32_t bK8  = ((lane >> 3) & 1) * 8;

    int nChunks = K >> 5;

    auto load_chunk = [&](int kc, int bsel) {
        uint32_t base = sb + bsel*BUFSZ;
        #pragma unroll
        for (int i = tid; i < 512; i += 256) {
            int r = i >> 2, c = i & 3;
            size_t go = (size_t)r*K*2 + (size_t)kc*64 + c*16;
            uint32_t so = r*80 + c*16;
            cp16(base + so,          pAh + go);
            cp16(base + T_ALO + so,  pAl + go);
            cp16(base + T_BHI + so,  pBh + go);
            cp16(base + T_BLO + so,  pBl + go);
        }
        cp_commit();
    };

    load_chunk(0, 0);

    for (int kc = 0; kc < nChunks; kc++) {
        __syncthreads();
        if (kc + 1 < nChunks) { load_chunk(kc+1, (kc+1)&1); cp_wait<1>(); }
        else                  { cp_wait<0>(); }
        __syncthreads();
        uint32_t bofs = sb + (kc&1)*BUFSZ;
        #pragma unroll
        for (int ks = 0; ks < 2; ks++) {
            uint32_t ah[4][4], al[4][4], bh[2][4], bl[2][4];
            #pragma unroll
            for (int mi = 0; mi < 4; mi++) {
                uint32_t ad = bofs + ((aRow + mi*16)*40 + ks*16 + aK8)*2;
                ldmat4(ah[mi], ad);
                ldmat4(al[mi], ad + T_ALO);
            }
            #pragma unroll
            for (int bj = 0; bj < 2; bj++) {
                uint32_t ad = bofs + T_BHI + ((bRow + bj*16)*40 + ks*16 + bK8)*2;
                ldmat4(bh[bj], ad);
                ldmat4(bl[bj], ad + (T_BLO - T_BHI));
            }
            #pragma unroll
            for (int mi = 0; mi < 4; mi++)
                #pragma unroll
                for (int nj = 0; nj < 4; nj++) {
                    int bj = nj >> 1, pr = (nj & 1)*2;
                    mma_bf16(acc[mi][nj], ah[mi], bh[bj][pr], bh[bj][pr+1]);
                    mma_bf16(acc[mi][nj], ah[mi], bl[bj][pr], bl[bj][pr+1]);
                    mma_bf16(acc[mi][nj], al[mi], bh[bj][pr], bh[bj][pr+1]);
                }
        }
    }
}

// fused QKV: z=0 -> Q (bf16 hi/lo), z=1 -> K (bf16 hi/lo), z=2 -> masked+transposed V split
__global__ __launch_bounds__(256, 1) void qkv_gemm() {
    extern __shared__ char smc[];
    uint32_t sb = smem_u32(smc);
    int z = blockIdx.z;
    int bm = blockIdx.y*128, bn = blockIdx.x*128;
    const __nv_bfloat16 *Bh, *Bl;
    if      (z == 0) { Bh = g_wqhi; Bl = g_wqlo; }
    else if (z == 1) { Bh = g_wkhi; Bl = g_wklo; }
    else             { Bh = g_wvhi; Bl = g_wvlo; }
    float acc[4][4][4] = {};
    gemm_main(smc, sb, g_xhi, g_xlo, Bh, Bl, Ez, bm, bn, acc);

    int lane = threadIdx.x & 31, wid = threadIdx.x >> 5;
    int wm = wid & 1, wn = wid >> 1;
    int r0l = wm*64 + (lane >> 2);
    int c0l = wn*32 + (lane & 3)*2;

    if (z < 2) {
        __nv_bfloat16* Ch = (z == 0) ? g_qhi : g_khi;
        __nv_bfloat16* Cl = (z == 0) ? g_qlo : g_klo;
        #pragma unroll
        for (int mi = 0; mi < 4; mi++)
            #pragma unroll
            for (int nj = 0; nj < 4; nj++) {
                int r = bm + r0l + mi*16, c = bn + c0l + nj*8;
                float v0 = acc[mi][nj][0], v1 = acc[mi][nj][1];
                float v2 = acc[mi][nj][2], v3 = acc[mi][nj][3];
                uint32_t h01 = pk2f(v0, v1), h23 = pk2f(v2, v3);
                uint32_t l01 = pk2f(v0 - bflo(h01), v1 - bfhi(h01));
                uint32_t l23 = pk2f(v2 - bflo(h23), v3 - bfhi(h23));
                *(uint32_t*)(Ch + (size_t)r*Ez + c)     = h01;
                *(uint32_t*)(Cl + (size_t)r*Ez + c)     = l01;
                *(uint32_t*)(Ch + (size_t)(r+8)*Ez + c) = h23;
                *(uint32_t*)(Cl + (size_t)(r+8)*Ez + c) = l23;
            }
    } else {
        // masked transpose split: vt[b][e][l] = mf[bm+l] * V[l][e]
        __syncthreads();
        #pragma unroll
        for (int mi = 0; mi < 4; mi++) {
            int r = r0l + mi*16;
            float m0 = g_mf[bm + r], m1 = g_mf[bm + r + 8];
            #pragma unroll
            for (int nj = 0; nj < 4; nj++) {
                int c = c0l + nj*8;
                #pragma unroll
                for (int e2 = 0; e2 < 2; e2++) {
                    float v0 = acc[mi][nj][e2]   * m0;
                    float v1 = acc[mi][nj][2+e2] * m1;
                    __nv_bfloat16 h0 = __float2bfloat16(v0);
                    __nv_bfloat16 h1 = __float2bfloat16(v1);
                    __nv_bfloat16 l0 = __float2bfloat16(v0 - __bfloat162float(h0));
                    __nv_bfloat16 l1 = __float2bfloat16(v1 - __bfloat162float(h1));
                    uint32_t o0 = (c+e2)*272 + r*2;
                    uint32_t o1 = (c+e2)*272 + (r+8)*2;
                    *(__nv_bfloat16*)(smc + o0) = h0;
                    *(__nv_bfloat16*)(smc + o1) = h1;
                    *(__nv_bfloat16*)(smc + BUFSZ + o0) = l0;
                    *(__nv_bfloat16*)(smc + BUFSZ + o1) = l1;
                }
            }
        }
        __syncthreads();
        int b = bm >> 10;
        int l0g = bm & 1023;
        for (int i = threadIdx.x; i < 2048; i += 256) {
            int e = i >> 4, l8 = (i & 15)*8;
            size_t go = ((size_t)b*Ez + bn + e)*Lz + l0g + l8;
            *(uint4*)(g_vthi + go) = *(const uint4*)(smc + e*272 + l8*2);
            *(uint4*)(g_vtlo + go) = *(const uint4*)(smc + BUFSZ + e*272 + l8*2);
        }
    }
}

// GAV with fused aout epilogue: aout = rs0*U + rs1*acc -> bf16 hi/lo
__global__ __launch_bounds__(256, 1) void gav_gemm() {
    extern __shared__ char smc[];
    uint32_t sb = smem_u32(smc);
    int z = blockIdx.z;
    int bm = blockIdx.y*128, bn = blockIdx.x*128;
    float acc[4][4][4] = {};
    gemm_main(smc, sb, g_acthi, g_actlo,
              g_vthi + (size_t)z*Ez*Lz, g_vtlo + (size_t)z*Ez*Lz,
              Lz, bm, bn, acc);

    int lane = threadIdx.x & 31, wid = threadIdx.x >> 5;
    int wm = wid & 1, wn = wid >> 1;
    int r0 = bm + wm*64 + (lane >> 2);
    int c0 = bn + wn*32 + (lane & 3)*2;
    #pragma unroll
    for (int mi = 0; mi < 4; mi++)
        #pragma unroll
        for (int nj = 0; nj < 4; nj++) {
            int c = c0 + nj*8;
            #pragma unroll
            for (int half = 0; half < 2; half++) {
                size_t R = (size_t)z*Lz + r0 + mi*16 + half*8;
                float rs0 = g_rs0[R], rs1 = g_rs1[R];
                float2 u = *(const float2*)(g_U + R*Ez + c);
                float v0 = rs0*u.x + rs1*acc[mi][nj][half*2];
                float v1 = rs0*u.y + rs1*acc[mi][nj][half*2+1];
                uint32_t h01 = pk2f(v0, v1);
                uint32_t l01 = pk2f(v0 - bflo(h01), v1 - bfhi(h01));
                *(uint32_t*)(g_aohi + R*Ez + c) = h01;
                *(uint32_t*)(g_aolo + R*Ez + c) = l01;
            }
        }
}

// out = Aout @ Wo^T (fp32 epilogue)
__global__ __launch_bounds__(256, 1) void out_gemm(float* __restrict__ C) {
    extern __shared__ char smc[];
    uint32_t sb = smem_u32(smc);
    int bm = blockIdx.y*128, bn = blockIdx.x*128;
    float acc[4][4][4] = {};
    gemm_main(smc, sb, g_aohi, g_aolo, g_wohi, g_wolo, Ez, bm, bn, acc);

    int lane = threadIdx.x & 31, wid = threadIdx.x >> 5;
    int wm = wid & 1, wn = wid >> 1;
    int r0 = bm + wm*64 + (lane >> 2);
    int c0 = bn + wn*32 + (lane & 3)*2;
    #pragma unroll
    for (int mi = 0; mi < 4; mi++)
        #pragma unroll
        for (int nj = 0; nj < 4; nj++) {
            float* p = C + (size_t)(r0 + mi*16)*Ez + c0 + nj*8;
            *(float2*)p                  = make_float2(acc[mi][nj][0], acc[mi][nj][1]);
            *(float2*)(p + (size_t)8*Ez) = make_float2(acc[mi][nj][2], acc[mi][nj][3]);
        }
}

// ---------------- tensor-core attention: cp.async pipelined ----------------
#define A_QHI 0
#define A_QLO 18432
#define A_K0  36864
#define A_KLOD 18432
#define A_KBUF 36864
#define A_VHI 110592
#define A_VLO 128000
#define A_PHI 145408
#define A_PLO 180224
#define A_MQ  215040
#define A_MK  215552
#define A_RED 216576
#define AT_SMEM (216576 + 2048)

__global__ __launch_bounds__(512, 1) void attn_mma() {
    extern __shared__ char smc[];
    uint32_t sb = smem_u32(smc);
    float* mqf = (float*)(smc + A_MQ);
    float* red = (float*)(smc + A_RED);

    int tid = threadIdx.x, lane = tid & 31, wid = tid >> 5;
    int qt = blockIdx.x, h = blockIdx.y, b = blockIdx.z;

    int wm = wid & 3, wn = wid >> 2;
    int wq = wid & 7, wd = wid >> 3;

    const __nv_bfloat16* Qh = g_qhi + ((size_t)(b*Lz + qt*128))*Ez + h*64;
    const __nv_bfloat16* Ql = g_qlo + ((size_t)(b*Lz + qt*128))*Ez + h*64;
    const __nv_bfloat16* Kh = g_khi + ((size_t)(b*Lz))*Ez + h*64;
    const __nv_bfloat16* Kl = g_klo + ((size_t)(b*Lz))*Ez + h*64;
    const __nv_bfloat16* Vth = g_vthi + ((size_t)(b*Ez + h*64))*Lz;
    const __nv_bfloat16* Vtl = g_vtlo + ((size_t)(b*Ez + h*64))*Lz;

    auto issue_K = [&](int kt, int bsel) {
        uint32_t base = sb + A_K0 + bsel*A_KBUF;
        #pragma unroll
        for (int i = tid; i < 1024; i += 512) {
            int r = i >> 3, c8 = (i & 7)*8;
            uint32_t off = r*144 + c8*2;
            cp16(base + off,           Kh + (size_t)(kt*128 + r)*Ez + c8);
            cp16(base + A_KLOD + off,  Kl + (size_t)(kt*128 + r)*Ez + c8);
        }
        if (tid < 32) cp16(sb + A_MK + bsel*512 + tid*16, g_mf + b*Lz + kt*128 + tid*4);
        cp_commit();
    };
    auto issue_V = [&](int kt) {
        #pragma unroll
        for (int i = tid; i < 1024; i += 512) {
            int r = i >> 4, c8 = (i & 15)*8;
            uint32_t off = r*272 + c8*2;
            cp16(sb + A_VHI + off, Vth + (size_t)r*Lz + kt*128 + c8);
            cp16(sb + A_VLO + off, Vtl + (size_t)r*Lz + kt*128 + c8);
        }
        cp_commit();
    };

    for (int i = tid; i < 1024; i += 512) {
        int r = i >> 3, c8 = (i & 7)*8;
        uint32_t off = r*144 + c8*2;
        *(uint4*)(smc + A_QHI + off) = *(const uint4*)(Qh + (size_t)r*Ez + c8);
        *(uint4*)(smc + A_QLO + off) = *(const uint4*)(Ql + (size_t)r*Ez + c8);
    }
    if (tid < 128) mqf[tid] = g_mf[b*Lz + qt*128 + tid];

    issue_K(0, 0);
    issue_V(0);

    uint32_t qRow = wm*32 + (lane & 15);
    uint32_t qK8  = (lane >> 4)*8;
    uint32_t kRowB = wn*32 + (lane & 7) + ((lane >> 4) << 3);
    uint32_t kK8  = ((lane >> 3) & 1)*8;
    uint32_t pRow = wq*16 + (lane & 15);
    uint32_t pK8  = (lane >> 4)*8;
    uint32_t vRowB = wd*32 + (lane & 7) + ((lane >> 4) << 3);
    uint32_t vK8  = ((lane >> 3) & 1)*8;

    float U[4][4] = {};
    float partial = 0.f;

    cp_wait<0>();
    __syncthreads();

    for (int kt = 0; kt < 8; kt++) {
        if (kt + 1 < 8) issue_K(kt+1, (kt+1)&1);

        uint32_t kbase = sb + A_K0 + (kt&1)*A_KBUF;
        const float* mkf = (const float*)(smc + A_MK + (kt&1)*512);

        float S[2][4][4] = {};
        #pragma unroll
        for (int ks = 0; ks < 4; ks++) {
            uint32_t ah[2][4], al[2][4], bh[2][4], bl[2][4];
            #pragma unroll
            for (int mi = 0; mi < 2; mi++) {
                uint32_t ad = sb + A_QHI + (qRow + mi*16)*144 + (ks*16 + qK8)*2;
                ldmat4(ah[mi], ad);
                ldmat4(al[mi], ad + (A_QLO - A_QHI));
            }
            #pragma unroll
            for (int nb = 0; nb < 2; nb++) {
                uint32_t ad = kbase + (kRowB + nb*16)*144 + (ks*16 + kK8)*2;
                ldmat4(bh[nb], ad);
                ldmat4(bl[nb], ad + A_KLOD);
            }
            #pragma unroll
            for (int mi = 0; mi < 2; mi++)
                #pragma unroll
                for (int nj = 0; nj < 4; nj++) {
                    int nb = nj >> 1, pr = (nj & 1)*2;
                    mma_bf16(S[mi][nj], ah[mi], bh[nb][pr], bh[nb][pr+1]);
                    mma_bf16(S[mi][nj], ah[mi], bl[nb][pr], bl[nb][pr+1]);
                    mma_bf16(S[mi][nj], al[mi], bh[nb][pr], bh[nb][pr+1]);
                }
        }

        {
            int r0 = wm*32 + (lane >> 2);
            int c0b = wn*32 + (lane & 3)*2;
            #pragma unroll
            for (int mi = 0; mi < 2; mi++) {
                int row0 = r0 + mi*16, row1 = row0 + 8;
                float mq0 = mqf[row0], mq1 = mqf[row1];
                #pragma unroll
                for (int nj = 0; nj < 4; nj++) {
                    int c0 = c0b + nj*8;
                    float mk0 = mkf[c0], mk1 = mkf[c0+1];
                    float p0 = ex2f(tanh_fast(S[mi][nj][0]*0.125f)*L2E)*mk0;
                    float p1 = ex2f(tanh_fast(S[mi][nj][1]*0.125f)*L2E)*mk1;
                    float p2 = ex2f(tanh_fast(S[mi][nj][2]*0.125f)*L2E)*mk0;
                    float p3 = ex2f(tanh_fast(S[mi][nj][3]*0.125f)*L2E)*mk1;
                    partial += mq0*(p0+p1) + mq1*(p2+p3);
                    uint32_t h01 = pk2f(p0, p1), h23 = pk2f(p2, p3);
                    uint32_t l01 = pk2f(p0 - bflo(h01), p1 - bfhi(h01));
                    uint32_t l23 = pk2f(p2 - bflo(h23), p3 - bfhi(h23));
                    uint32_t o0 = row0*272 + c0*2, o1 = row1*272 + c0*2;
                    *(uint32_t*)(smc + A_PHI + o0) = h01;
                    *(uint32_t*)(smc + A_PHI + o1) = h23;
                    *(uint32_t*)(smc + A_PLO + o0) = l01;
                    *(uint32_t*)(smc + A_PLO + o1) = l23;
                }
            }
        }
        __syncthreads();
        if (kt < 7) cp_wait<1>();
        else        cp_wait<0>();

        #pragma unroll
        for (int ch = 0; ch < 8; ch++) {
            uint32_t ph[4], pl[4];
            uint32_t pa = sb + A_PHI + pRow*272 + (ch*16 + pK8)*2;
            ldmat4(ph, pa);
            ldmat4(pl, pa + (A_PLO - A_PHI));
            #pragma unroll
            for (int g = 0; g < 2; g++) {
                uint32_t vh[4], vl[4];
                uint32_t va = sb + A_VHI + (vRowB + g*16)*272 + (ch*16 + vK8)*2;
                ldmat4(vh, va);
                ldmat4(vl, va + (A_VLO - A_VHI));
                mma_bf16(U[g*2],   ph, vh[0], vh[1]);
                mma_bf16(U[g*2],   ph, vl[0], vl[1]);
                mma_bf16(U[g*2],   pl, vh[0], vh[1]);
                mma_bf16(U[g*2+1], ph, vh[2], vh[3]);
                mma_bf16(U[g*2+1], ph, vl[2], vl[3]);
                mma_bf16(U[g*2+1], pl, vh[2], vh[3]);
            }
        }
        __syncthreads();
        if (kt + 1 < 8) {
            issue_V(kt+1);
            cp_wait<1>();
            __syncthreads();
        }
    }

    {
        int r = wq*16 + (lane >> 2);
        int cb = wd*32 + (lane & 3)*2;
        float* Ug = g_U + ((size_t)(b*Lz + qt*128))*Ez + h*64;
        #pragma unroll
        for (int dj = 0; dj < 4; dj++) {
            int c = cb + dj*8;
            *(float2*)(Ug + (size_t)r*Ez + c)     = make_float2(U[dj][0], U[dj][1]);
            *(float2*)(Ug + (size_t)(r+8)*Ez + c) = make_float2(U[dj][2], U[dj][3]);
        }
    }

    red[tid] = partial; __syncthreads();
    for (int s = 256; s > 0; s >>= 1) { if (tid < s) red[tid] += red[tid+s]; __syncthreads(); }
    if (tid == 0) g_Spart[(b*Hz + h)*8 + qt] = red[0];
}

// ---------------- host launcher ----------------
extern "C" void kernel_launch(void* const* d_in, const int* in_sizes, int n_in,
                              void* d_out, int out_size) {
    const float* x    = (const float*)d_in[0];
    const void*  mask = d_in[1];
    const float* Wq   = (const float*)d_in[2];
    const float* Wk   = (const float*)d_in[3];
    const float* Wv   = (const float*)d_in[4];
    const float* Wo   = (const float*)d_in[5];
    const float* G    = (const float*)d_in[6];
    float* out = (float*)d_out;

    static bool inited = false;
    static cudaStream_t s2;
    static cudaEvent_t evFork, evJoin;
    if (!inited) {
        cudaStreamCreateWithFlags(&s2, cudaStreamNonBlocking);
        cudaEventCreateWithFlags(&evFork, cudaEventDisableTiming);
        cudaEventCreateWithFlags(&evJoin, cudaEventDisableTiming);
        cudaFuncSetAttribute((const void*)attn_mma,
                             cudaFuncAttributeMaxDynamicSharedMemorySize, AT_SMEM);
        cudaFuncSetAttribute((const void*)qkv_gemm,
                             cudaFuncAttributeMaxDynamicSharedMemorySize, PIPE_SMEM);
        cudaFuncSetAttribute((const void*)gav_gemm,
                             cudaFuncAttributeMaxDynamicSharedMemorySize, PIPE_SMEM);
        cudaFuncSetAttribute((const void*)out_gemm,
                             cudaFuncAttributeMaxDynamicSharedMemorySize, PIPE_SMEM);
        inited = true;
    }

    convert_mask<<<32,256>>>(mask);

    // fork: G-softmax chain on s2 (independent until gav/rowscales)
    cudaEventRecord(evFork, 0);
    cudaStreamWaitEvent(s2, evFork, 0);
    softmax_g<<<1024,256,0,s2>>>(G);
    reduce_g<<<8,256,0,s2>>>();
    cudaEventRecord(evJoin, s2);

    // main chain
    split_all<<<(NXS4 + 4*NWS4)/256,256>>>((const float4*)x, (const float4*)Wq,
                                           (const float4*)Wk, (const float4*)Wv,
                                           (const float4*)Wo);
    qkv_gemm<<<dim3(4,64,3),256,PIPE_SMEM>>>();
    attn_mma<<<dim3(8,Hz,Bz),512,AT_SMEM>>>();

    // join: gs + act needed from here on
    cudaStreamWaitEvent(0, evJoin, 0);
    reduce_s_rowscales<<<8,256>>>();
    gav_gemm<<<dim3(4,8,Bz),256,PIPE_SMEM>>>();
    out_gemm<<<dim3(4,64),256,PIPE_SMEM>>>(out);
}

// round 12
// speedup vs baseline: 2.8690x; 1.0776x over previous
#include <cuda_runtime.h>
#include <cuda_bf16.h>
#include <float.h>
#include <stdint.h>

#define Bz   8
#define Lz   1024
#define Ez   512
#define Hz   8
#define Dz   64

// ---------------- fast-math helpers ----------------
__device__ __forceinline__ float tanh_fast(float x) {
    float y; asm("tanh.approx.f32 %0, %1;" : "=f"(y) : "f"(x)); return y;
}
__device__ __forceinline__ float ex2f(float x) {
    float y; asm("ex2.approx.f32 %0, %1;" : "=f"(y) : "f"(x)); return y;
}
#define L2E 1.4426950408889634f

__device__ __forceinline__ uint32_t smem_u32(const void* p) {
    uint32_t a;
    asm("{ .reg .u64 t; cvta.to.shared.u64 t, %1; cvt.u32.u64 %0, t; }" : "=r"(a) : "l"(p));
    return a;
}
__device__ __forceinline__ uint32_t pk2f(float lo, float hi) {
    uint32_t r; asm("cvt.rn.bf16x2.f32 %0, %1, %2;" : "=r"(r) : "f"(hi), "f"(lo)); return r;
}
__device__ __forceinline__ float bflo(uint32_t v) { return __uint_as_float(v << 16); }
__device__ __forceinline__ float bfhi(uint32_t v) { return __uint_as_float(v & 0xFFFF0000u); }

// ---------------- mma.sync / cp.async helpers ----------------
__device__ __forceinline__ void ldmat4(uint32_t* r, uint32_t a) {
    asm volatile("ldmatrix.sync.aligned.m8n8.x4.shared.b16 {%0,%1,%2,%3}, [%4];"
                 : "=r"(r[0]), "=r"(r[1]), "=r"(r[2]), "=r"(r[3]) : "r"(a));
}
__device__ __forceinline__ void mma_bf16(float* c, const uint32_t* a, uint32_t b0, uint32_t b1) {
    asm volatile("mma.sync.aligned.m16n8k16.row.col.f32.bf16.bf16.f32 "
                 "{%0,%1,%2,%3}, {%4,%5,%6,%7}, {%8,%9}, {%0,%1,%2,%3};"
                 : "+f"(c[0]), "+f"(c[1]), "+f"(c[2]), "+f"(c[3])
                 : "r"(a[0]), "r"(a[1]), "r"(a[2]), "r"(a[3]), "r"(b0), "r"(b1));
}
__device__ __forceinline__ void cp16(uint32_t s, const void* g) {
    asm volatile("cp.async.cg.shared.global [%0], [%1], 16;" :: "r"(s), "l"(g));
}
__device__ __forceinline__ void cp_commit() { asm volatile("cp.async.commit_group;"); }
template<int N> __device__ __forceinline__ void cp_wait() {
    asm volatile("cp.async.wait_group %0;" :: "n"(N));
}

// ---------------- device scratch ----------------
__device__ float g_mf[Bz*Lz];
__device__ float g_U [Bz*Lz*Ez];
__device__ float g_GAV[Bz*Lz*Ez];
__device__ float g_Spart[Bz*Hz*8];
__device__ float g_Gpart[Bz*Lz];
__device__ float g_gs[Bz];
__device__ float g_rs0[Bz*Lz];
__device__ float g_rs1[Bz*Lz];

__device__ __nv_bfloat16 g_xhi[Bz*Lz*Ez],  g_xlo[Bz*Lz*Ez];
__device__ __nv_bfloat16 g_qhi[Bz*Lz*Ez],  g_qlo[Bz*Lz*Ez];
__device__ __nv_bfloat16 g_khi[Bz*Lz*Ez],  g_klo[Bz*Lz*Ez];
__device__ __nv_bfloat16 g_wqhi[Ez*Ez], g_wqlo[Ez*Ez];
__device__ __nv_bfloat16 g_wkhi[Ez*Ez], g_wklo[Ez*Ez];
__device__ __nv_bfloat16 g_wvhi[Ez*Ez], g_wvlo[Ez*Ez];
__device__ __nv_bfloat16 g_wohi[Ez*Ez], g_wolo[Ez*Ez];
__device__ __nv_bfloat16 g_acthi[Lz*Lz], g_actlo[Lz*Lz];
__device__ __nv_bfloat16 g_vthi[Bz*Ez*Lz], g_vtlo[Bz*Ez*Lz];
__device__ __nv_bfloat16 g_aohi[Bz*Lz*Ez], g_aolo[Bz*Lz*Ez];

// ---------------- mask convert (detection fused, per-block) ----------------
__global__ void convert_mask(const void* mv) {
    __shared__ int skind;
    const unsigned char* m = (const unsigned char*)mv;
    if (threadIdx.x == 0) {
        bool isInt32 = true;
        for (int i = 0; i < 64; i++) {
            if (m[4*i] > 1) isInt32 = false;
            if (m[4*i+1] | m[4*i+2] | m[4*i+3]) isInt32 = false;
        }
        int kind;
        if (isInt32) kind = 0;
        else {
            const unsigned int* w = (const unsigned int*)m;
            bool isFloat = true;
            for (int i = 0; i < 64; i++) {
                unsigned v = w[i];
                if (v != 0u && v != 0x3F800000u) isFloat = false;
            }
            kind = isFloat ? 2 : 1;
        }
        skind = kind;
    }
    __syncthreads();
    int i = blockIdx.x*256 + threadIdx.x;
    if (i >= Bz*Lz) return;
    int k = skind;
    float v;
    if (k == 0)      v = ((const int*)mv)[i] ? 1.f : 0.f;
    else if (k == 1) v = m[i] ? 1.f : 0.f;
    else             v = ((const float*)mv)[i];
    g_mf[i] = v;
}

// ---------------- fused hi/lo split of x + 4 weights (float4 vectorized) ----------------
#define NXS4 (Bz*Lz*Ez/4)
#define NWS4 (Ez*Ez/4)
__global__ void split_all(const float4* __restrict__ x,
                          const float4* __restrict__ wq, const float4* __restrict__ wk,
                          const float4* __restrict__ wv, const float4* __restrict__ wo) {
    int i = blockIdx.x*256 + threadIdx.x;
    const float4* s; uint2 *hp, *lp; int idx;
    if (i < NXS4) { s = x; hp = (uint2*)g_xhi; lp = (uint2*)g_xlo; idx = i; }
    else {
        int j = i - NXS4;
        int w = j >> 16;
        idx = j & (NWS4-1);
        if      (w == 0) { s = wq; hp = (uint2*)g_wqhi; lp = (uint2*)g_wqlo; }
        else if (w == 1) { s = wk; hp = (uint2*)g_wkhi; lp = (uint2*)g_wklo; }
        else if (w == 2) { s = wv; hp = (uint2*)g_wvhi; lp = (uint2*)g_wvlo; }
        else             { s = wo; hp = (uint2*)g_wohi; lp = (uint2*)g_wolo; }
    }
    float4 v = s[idx];
    uint32_t h01 = pk2f(v.x, v.y), h23 = pk2f(v.z, v.w);
    uint32_t l01 = pk2f(v.x - bflo(h01), v.y - bfhi(h01));
    uint32_t l23 = pk2f(v.z - bflo(h23), v.w - bfhi(h23));
    hp[idx] = make_uint2(h01, h23);
    lp[idx] = make_uint2(l01, l23);
}

// ---------------- softmax of G rows -> bf16 hi/lo + fused gsum partials ----------------
__global__ __launch_bounds__(256) void softmax_g(const float* __restrict__ G) {
    int q = blockIdx.x, t = threadIdx.x;
    const float* row = G + (size_t)q*Lz;
    __shared__ float red[256];
    __shared__ float part[8][8];
    float mx = -FLT_MAX;
    for (int k = t; k < Lz; k += 256) mx = fmaxf(mx, row[k]);
    red[t] = mx; __syncthreads();
    for (int s = 128; s > 0; s >>= 1) { if (t < s) red[t] = fmaxf(red[t], red[t+s]); __syncthreads(); }
    mx = red[0]; __syncthreads();
    float vals[4]; float sum = 0.f;
    for (int k = t, j = 0; k < Lz; k += 256, j++) { float e = __expf(row[k]-mx); vals[j] = e; sum += e; }
    red[t] = sum; __syncthreads();
    for (int s = 128; s > 0; s >>= 1) { if (t < s) red[t] += red[t+s]; __syncthreads(); }
    float inv = 1.f / red[0];
    float gs[8] = {};
    for (int k = t, j = 0; k < Lz; k += 256, j++) {
        float v = vals[j]*inv;
        __nv_bfloat16 h = __float2bfloat16(v);
        g_acthi[(size_t)q*Lz + k] = h;
        g_actlo[(size_t)q*Lz + k] = __float2bfloat16(v - __bfloat162float(h));
        #pragma unroll
        for (int b2 = 0; b2 < 8; b2++) gs[b2] += v * __ldg(g_mf + b2*Lz + k);
    }
    #pragma unroll
    for (int o = 16; o; o >>= 1)
        #pragma unroll
        for (int b2 = 0; b2 < 8; b2++) gs[b2] += __shfl_down_sync(0xffffffffu, gs[b2], o);
    if ((t & 31) == 0)
        #pragma unroll
        for (int b2 = 0; b2 < 8; b2++) part[t>>5][b2] = gs[b2];
    __syncthreads();
    if (t < 8) {
        float r = 0.f;
        #pragma unroll
        for (int w = 0; w < 8; w++) r += part[w][t];
        g_Gpart[t*Lz + q] = r * __ldg(g_mf + t*Lz + q);
    }
}

__global__ __launch_bounds__(256) void reduce_g() {
    int b = blockIdx.x, t = threadIdx.x;
    __shared__ float red[256];
    float s = 0.f;
    for (int i = t; i < Lz; i += 256) s += g_Gpart[b*Lz + i];
    red[t] = s; __syncthreads();
    for (int st = 128; st > 0; st >>= 1) { if (t < st) red[t] += red[t+st]; __syncthreads(); }
    if (t == 0) g_gs[b] = red[0];
}

__global__ __launch_bounds__(256) void reduce_s_rowscales() {
    int b = blockIdx.x, t = threadIdx.x;
    __shared__ float red[256];
    float s = 0.f;
    for (int i = t; i < Hz*8; i += 256) s += g_Spart[b*Hz*8 + i];
    red[t] = s; __syncthreads();
    for (int st = 128; st > 0; st >>= 1) { if (t < st) red[t] += red[t+st]; __syncthreads(); }
    __syncthreads();
    const float TINY = 1.175494351e-38f;
    float Sv  = fmaxf(red[0], TINY);
    float gsv = fmaxf(g_gs[b], TINY);
    float i0 = 0.5f / Sv, i1 = 0.5f / gsv;
    for (int i = t; i < Lz; i += 256) {
        float mf = g_mf[b*Lz + i];
        g_rs0[b*Lz + i] = mf * i0;
        g_rs1[b*Lz + i] = mf * i1;
    }
}

// aout = rs0*U + rs1*GAV -> bf16 hi/lo (float4 vectorized)
__global__ void prep_out() {
    int i = blockIdx.x*256 + threadIdx.x;     // float4 units
    if (i >= Bz*Lz*Ez/4) return;
    int row = i >> 7;                          // (i*4) >> 9
    float rs0 = g_rs0[row], rs1 = g_rs1[row];
    float4 u = ((const float4*)g_U)[i];
    float4 g = ((const float4*)g_GAV)[i];
    float v0 = rs0*u.x + rs1*g.x;
    float v1 = rs0*u.y + rs1*g.y;
    float v2 = rs0*u.z + rs1*g.z;
    float v3 = rs0*u.w + rs1*g.w;
    uint32_t h01 = pk2f(v0, v1), h23 = pk2f(v2, v3);
    uint32_t l01 = pk2f(v0 - bflo(h01), v1 - bfhi(h01));
    uint32_t l23 = pk2f(v2 - bflo(h23), v3 - bfhi(h23));
    ((uint2*)g_aohi)[i] = make_uint2(h01, h23);
    ((uint2*)g_aolo)[i] = make_uint2(l01, l23);
}

// ---------------- pipelined HMMA bf16-split GEMM mainloop ----------------
#define T_ALO 10240
#define T_BHI 20480
#define T_BLO 30720
#define BUFSZ 40960
#define PIPE_SMEM (2*BUFSZ)

__device__ __forceinline__ void gemm_main(
    char* smc, uint32_t sb,
    const __nv_bfloat16* Ahi, const __nv_bfloat16* Alo,
    const __nv_bfloat16* Bhi, const __nv_bfloat16* Blo,
    int K, int bm, int bn, float acc[4][4][4])
{
    int tid = threadIdx.x, lane = tid & 31, wid = tid >> 5;
    int wm = wid & 1, wn = wid >> 1;
    const char* pAh = (const char*)(Ahi + (size_t)bm*K);
    const char* pAl = (const char*)(Alo + (size_t)bm*K);
    const char* pBh = (const char*)(Bhi + (size_t)bn*K);
    const char* pBl = (const char*)(Blo + (size_t)bn*K);

    uint32_t aRow = wm*64 + (lane & 15);
    uint32_t aK8  = (lane >> 4) * 8;
    uint32_t bRow = wn*32 + (lane & 7) + ((lane >> 4) << 3);
    uint32_t bK8  = ((lane >> 3) & 1) * 8;

    int nChunks = K >> 5;

    auto load_chunk = [&](int kc, int bsel) {
        uint32_t base = sb + bsel*BUFSZ;
        #pragma unroll
        for (int i = tid; i < 512; i += 256) {
            int r = i >> 2, c = i & 3;
            size_t go = (size_t)r*K*2 + (size_t)kc*64 + c*16;
            uint32_t so = r*80 + c*16;
            cp16(base + so,          pAh + go);
            cp16(base + T_ALO + so,  pAl + go);
            cp16(base + T_BHI + so,  pBh + go);
            cp16(base + T_BLO + so,  pBl + go);
        }
        cp_commit();
    };

    load_chunk(0, 0);

    for (int kc = 0; kc < nChunks; kc++) {
        __syncthreads();
        if (kc + 1 < nChunks) { load_chunk(kc+1, (kc+1)&1); cp_wait<1>(); }
        else                  { cp_wait<0>(); }
        __syncthreads();
        uint32_t bofs = sb + (kc&1)*BUFSZ;
        #pragma unroll
        for (int ks = 0; ks < 2; ks++) {
            uint32_t ah[4][4], al[4][4], bh[2][4], bl[2][4];
            #pragma unroll
            for (int mi = 0; mi < 4; mi++) {
                uint32_t ad = bofs + ((aRow + mi*16)*40 + ks*16 + aK8)*2;
                ldmat4(ah[mi], ad);
                ldmat4(al[mi], ad + T_ALO);
            }
            #pragma unroll
            for (int bj = 0; bj < 2; bj++) {
                uint32_t ad = bofs + T_BHI + ((bRow + bj*16)*40 + ks*16 + bK8)*2;
                ldmat4(bh[bj], ad);
                ldmat4(bl[bj], ad + (T_BLO - T_BHI));
            }
            #pragma unroll
            for (int mi = 0; mi < 4; mi++)
                #pragma unroll
                for (int nj = 0; nj < 4; nj++) {
                    int bj = nj >> 1, pr = (nj & 1)*2;
                    mma_bf16(acc[mi][nj], ah[mi], bh[bj][pr], bh[bj][pr+1]);
                    mma_bf16(acc[mi][nj], ah[mi], bl[bj][pr], bl[bj][pr+1]);
                    mma_bf16(acc[mi][nj], al[mi], bh[bj][pr], bh[bj][pr+1]);
                }
        }
    }
}

// fused QKV: z=0 -> Q (bf16 hi/lo), z=1 -> K (bf16 hi/lo), z=2 -> masked+transposed V split
__global__ __launch_bounds__(256, 1) void qkv_gemm() {
    extern __shared__ char smc[];
    uint32_t sb = smem_u32(smc);
    int z = blockIdx.z;
    int bm = blockIdx.y*128, bn = blockIdx.x*128;
    const __nv_bfloat16 *Bh, *Bl;
    if      (z == 0) { Bh = g_wqhi; Bl = g_wqlo; }
    else if (z == 1) { Bh = g_wkhi; Bl = g_wklo; }
    else             { Bh = g_wvhi; Bl = g_wvlo; }
    float acc[4][4][4] = {};
    gemm_main(smc, sb, g_xhi, g_xlo, Bh, Bl, Ez, bm, bn, acc);

    int lane = threadIdx.x & 31, wid = threadIdx.x >> 5;
    int wm = wid & 1, wn = wid >> 1;
    int r0l = wm*64 + (lane >> 2);
    int c0l = wn*32 + (lane & 3)*2;

    if (z < 2) {
        __nv_bfloat16* Ch = (z == 0) ? g_qhi : g_khi;
        __nv_bfloat16* Cl = (z == 0) ? g_qlo : g_klo;
        #pragma unroll
        for (int mi = 0; mi < 4; mi++)
            #pragma unroll
            for (int nj = 0; nj < 4; nj++) {
                int r = bm + r0l + mi*16, c = bn + c0l + nj*8;
                float v0 = acc[mi][nj][0], v1 = acc[mi][nj][1];
                float v2 = acc[mi][nj][2], v3 = acc[mi][nj][3];
                uint32_t h01 = pk2f(v0, v1), h23 = pk2f(v2, v3);
                uint32_t l01 = pk2f(v0 - bflo(h01), v1 - bfhi(h01));
                uint32_t l23 = pk2f(v2 - bflo(h23), v3 - bfhi(h23));
                *(uint32_t*)(Ch + (size_t)r*Ez + c)     = h01;
                *(uint32_t*)(Cl + (size_t)r*Ez + c)     = l01;
                *(uint32_t*)(Ch + (size_t)(r+8)*Ez + c) = h23;
                *(uint32_t*)(Cl + (size_t)(r+8)*Ez + c) = l23;
            }
    } else {
        __syncthreads();
        #pragma unroll
        for (int mi = 0; mi < 4; mi++) {
            int r = r0l + mi*16;
            float m0 = g_mf[bm + r], m1 = g_mf[bm + r + 8];
            #pragma unroll
            for (int nj = 0; nj < 4; nj++) {
                int c = c0l + nj*8;
                #pragma unroll
                for (int e2 = 0; e2 < 2; e2++) {
                    float v0 = acc[mi][nj][e2]   * m0;
                    float v1 = acc[mi][nj][2+e2] * m1;
                    __nv_bfloat16 h0 = __float2bfloat16(v0);
                    __nv_bfloat16 h1 = __float2bfloat16(v1);
                    __nv_bfloat16 l0 = __float2bfloat16(v0 - __bfloat162float(h0));
                    __nv_bfloat16 l1 = __float2bfloat16(v1 - __bfloat162float(h1));
                    uint32_t o0 = (c+e2)*272 + r*2;
                    uint32_t o1 = (c+e2)*272 + (r+8)*2;
                    *(__nv_bfloat16*)(smc + o0) = h0;
                    *(__nv_bfloat16*)(smc + o1) = h1;
                    *(__nv_bfloat16*)(smc + BUFSZ + o0) = l0;
                    *(__nv_bfloat16*)(smc + BUFSZ + o1) = l1;
                }
            }
        }
        __syncthreads();
        int b = bm >> 10;
        int l0g = bm & 1023;
        for (int i = threadIdx.x; i < 2048; i += 256) {
            int e = i >> 4, l8 = (i & 15)*8;
            size_t go = ((size_t)b*Ez + bn + e)*Lz + l0g + l8;
            *(uint4*)(g_vthi + go) = *(const uint4*)(smc + e*272 + l8*2);
            *(uint4*)(g_vtlo + go) = *(const uint4*)(smc + BUFSZ + e*272 + l8*2);
        }
    }
}

// GAV plain GEMM (fp32 out) — runs on stream2 concurrent with attention
__global__ __launch_bounds__(256, 1) void gav_gemm() {
    extern __shared__ char smc[];
    uint32_t sb = smem_u32(smc);
    int z = blockIdx.z;
    int bm = blockIdx.y*128, bn = blockIdx.x*128;
    float acc[4][4][4] = {};
    gemm_main(smc, sb, g_acthi, g_actlo,
              g_vthi + (size_t)z*Ez*Lz, g_vtlo + (size_t)z*Ez*Lz,
              Lz, bm, bn, acc);

    int lane = threadIdx.x & 31, wid = threadIdx.x >> 5;
    int wm = wid & 1, wn = wid >> 1;
    int r0 = bm + wm*64 + (lane >> 2);
    int c0 = bn + wn*32 + (lane & 3)*2;
    float* Cp = g_GAV + (size_t)z*Lz*Ez;
    #pragma unroll
    for (int mi = 0; mi < 4; mi++)
        #pragma unroll
        for (int nj = 0; nj < 4; nj++) {
            float* p = Cp + (size_t)(r0 + mi*16)*Ez + c0 + nj*8;
            *(float2*)p                  = make_float2(acc[mi][nj][0], acc[mi][nj][1]);
            *(float2*)(p + (size_t)8*Ez) = make_float2(acc[mi][nj][2], acc[mi][nj][3]);
        }
}

// out = Aout @ Wo^T (fp32 epilogue)
__global__ __launch_bounds__(256, 1) void out_gemm(float* __restrict__ C) {
    extern __shared__ char smc[];
    uint32_t sb = smem_u32(smc);
    int bm = blockIdx.y*128, bn = blockIdx.x*128;
    float acc[4][4][4] = {};
    gemm_main(smc, sb, g_aohi, g_aolo, g_wohi, g_wolo, Ez, bm, bn, acc);

    int lane = threadIdx.x & 31, wid = threadIdx.x >> 5;
    int wm = wid & 1, wn = wid >> 1;
    int r0 = bm + wm*64 + (lane >> 2);
    int c0 = bn + wn*32 + (lane & 3)*2;
    #pragma unroll
    for (int mi = 0; mi < 4; mi++)
        #pragma unroll
        for (int nj = 0; nj < 4; nj++) {
            float* p = C + (size_t)(r0 + mi*16)*Ez + c0 + nj*8;
            *(float2*)p                  = make_float2(acc[mi][nj][0], acc[mi][nj][1]);
            *(float2*)(p + (size_t)8*Ez) = make_float2(acc[mi][nj][2], acc[mi][nj][3]);
        }
}

// ---------------- tensor-core attention: cp.async pipelined, Q hi-only S phase ----------------
#define A_QHI 0
#define A_K0  36864
#define A_KLOD 18432
#define A_KBUF 36864
#define A_VHI 110592
#define A_VLO 128000
#define A_PHI 145408
#define A_PLO 180224
#define A_MQ  215040
#define A_MK  215552
#define A_RED 216576
#define AT_SMEM (216576 + 2048)

__global__ __launch_bounds__(512, 1) void attn_mma() {
    extern __shared__ char smc[];
    uint32_t sb = smem_u32(smc);
    float* mqf = (float*)(smc + A_MQ);
    float* red = (float*)(smc + A_RED);

    int tid = threadIdx.x, lane = tid & 31, wid = tid >> 5;
    int qt = blockIdx.x, h = blockIdx.y, b = blockIdx.z;

    int wm = wid & 3, wn = wid >> 2;
    int wq = wid & 7, wd = wid >> 3;

    const __nv_bfloat16* Qh = g_qhi + ((size_t)(b*Lz + qt*128))*Ez + h*64;
    const __nv_bfloat16* Kh = g_khi + ((size_t)(b*Lz))*Ez + h*64;
    const __nv_bfloat16* Kl = g_klo + ((size_t)(b*Lz))*Ez + h*64;
    const __nv_bfloat16* Vth = g_vthi + ((size_t)(b*Ez + h*64))*Lz;
    const __nv_bfloat16* Vtl = g_vtlo + ((size_t)(b*Ez + h*64))*Lz;

    auto issue_K = [&](int kt, int bsel) {
        uint32_t base = sb + A_K0 + bsel*A_KBUF;
        #pragma unroll
        for (int i = tid; i < 1024; i += 512) {
            int r = i >> 3, c8 = (i & 7)*8;
            uint32_t off = r*144 + c8*2;
            cp16(base + off,           Kh + (size_t)(kt*128 + r)*Ez + c8);
            cp16(base + A_KLOD + off,  Kl + (size_t)(kt*128 + r)*Ez + c8);
        }
        if (tid < 32) cp16(sb + A_MK + bsel*512 + tid*16, g_mf + b*Lz + kt*128 + tid*4);
        cp_commit();
    };
    auto issue_V = [&](int kt) {
        #pragma unroll
        for (int i = tid; i < 1024; i += 512) {
            int r = i >> 4, c8 = (i & 15)*8;
            uint32_t off = r*272 + c8*2;
            cp16(sb + A_VHI + off, Vth + (size_t)r*Lz + kt*128 + c8);
            cp16(sb + A_VLO + off, Vtl + (size_t)r*Lz + kt*128 + c8);
        }
        cp_commit();
    };

    // Q hi only (rows 128 x 64, stride 144B)
    for (int i = tid; i < 1024; i += 512) {
        int r = i >> 3, c8 = (i & 7)*8;
        uint32_t off = r*144 + c8*2;
        *(uint4*)(smc + A_QHI + off) = *(const uint4*)(Qh + (size_t)r*Ez + c8);
    }
    if (tid < 128) mqf[tid] = g_mf[b*Lz + qt*128 + tid];

    issue_K(0, 0);
    issue_V(0);

    uint32_t qRow = wm*32 + (lane & 15);
    uint32_t qK8  = (lane >> 4)*8;
    uint32_t kRowB = wn*32 + (lane & 7) + ((lane >> 4) << 3);
    uint32_t kK8  = ((lane >> 3) & 1)*8;
    uint32_t pRow = wq*16 + (lane & 15);
    uint32_t pK8  = (lane >> 4)*8;
    uint32_t vRowB = wd*32 + (lane & 7) + ((lane >> 4) << 3);
    uint32_t vK8  = ((lane >> 3) & 1)*8;

    float U[4][4] = {};
    float partial = 0.f;

    cp_wait<0>();
    __syncthreads();

    for (int kt = 0; kt < 8; kt++) {
        if (kt + 1 < 8) issue_K(kt+1, (kt+1)&1);

        uint32_t kbase = sb + A_K0 + (kt&1)*A_KBUF;
        const float* mkf = (const float*)(smc + A_MK + (kt&1)*512);

        // ---- S = Qhi (Khi + Klo)^T  (2-product) ----
        float S[2][4][4] = {};
        #pragma unroll
        for (int ks = 0; ks < 4; ks++) {
            uint32_t ah[2][4], bh[2][4], bl[2][4];
            #pragma unroll
            for (int mi = 0; mi < 2; mi++) {
                uint32_t ad = sb + A_QHI + (qRow + mi*16)*144 + (ks*16 + qK8)*2;
                ldmat4(ah[mi], ad);
            }
            #pragma unroll
            for (int nb = 0; nb < 2; nb++) {
                uint32_t ad = kbase + (kRowB + nb*16)*144 + (ks*16 + kK8)*2;
                ldmat4(bh[nb], ad);
                ldmat4(bl[nb], ad + A_KLOD);
            }
            #pragma unroll
            for (int mi = 0; mi < 2; mi++)
                #pragma unroll
                for (int nj = 0; nj < 4; nj++) {
                    int nb = nj >> 1, pr = (nj & 1)*2;
                    mma_bf16(S[mi][nj], ah[mi], bh[nb][pr], bh[nb][pr+1]);
                    mma_bf16(S[mi][nj], ah[mi], bl[nb][pr], bl[nb][pr+1]);
                }
        }

        {
            int r0 = wm*32 + (lane >> 2);
            int c0b = wn*32 + (lane & 3)*2;
            #pragma unroll
            for (int mi = 0; mi < 2; mi++) {
                int row0 = r0 + mi*16, row1 = row0 + 8;
                float mq0 = mqf[row0], mq1 = mqf[row1];
                #pragma unroll
                for (int nj = 0; nj < 4; nj++) {
                    int c0 = c0b + nj*8;
                    float mk0 = mkf[c0], mk1 = mkf[c0+1];
                    float p0 = ex2f(tanh_fast(S[mi][nj][0]*0.125f)*L2E)*mk0;
                    float p1 = ex2f(tanh_fast(S[mi][nj][1]*0.125f)*L2E)*mk1;
                    float p2 = ex2f(tanh_fast(S[mi][nj][2]*0.125f)*L2E)*mk0;
                    float p3 = ex2f(tanh_fast(S[mi][nj][3]*0.125f)*L2E)*mk1;
                    partial += mq0*(p0+p1) + mq1*(p2+p3);
                    uint32_t h01 = pk2f(p0, p1), h23 = pk2f(p2, p3);
                    uint32_t l01 = pk2f(p0 - bflo(h01), p1 - bfhi(h01));
                    uint32_t l23 = pk2f(p2 - bflo(h23), p3 - bfhi(h23));
                    uint32_t o0 = row0*272 + c0*2, o1 = row1*272 + c0*2;
                    *(uint32_t*)(smc + A_PHI + o0) = h01;
                    *(uint32_t*)(smc + A_PHI + o1) = h23;
                    *(uint32_t*)(smc + A_PLO + o0) = l01;
                    *(uint32_t*)(smc + A_PLO + o1) = l23;
                }
            }
        }
        __syncthreads();
        if (kt < 7) cp_wait<1>();
        else        cp_wait<0>();

        #pragma unroll
        for (int ch = 0; ch < 8; ch++) {
            uint32_t ph[4], pl[4];
            uint32_t pa = sb + A_PHI + pRow*272 + (ch*16 + pK8)*2;
            ldmat4(ph, pa);
            ldmat4(pl, pa + (A_PLO - A_PHI));
            #pragma unroll
            for (int g = 0; g < 2; g++) {
                uint32_t vh[4], vl[4];
                uint32_t va = sb + A_VHI + (vRowB + g*16)*272 + (ch*16 + vK8)*2;
                ldmat4(vh, va);
                ldmat4(vl, va + (A_VLO - A_VHI));
                mma_bf16(U[g*2],   ph, vh[0], vh[1]);
                mma_bf16(U[g*2],   ph, vl[0], vl[1]);
                mma_bf16(U[g*2],   pl, vh[0], vh[1]);
                mma_bf16(U[g*2+1], ph, vh[2], vh[3]);
                mma_bf16(U[g*2+1], ph, vl[2], vl[3]);
                mma_bf16(U[g*2+1], pl, vh[2], vh[3]);
            }
        }
        __syncthreads();
        if (kt + 1 < 8) {
            issue_V(kt+1);
            cp_wait<1>();
            __syncthreads();
        }
    }

    {
        int r = wq*16 + (lane >> 2);
        int cb = wd*32 + (lane & 3)*2;
        float* Ug = g_U + ((size_t)(b*Lz + qt*128))*Ez + h*64;
        #pragma unroll
        for (int dj = 0; dj < 4; dj++) {
            int c = cb + dj*8;
            *(float2*)(Ug + (size_t)r*Ez + c)     = make_float2(U[dj][0], U[dj][1]);
            *(float2*)(Ug + (size_t)(r+8)*Ez + c) = make_float2(U[dj][2], U[dj][3]);
        }
    }

    red[tid] = partial; __syncthreads();
    for (int s = 256; s > 0; s >>= 1) { if (tid < s) red[tid] += red[tid+s]; __syncthreads(); }
    if (tid == 0) g_Spart[(b*Hz + h)*8 + qt] = red[0];
}

// ---------------- host launcher ----------------
extern "C" void kernel_launch(void* const* d_in, const int* in_sizes, int n_in,
                              void* d_out, int out_size) {
    const float* x    = (const float*)d_in[0];
    const void*  mask = d_in[1];
    const float* Wq   = (const float*)d_in[2];
    const float* Wk   = (const float*)d_in[3];
    const float* Wv   = (const float*)d_in[4];
    const float* Wo   = (const float*)d_in[5];
    const float* G    = (const float*)d_in[6];
    float* out = (float*)d_out;

    static bool inited = false;
    static cudaStream_t s2;
    static cudaEvent_t evFork, evQKV, evJoin;
    if (!inited) {
        cudaStreamCreateWithFlags(&s2, cudaStreamNonBlocking);
        cudaEventCreateWithFlags(&evFork, cudaEventDisableTiming);
        cudaEventCreateWithFlags(&evQKV, cudaEventDisableTiming);
        cudaEventCreateWithFlags(&evJoin, cudaEventDisableTiming);
        cudaFuncSetAttribute((const void*)attn_mma,
                             cudaFuncAttributeMaxDynamicSharedMemorySize, AT_SMEM);
        cudaFuncSetAttribute((const void*)qkv_gemm,
                             cudaFuncAttributeMaxDynamicSharedMemorySize, PIPE_SMEM);
        cudaFuncSetAttribute((const void*)gav_gemm,
                             cudaFuncAttributeMaxDynamicSharedMemorySize, PIPE_SMEM);
        cudaFuncSetAttribute((const void*)out_gemm,
                             cudaFuncAttributeMaxDynamicSharedMemorySize, PIPE_SMEM);
        inited = true;
    }

    convert_mask<<<32,256>>>(mask);

    // fork G-softmax chain onto s2 (needs only g_mf)
    cudaEventRecord(evFork, 0);
    cudaStreamWaitEvent(s2, evFork, 0);
    softmax_g<<<1024,256,0,s2>>>(G);
    reduce_g<<<8,256,0,s2>>>();

    // main chain
    split_all<<<(NXS4 + 4*NWS4)/256,256>>>((const float4*)x, (const float4*)Wq,
                                           (const float4*)Wk, (const float4*)Wv,
                                           (const float4*)Wo);
    qkv_gemm<<<dim3(4,64,3),256,PIPE_SMEM>>>();
    cudaEventRecord(evQKV, 0);

    // s2: GAV mainloop overlaps with attention (needs act + vt only)
    cudaStreamWaitEvent(s2, evQKV, 0);
    gav_gemm<<<dim3(4,8,Bz),256,PIPE_SMEM,s2>>>();
    cudaEventRecord(evJoin, s2);

    attn_mma<<<dim3(8,Hz,Bz),512,AT_SMEM>>>();

    // join: GAV + gs ready; U/Spart ready on main
    cudaStreamWaitEvent(0, evJoin, 0);
    reduce_s_rowscales<<<8,256>>>();
    prep_out<<<(Bz*Lz*Ez/4 + 255)/256,256>>>();
    out_gemm<<<dim3(4,64),256,PIPE_SMEM>>>(out);
}

// round 14
// speedup vs baseline: 3.0677x; 1.0693x over previous
#include <cuda_runtime.h>
#include <cuda_bf16.h>
#include <float.h>
#include <stdint.h>

#define Bz   8
#define Lz   1024
#define Ez   512
#define Hz   8
#define Dz   64

// ---------------- fast-math helpers ----------------
__device__ __forceinline__ float tanh_fast(float x) {
    float y; asm("tanh.approx.f32 %0, %1;" : "=f"(y) : "f"(x)); return y;
}
__device__ __forceinline__ float ex2f(float x) {
    float y; asm("ex2.approx.f32 %0, %1;" : "=f"(y) : "f"(x)); return y;
}
#define L2E 1.4426950408889634f

__device__ __forceinline__ uint32_t smem_u32(const void* p) {
    uint32_t a;
    asm("{ .reg .u64 t; cvta.to.shared.u64 t, %1; cvt.u32.u64 %0, t; }" : "=r"(a) : "l"(p));
    return a;
}
__device__ __forceinline__ uint32_t pk2f(float lo, float hi) {
    uint32_t r; asm("cvt.rn.bf16x2.f32 %0, %1, %2;" : "=r"(r) : "f"(hi), "f"(lo)); return r;
}
__device__ __forceinline__ float bflo(uint32_t v) { return __uint_as_float(v << 16); }
__device__ __forceinline__ float bfhi(uint32_t v) { return __uint_as_float(v & 0xFFFF0000u); }

// ---------------- mma.sync / cp.async helpers ----------------
__device__ __forceinline__ void ldmat4(uint32_t* r, uint32_t a) {
    asm volatile("ldmatrix.sync.aligned.m8n8.x4.shared.b16 {%0,%1,%2,%3}, [%4];"
                 : "=r"(r[0]), "=r"(r[1]), "=r"(r[2]), "=r"(r[3]) : "r"(a));
}
__device__ __forceinline__ void mma_bf16(float* c, const uint32_t* a, uint32_t b0, uint32_t b1) {
    asm volatile("mma.sync.aligned.m16n8k16.row.col.f32.bf16.bf16.f32 "
                 "{%0,%1,%2,%3}, {%4,%5,%6,%7}, {%8,%9}, {%0,%1,%2,%3};"
                 : "+f"(c[0]), "+f"(c[1]), "+f"(c[2]), "+f"(c[3])
                 : "r"(a[0]), "r"(a[1]), "r"(a[2]), "r"(a[3]), "r"(b0), "r"(b1));
}
__device__ __forceinline__ void cp16(uint32_t s, const void* g) {
    asm volatile("cp.async.cg.shared.global [%0], [%1], 16;" :: "r"(s), "l"(g));
}
__device__ __forceinline__ void cp_commit() { asm volatile("cp.async.commit_group;"); }
template<int N> __device__ __forceinline__ void cp_wait() {
    asm volatile("cp.async.wait_group %0;" :: "n"(N));
}

// ---------------- device scratch ----------------
__device__ float g_mf[Bz*Lz];
__device__ float g_U [Bz*Lz*Ez];
__device__ float g_GAV[Bz*Lz*Ez];
__device__ float g_Spart[Bz*Hz*8];
__device__ float g_Gpart[Bz*Lz];
__device__ float g_gs[Bz];
__device__ float g_rs0[Bz*Lz];
__device__ float g_rs1[Bz*Lz];

__device__ __nv_bfloat16 g_xhi[Bz*Lz*Ez], g_xlo[Bz*Lz*Ez];
__device__ __nv_bfloat16 g_qhi[Bz*Lz*Ez];
__device__ __nv_bfloat16 g_khi[Bz*Lz*Ez];
__device__ __nv_bfloat16 g_wqhi[Ez*Ez], g_wqlo[Ez*Ez];
__device__ __nv_bfloat16 g_wkhi[Ez*Ez], g_wklo[Ez*Ez];
__device__ __nv_bfloat16 g_wvhi[Ez*Ez], g_wvlo[Ez*Ez];
__device__ __nv_bfloat16 g_wohi[Ez*Ez], g_wolo[Ez*Ez];
__device__ __nv_bfloat16 g_acthi[Lz*Lz], g_actlo[Lz*Lz];
__device__ __nv_bfloat16 g_vthi[Bz*Ez*Lz], g_vtlo[Bz*Ez*Lz];
__device__ __nv_bfloat16 g_aohi[Bz*Lz*Ez], g_aolo[Bz*Lz*Ez];

// ---------------- mask convert (detection fused, per-block) ----------------
__global__ void convert_mask(const void* mv) {
    __shared__ int skind;
    const unsigned char* m = (const unsigned char*)mv;
    if (threadIdx.x == 0) {
        bool isInt32 = true;
        for (int i = 0; i < 64; i++) {
            if (m[4*i] > 1) isInt32 = false;
            if (m[4*i+1] | m[4*i+2] | m[4*i+3]) isInt32 = false;
        }
        int kind;
        if (isInt32) kind = 0;
        else {
            const unsigned int* w = (const unsigned int*)m;
            bool isFloat = true;
            for (int i = 0; i < 64; i++) {
                unsigned v = w[i];
                if (v != 0u && v != 0x3F800000u) isFloat = false;
            }
            kind = isFloat ? 2 : 1;
        }
        skind = kind;
    }
    __syncthreads();
    int i = blockIdx.x*256 + threadIdx.x;
    if (i >= Bz*Lz) return;
    int k = skind;
    float v;
    if (k == 0)      v = ((const int*)mv)[i] ? 1.f : 0.f;
    else if (k == 1) v = m[i] ? 1.f : 0.f;
    else             v = ((const float*)mv)[i];
    g_mf[i] = v;
}

// ---------------- splits: x + 4 weights -> hi/lo (float4 vectorized) ----------------
#define NXS4 (Bz*Lz*Ez/4)
#define NWS4 (Ez*Ez/4)
__global__ void split_all(const float4* __restrict__ x,
                          const float4* __restrict__ wq, const float4* __restrict__ wk,
                          const float4* __restrict__ wv, const float4* __restrict__ wo) {
    int i = blockIdx.x*256 + threadIdx.x;
    const float4* s; uint2 *hp, *lp; int idx;
    if (i < NXS4) { s = x; hp = (uint2*)g_xhi; lp = (uint2*)g_xlo; idx = i; }
    else {
        int j = i - NXS4;
        int w = j >> 16;
        idx = j & (NWS4-1);
        if      (w == 0) { s = wq; hp = (uint2*)g_wqhi; lp = (uint2*)g_wqlo; }
        else if (w == 1) { s = wk; hp = (uint2*)g_wkhi; lp = (uint2*)g_wklo; }
        else if (w == 2) { s = wv; hp = (uint2*)g_wvhi; lp = (uint2*)g_wvlo; }
        else             { s = wo; hp = (uint2*)g_wohi; lp = (uint2*)g_wolo; }
    }
    float4 v = s[idx];
    uint32_t h01 = pk2f(v.x, v.y), h23 = pk2f(v.z, v.w);
    uint32_t l01 = pk2f(v.x - bflo(h01), v.y - bfhi(h01));
    uint32_t l23 = pk2f(v.z - bflo(h23), v.w - bfhi(h23));
    hp[idx] = make_uint2(h01, h23);
    lp[idx] = make_uint2(l01, l23);
}

// ---------------- softmax of G rows -> bf16 hi/lo + fused gsum partials ----------------
__global__ __launch_bounds__(256) void softmax_g(const float* __restrict__ G) {
    int q = blockIdx.x, t = threadIdx.x;
    const float* row = G + (size_t)q*Lz;
    __shared__ float red[256];
    __shared__ float part[8][8];
    float mx = -FLT_MAX;
    for (int k = t; k < Lz; k += 256) mx = fmaxf(mx, row[k]);
    red[t] = mx; __syncthreads();
    for (int s = 128; s > 0; s >>= 1) { if (t < s) red[t] = fmaxf(red[t], red[t+s]); __syncthreads(); }
    mx = red[0]; __syncthreads();
    float vals[4]; float sum = 0.f;
    for (int k = t, j = 0; k < Lz; k += 256, j++) { float e = __expf(row[k]-mx); vals[j] = e; sum += e; }
    red[t] = sum; __syncthreads();
    for (int s = 128; s > 0; s >>= 1) { if (t < s) red[t] += red[t+s]; __syncthreads(); }
    float inv = 1.f / red[0];
    float gs[8] = {};
    for (int k = t, j = 0; k < Lz; k += 256, j++) {
        float v = vals[j]*inv;
        __nv_bfloat16 h = __float2bfloat16(v);
        g_acthi[(size_t)q*Lz + k] = h;
        g_actlo[(size_t)q*Lz + k] = __float2bfloat16(v - __bfloat162float(h));
        #pragma unroll
        for (int b2 = 0; b2 < 8; b2++) gs[b2] += v * __ldg(g_mf + b2*Lz + k);
    }
    #pragma unroll
    for (int o = 16; o; o >>= 1)
        #pragma unroll
        for (int b2 = 0; b2 < 8; b2++) gs[b2] += __shfl_down_sync(0xffffffffu, gs[b2], o);
    if ((t & 31) == 0)
        #pragma unroll
        for (int b2 = 0; b2 < 8; b2++) part[t>>5][b2] = gs[b2];
    __syncthreads();
    if (t < 8) {
        float r = 0.f;
        #pragma unroll
        for (int w = 0; w < 8; w++) r += part[w][t];
        g_Gpart[t*Lz + q] = r * __ldg(g_mf + t*Lz + q);
    }
}

__global__ __launch_bounds__(256) void reduce_g() {
    int b = blockIdx.x, t = threadIdx.x;
    __shared__ float red[256];
    float s = 0.f;
    for (int i = t; i < Lz; i += 256) s += g_Gpart[b*Lz + i];
    red[t] = s; __syncthreads();
    for (int st = 128; st > 0; st >>= 1) { if (t < st) red[t] += red[t+st]; __syncthreads(); }
    if (t == 0) g_gs[b] = red[0];
}

__global__ __launch_bounds__(256) void reduce_s_rowscales() {
    int b = blockIdx.x, t = threadIdx.x;
    __shared__ float red[256];
    float s = 0.f;
    for (int i = t; i < Hz*8; i += 256) s += g_Spart[b*Hz*8 + i];
    red[t] = s; __syncthreads();
    for (int st = 128; st > 0; st >>= 1) { if (t < st) red[t] += red[t+st]; __syncthreads(); }
    __syncthreads();
    const float TINY = 1.175494351e-38f;
    float Sv  = fmaxf(red[0], TINY);
    float gsv = fmaxf(g_gs[b], TINY);
    float i0 = 0.5f / Sv, i1 = 0.5f / gsv;
    for (int i = t; i < Lz; i += 256) {
        float mf = g_mf[b*Lz + i];
        g_rs0[b*Lz + i] = mf * i0;
        g_rs1[b*Lz + i] = mf * i1;
    }
}

// aout = rs0*U + rs1*GAV -> bf16 hi/lo (float4 vectorized)
__global__ void prep_out() {
    int i = blockIdx.x*256 + threadIdx.x;
    if (i >= Bz*Lz*Ez/4) return;
    int row = i >> 7;
    float rs0 = g_rs0[row], rs1 = g_rs1[row];
    float4 u = ((const float4*)g_U)[i];
    float4 g = ((const float4*)g_GAV)[i];
    float v0 = rs0*u.x + rs1*g.x;
    float v1 = rs0*u.y + rs1*g.y;
    float v2 = rs0*u.z + rs1*g.z;
    float v3 = rs0*u.w + rs1*g.w;
    uint32_t h01 = pk2f(v0, v1), h23 = pk2f(v2, v3);
    uint32_t l01 = pk2f(v0 - bflo(h01), v1 - bfhi(h01));
    uint32_t l23 = pk2f(v2 - bflo(h23), v3 - bfhi(h23));
    ((uint2*)g_aohi)[i] = make_uint2(h01, h23);
    ((uint2*)g_aolo)[i] = make_uint2(l01, l23);
}

// ---------------- pipelined HMMA GEMM mainloop (3-product) ----------------
#define T_ALO 10240
#define T_BHI 20480
#define T_BLO 30720
#define BUFSZ 40960
#define PIPE_SMEM (2*BUFSZ)

__device__ __forceinline__ void gemm_main(
    char* smc, uint32_t sb,
    const __nv_bfloat16* Ahi, const __nv_bfloat16* Alo,
    const __nv_bfloat16* Bhi, const __nv_bfloat16* Blo,
    int K, int bm, int bn, float acc[4][4][4])
{
    int tid = threadIdx.x, lane = tid & 31, wid = tid >> 5;
    int wm = wid & 1, wn = wid >> 1;
    const char* pAh = (const char*)(Ahi + (size_t)bm*K);
    const char* pAl = (const char*)(Alo + (size_t)bm*K);
    const char* pBh = (const char*)(Bhi + (size_t)bn*K);
    const char* pBl = (const char*)(Blo + (size_t)bn*K);

    uint32_t aRow = wm*64 + (lane & 15);
    uint32_t aK8  = (lane >> 4) * 8;
    uint32_t bRow = wn*32 + (lane & 7) + ((lane >> 4) << 3);
    uint32_t bK8  = ((lane >> 3) & 1) * 8;

    int nChunks = K >> 5;

    auto load_chunk = [&](int kc, int bsel) {
        uint32_t base = sb + bsel*BUFSZ;
        #pragma unroll
        for (int i = tid; i < 512; i += 256) {
            int r = i >> 2, c = i & 3;
            size_t go = (size_t)r*K*2 + (size_t)kc*64 + c*16;
            uint32_t so = r*80 + c*16;
            cp16(base + so,          pAh + go);
            cp16(base + T_ALO + so,  pAl + go);
            cp16(base + T_BHI + so,  pBh + go);
            cp16(base + T_BLO + so,  pBl + go);
        }
        cp_commit();
    };

    load_chunk(0, 0);

    for (int kc = 0; kc < nChunks; kc++) {
        __syncthreads();
        if (kc + 1 < nChunks) { load_chunk(kc+1, (kc+1)&1); cp_wait<1>(); }
        else                  { cp_wait<0>(); }
        __syncthreads();
        uint32_t bofs = sb + (kc&1)*BUFSZ;
        #pragma unroll
        for (int ks = 0; ks < 2; ks++) {
            uint32_t ah[4][4], al[4][4], bh[2][4], bl[2][4];
            #pragma unroll
            for (int mi = 0; mi < 4; mi++) {
                uint32_t ad = bofs + ((aRow + mi*16)*40 + ks*16 + aK8)*2;
                ldmat4(ah[mi], ad);
                ldmat4(al[mi], ad + T_ALO);
            }
            #pragma unroll
            for (int bj = 0; bj < 2; bj++) {
                uint32_t ad = bofs + T_BHI + ((bRow + bj*16)*40 + ks*16 + bK8)*2;
                ldmat4(bh[bj], ad);
                ldmat4(bl[bj], ad + (T_BLO - T_BHI));
            }
            #pragma unroll
            for (int mi = 0; mi < 4; mi++)
                #pragma unroll
                for (int nj = 0; nj < 4; nj++) {
                    int bj = nj >> 1, pr = (nj & 1)*2;
                    mma_bf16(acc[mi][nj], ah[mi], bh[bj][pr], bh[bj][pr+1]);
                    mma_bf16(acc[mi][nj], ah[mi], bl[bj][pr], bl[bj][pr+1]);
                    mma_bf16(acc[mi][nj], al[mi], bh[bj][pr], bh[bj][pr+1]);
                }
        }
    }
}

// fused QKV (3-product): z=0 -> Q (bf16 hi), z=1 -> K (bf16 hi), z=2 -> masked+transposed V split
__global__ __launch_bounds__(256, 1) void qkv_gemm() {
    extern __shared__ char smc[];
    uint32_t sb = smem_u32(smc);
    int z = blockIdx.z;
    int bm = blockIdx.y*128, bn = blockIdx.x*128;
    const __nv_bfloat16 *Bh, *Bl;
    if      (z == 0) { Bh = g_wqhi; Bl = g_wqlo; }
    else if (z == 1) { Bh = g_wkhi; Bl = g_wklo; }
    else             { Bh = g_wvhi; Bl = g_wvlo; }
    float acc[4][4][4] = {};
    gemm_main(smc, sb, g_xhi, g_xlo, Bh, Bl, Ez, bm, bn, acc);

    int lane = threadIdx.x & 31, wid = threadIdx.x >> 5;
    int wm = wid & 1, wn = wid >> 1;
    int r0l = wm*64 + (lane >> 2);
    int c0l = wn*32 + (lane & 3)*2;

    if (z < 2) {
        __nv_bfloat16* Ch = (z == 0) ? g_qhi : g_khi;
        #pragma unroll
        for (int mi = 0; mi < 4; mi++)
            #pragma unroll
            for (int nj = 0; nj < 4; nj++) {
                int r = bm + r0l + mi*16, c = bn + c0l + nj*8;
                *(uint32_t*)(Ch + (size_t)r*Ez + c)     = pk2f(acc[mi][nj][0], acc[mi][nj][1]);
                *(uint32_t*)(Ch + (size_t)(r+8)*Ez + c) = pk2f(acc[mi][nj][2], acc[mi][nj][3]);
            }
    } else {
        __syncthreads();
        #pragma unroll
        for (int mi = 0; mi < 4; mi++) {
            int r = r0l + mi*16;
            float m0 = g_mf[bm + r], m1 = g_mf[bm + r + 8];
            #pragma unroll
            for (int nj = 0; nj < 4; nj++) {
                int c = c0l + nj*8;
                #pragma unroll
                for (int e2 = 0; e2 < 2; e2++) {
                    float v0 = acc[mi][nj][e2]   * m0;
                    float v1 = acc[mi][nj][2+e2] * m1;
                    __nv_bfloat16 h0 = __float2bfloat16(v0);
                    __nv_bfloat16 h1 = __float2bfloat16(v1);
                    __nv_bfloat16 l0 = __float2bfloat16(v0 - __bfloat162float(h0));
                    __nv_bfloat16 l1 = __float2bfloat16(v1 - __bfloat162float(h1));
                    uint32_t o0 = (c+e2)*272 + r*2;
                    uint32_t o1 = (c+e2)*272 + (r+8)*2;
                    *(__nv_bfloat16*)(smc + o0) = h0;
                    *(__nv_bfloat16*)(smc + o1) = h1;
                    *(__nv_bfloat16*)(smc + BUFSZ + o0) = l0;
                    *(__nv_bfloat16*)(smc + BUFSZ + o1) = l1;
                }
            }
        }
        __syncthreads();
        int b = bm >> 10;
        int l0g = bm & 1023;
        for (int i = threadIdx.x; i < 2048; i += 256) {
            int e = i >> 4, l8 = (i & 15)*8;
            size_t go = ((size_t)b*Ez + bn + e)*Lz + l0g + l8;
            *(uint4*)(g_vthi + go) = *(const uint4*)(smc + e*272 + l8*2);
            *(uint4*)(g_vtlo + go) = *(const uint4*)(smc + BUFSZ + e*272 + l8*2);
        }
    }
}

// GAV plain GEMM (3-product, fp32 out) — on stream2 concurrent with attention
__global__ __launch_bounds__(256, 1) void gav_gemm() {
    extern __shared__ char smc[];
    uint32_t sb = smem_u32(smc);
    int z = blockIdx.z;
    int bm = blockIdx.y*128, bn = blockIdx.x*128;
    float acc[4][4][4] = {};
    gemm_main(smc, sb, g_acthi, g_actlo,
              g_vthi + (size_t)z*Ez*Lz, g_vtlo + (size_t)z*Ez*Lz,
              Lz, bm, bn, acc);

    int lane = threadIdx.x & 31, wid = threadIdx.x >> 5;
    int wm = wid & 1, wn = wid >> 1;
    int r0 = bm + wm*64 + (lane >> 2);
    int c0 = bn + wn*32 + (lane & 3)*2;
    float* Cp = g_GAV + (size_t)z*Lz*Ez;
    #pragma unroll
    for (int mi = 0; mi < 4; mi++)
        #pragma unroll
        for (int nj = 0; nj < 4; nj++) {
            float* p = Cp + (size_t)(r0 + mi*16)*Ez + c0 + nj*8;
            *(float2*)p                  = make_float2(acc[mi][nj][0], acc[mi][nj][1]);
            *(float2*)(p + (size_t)8*Ez) = make_float2(acc[mi][nj][2], acc[mi][nj][3]);
        }
}

// out = Aout @ Wo^T (3-product, fp32 epilogue)
__global__ __launch_bounds__(256, 1) void out_gemm(float* __restrict__ C) {
    extern __shared__ char smc[];
    uint32_t sb = smem_u32(smc);
    int bm = blockIdx.y*128, bn = blockIdx.x*128;
    float acc[4][4][4] = {};
    gemm_main(smc, sb, g_aohi, g_aolo, g_wohi, g_wolo, Ez, bm, bn, acc);

    int lane = threadIdx.x & 31, wid = threadIdx.x >> 5;
    int wm = wid & 1, wn = wid >> 1;
    int r0 = bm + wm*64 + (lane >> 2);
    int c0 = bn + wn*32 + (lane & 3)*2;
    #pragma unroll
    for (int mi = 0; mi < 4; mi++)
        #pragma unroll
        for (int nj = 0; nj < 4; nj++) {
            float* p = C + (size_t)(r0 + mi*16)*Ez + c0 + nj*8;
            *(float2*)p                  = make_float2(acc[mi][nj][0], acc[mi][nj][1]);
            *(float2*)(p + (size_t)8*Ez) = make_float2(acc[mi][nj][2], acc[mi][nj][3]);
        }
}

// ---------------- attention: S = Qhi Khi^T (1-product), PV 3-product ----------------
#define A_QHI 0
#define A_K0  36864
#define A_KBUF 18432
#define A_VHI 110592
#define A_VLO 128000
#define A_PHI 145408
#define A_PLO 180224
#define A_MQ  215040
#define A_MK  215552
#define A_RED 216576
#define AT_SMEM (216576 + 2048)

__global__ __launch_bounds__(512, 1) void attn_mma() {
    extern __shared__ char smc[];
    uint32_t sb = smem_u32(smc);
    float* mqf = (float*)(smc + A_MQ);
    float* red = (float*)(smc + A_RED);

    int tid = threadIdx.x, lane = tid & 31, wid = tid >> 5;
    int qt = blockIdx.x, h = blockIdx.y, b = blockIdx.z;

    int wm = wid & 3, wn = wid >> 2;
    int wq = wid & 7, wd = wid >> 3;

    const __nv_bfloat16* Qh = g_qhi + ((size_t)(b*Lz + qt*128))*Ez + h*64;
    const __nv_bfloat16* Kh = g_khi + ((size_t)(b*Lz))*Ez + h*64;
    const __nv_bfloat16* Vth = g_vthi + ((size_t)(b*Ez + h*64))*Lz;
    const __nv_bfloat16* Vtl = g_vtlo + ((size_t)(b*Ez + h*64))*Lz;

    auto issue_K = [&](int kt, int bsel) {
        uint32_t base = sb + A_K0 + bsel*A_KBUF;
        #pragma unroll
        for (int i = tid; i < 1024; i += 512) {
            int r = i >> 3, c8 = (i & 7)*8;
            cp16(base + r*144 + c8*2, Kh + (size_t)(kt*128 + r)*Ez + c8);
        }
        if (tid < 32) cp16(sb + A_MK + bsel*512 + tid*16, g_mf + b*Lz + kt*128 + tid*4);
        cp_commit();
    };
    auto issue_V = [&](int kt) {
        #pragma unroll
        for (int i = tid; i < 1024; i += 512) {
            int r = i >> 4, c8 = (i & 15)*8;
            uint32_t off = r*272 + c8*2;
            cp16(sb + A_VHI + off, Vth + (size_t)r*Lz + kt*128 + c8);
            cp16(sb + A_VLO + off, Vtl + (size_t)r*Lz + kt*128 + c8);
        }
        cp_commit();
    };

    // Q hi only
    for (int i = tid; i < 1024; i += 512) {
        int r = i >> 3, c8 = (i & 7)*8;
        *(uint4*)(smc + A_QHI + r*144 + c8*2) = *(const uint4*)(Qh + (size_t)r*Ez + c8);
    }
    if (tid < 128) mqf[tid] = g_mf[b*Lz + qt*128 + tid];

    issue_K(0, 0);
    issue_V(0);

    uint32_t qRow = wm*32 + (lane & 15);
    uint32_t qK8  = (lane >> 4)*8;
    uint32_t kRowB = wn*32 + (lane & 7) + ((lane >> 4) << 3);
    uint32_t kK8  = ((lane >> 3) & 1)*8;
    uint32_t pRow = wq*16 + (lane & 15);
    uint32_t pK8  = (lane >> 4)*8;
    uint32_t vRowB = wd*32 + (lane & 7) + ((lane >> 4) << 3);
    uint32_t vK8  = ((lane >> 3) & 1)*8;

    float U[4][4] = {};
    float partial = 0.f;

    cp_wait<0>();
    __syncthreads();

    for (int kt = 0; kt < 8; kt++) {
        if (kt + 1 < 8) issue_K(kt+1, (kt+1)&1);

        uint32_t kbase = sb + A_K0 + (kt&1)*A_KBUF;
        const float* mkf = (const float*)(smc + A_MK + (kt&1)*512);

        // ---- S = Qhi Khi^T (single product) ----
        float S[2][4][4] = {};
        #pragma unroll
        for (int ks = 0; ks < 4; ks++) {
            uint32_t ah[2][4], bh[2][4];
            #pragma unroll
            for (int mi = 0; mi < 2; mi++) {
                uint32_t ad = sb + A_QHI + (qRow + mi*16)*144 + (ks*16 + qK8)*2;
                ldmat4(ah[mi], ad);
            }
            #pragma unroll
            for (int nb = 0; nb < 2; nb++) {
                uint32_t ad = kbase + (kRowB + nb*16)*144 + (ks*16 + kK8)*2;
                ldmat4(bh[nb], ad);
            }
            #pragma unroll
            for (int mi = 0; mi < 2; mi++)
                #pragma unroll
                for (int nj = 0; nj < 4; nj++) {
                    int nb = nj >> 1, pr = (nj & 1)*2;
                    mma_bf16(S[mi][nj], ah[mi], bh[nb][pr], bh[nb][pr+1]);
                }
        }

        {
            int r0 = wm*32 + (lane >> 2);
            int c0b = wn*32 + (lane & 3)*2;
            #pragma unroll
            for (int mi = 0; mi < 2; mi++) {
                int row0 = r0 + mi*16, row1 = row0 + 8;
                float mq0 = mqf[row0], mq1 = mqf[row1];
                #pragma unroll
                for (int nj = 0; nj < 4; nj++) {
                    int c0 = c0b + nj*8;
                    float mk0 = mkf[c0], mk1 = mkf[c0+1];
                    float p0 = ex2f(tanh_fast(S[mi][nj][0]*0.125f)*L2E)*mk0;
                    float p1 = ex2f(tanh_fast(S[mi][nj][1]*0.125f)*L2E)*mk1;
                    float p2 = ex2f(tanh_fast(S[mi][nj][2]*0.125f)*L2E)*mk0;
                    float p3 = ex2f(tanh_fast(S[mi][nj][3]*0.125f)*L2E)*mk1;
                    partial += mq0*(p0+p1) + mq1*(p2+p3);
                    uint32_t h01 = pk2f(p0, p1), h23 = pk2f(p2, p3);
                    uint32_t l01 = pk2f(p0 - bflo(h01), p1 - bfhi(h01));
                    uint32_t l23 = pk2f(p2 - bflo(h23), p3 - bfhi(h23));
                    uint32_t o0 = row0*272 + c0*2, o1 = row1*272 + c0*2;
                    *(uint32_t*)(smc + A_PHI + o0) = h01;
                    *(uint32_t*)(smc + A_PHI + o1) = h23;
                    *(uint32_t*)(smc + A_PLO + o0) = l01;
                    *(uint32_t*)(smc + A_PLO + o1) = l23;
                }
            }
        }
        __syncthreads();
        if (kt < 7) cp_wait<1>();
        else        cp_wait<0>();

        #pragma unroll
        for (int ch = 0; ch < 8; ch++) {
            uint32_t ph[4], pl[4];
            uint32_t pa = sb + A_PHI + pRow*272 + (ch*16 + pK8)*2;
            ldmat4(ph, pa);
            ldmat4(pl, pa + (A_PLO - A_PHI));
            #pragma unroll
            for (int g = 0; g < 2; g++) {
                uint32_t vh[4], vl[4];
                uint32_t va = sb + A_VHI + (vRowB + g*16)*272 + (ch*16 + vK8)*2;
                ldmat4(vh, va);
                ldmat4(vl, va + (A_VLO - A_VHI));
                mma_bf16(U[g*2],   ph, vh[0], vh[1]);
                mma_bf16(U[g*2],   ph, vl[0], vl[1]);
                mma_bf16(U[g*2],   pl, vh[0], vh[1]);
                mma_bf16(U[g*2+1], ph, vh[2], vh[3]);
                mma_bf16(U[g*2+1], ph, vl[2], vl[3]);
                mma_bf16(U[g*2+1], pl, vh[2], vh[3]);
            }
        }
        __syncthreads();
        if (kt + 1 < 8) {
            issue_V(kt+1);
            cp_wait<1>();
            __syncthreads();
        }
    }

    {
        int r = wq*16 + (lane >> 2);
        int cb = wd*32 + (lane & 3)*2;
        float* Ug = g_U + ((size_t)(b*Lz + qt*128))*Ez + h*64;
        #pragma unroll
        for (int dj = 0; dj < 4; dj++) {
            int c = cb + dj*8;
            *(float2*)(Ug + (size_t)r*Ez + c)     = make_float2(U[dj][0], U[dj][1]);
            *(float2*)(Ug + (size_t)(r+8)*Ez + c) = make_float2(U[dj][2], U[dj][3]);
        }
    }

    red[tid] = partial; __syncthreads();
    for (int s = 256; s > 0; s >>= 1) { if (tid < s) red[tid] += red[tid+s]; __syncthreads(); }
    if (tid == 0) g_Spart[(b*Hz + h)*8 + qt] = red[0];
}

// ---------------- host launcher ----------------
extern "C" void kernel_launch(void* const* d_in, const int* in_sizes, int n_in,
                              void* d_out, int out_size) {
    const float* x    = (const float*)d_in[0];
    const void*  mask = d_in[1];
    const float* Wq   = (const float*)d_in[2];
    const float* Wk   = (const float*)d_in[3];
    const float* Wv   = (const float*)d_in[4];
    const float* Wo   = (const float*)d_in[5];
    const float* G    = (const float*)d_in[6];
    float* out = (float*)d_out;

    static bool inited = false;
    static cudaStream_t s2;
    static cudaEvent_t evFork, evQKV, evJoin;
    if (!inited) {
        cudaStreamCreateWithFlags(&s2, cudaStreamNonBlocking);
        cudaEventCreateWithFlags(&evFork, cudaEventDisableTiming);
        cudaEventCreateWithFlags(&evQKV, cudaEventDisableTiming);
        cudaEventCreateWithFlags(&evJoin, cudaEventDisableTiming);
        cudaFuncSetAttribute((const void*)attn_mma,
                             cudaFuncAttributeMaxDynamicSharedMemorySize, AT_SMEM);
        cudaFuncSetAttribute((const void*)qkv_gemm,
                             cudaFuncAttributeMaxDynamicSharedMemorySize, PIPE_SMEM);
        cudaFuncSetAttribute((const void*)gav_gemm,
                             cudaFuncAttributeMaxDynamicSharedMemorySize, PIPE_SMEM);
        cudaFuncSetAttribute((const void*)out_gemm,
                             cudaFuncAttributeMaxDynamicSharedMemorySize, PIPE_SMEM);
        inited = true;
    }

    convert_mask<<<32,256>>>(mask);

    // fork G-softmax chain onto s2 (needs only g_mf)
    cudaEventRecord(evFork, 0);
    cudaStreamWaitEvent(s2, evFork, 0);
    softmax_g<<<1024,256,0,s2>>>(G);
    reduce_g<<<8,256,0,s2>>>();

    // main chain
    split_all<<<(NXS4 + 4*NWS4)/256,256>>>((const float4*)x, (const float4*)Wq,
                                           (const float4*)Wk, (const float4*)Wv,
                                           (const float4*)Wo);
    qkv_gemm<<<dim3(4,64,3),256,PIPE_SMEM>>>();
    cudaEventRecord(evQKV, 0);

    // s2: GAV mainloop overlaps with attention
    cudaStreamWaitEvent(s2, evQKV, 0);
    gav_gemm<<<dim3(4,8,Bz),256,PIPE_SMEM,s2>>>();
    cudaEventRecord(evJoin, s2);

    attn_mma<<<dim3(8,Hz,Bz),512,AT_SMEM>>>();

    cudaStreamWaitEvent(0, evJoin, 0);
    reduce_s_rowscales<<<8,256>>>();
    prep_out<<<(Bz*Lz*Ez/4 + 255)/256,256>>>();
    out_gemm<<<dim3(4,64),256,PIPE_SMEM>>>(out);
}

// round 15
// speedup vs baseline: 3.3172x; 1.0813x over previous
#include <cuda_runtime.h>
#include <cuda_bf16.h>
#include <float.h>
#include <stdint.h>

#define Bz   8
#define Lz   1024
#define Ez   512
#define Hz   8
#define Dz   64

// ---------------- fast-math helpers ----------------
__device__ __forceinline__ float tanh_fast(float x) {
    float y; asm("tanh.approx.f32 %0, %1;" : "=f"(y) : "f"(x)); return y;
}
__device__ __forceinline__ float ex2f(float x) {
    float y; asm("ex2.approx.f32 %0, %1;" : "=f"(y) : "f"(x)); return y;
}
#define L2E 1.4426950408889634f

__device__ __forceinline__ uint32_t smem_u32(const void* p) {
    uint32_t a;
    asm("{ .reg .u64 t; cvta.to.shared.u64 t, %1; cvt.u32.u64 %0, t; }" : "=r"(a) : "l"(p));
    return a;
}
__device__ __forceinline__ uint32_t pk2f(float lo, float hi) {
    uint32_t r; asm("cvt.rn.bf16x2.f32 %0, %1, %2;" : "=r"(r) : "f"(hi), "f"(lo)); return r;
}
__device__ __forceinline__ float bflo(uint32_t v) { return __uint_as_float(v << 16); }
__device__ __forceinline__ float bfhi(uint32_t v) { return __uint_as_float(v & 0xFFFF0000u); }

// ---------------- mma.sync / cp.async helpers ----------------
__device__ __forceinline__ void ldmat4(uint32_t* r, uint32_t a) {
    asm volatile("ldmatrix.sync.aligned.m8n8.x4.shared.b16 {%0,%1,%2,%3}, [%4];"
                 : "=r"(r[0]), "=r"(r[1]), "=r"(r[2]), "=r"(r[3]) : "r"(a));
}
__device__ __forceinline__ void mma_bf16(float* c, const uint32_t* a, uint32_t b0, uint32_t b1) {
    asm volatile("mma.sync.aligned.m16n8k16.row.col.f32.bf16.bf16.f32 "
                 "{%0,%1,%2,%3}, {%4,%5,%6,%7}, {%8,%9}, {%0,%1,%2,%3};"
                 : "+f"(c[0]), "+f"(c[1]), "+f"(c[2]), "+f"(c[3])
                 : "r"(a[0]), "r"(a[1]), "r"(a[2]), "r"(a[3]), "r"(b0), "r"(b1));
}
__device__ __forceinline__ void cp16(uint32_t s, const void* g) {
    asm volatile("cp.async.cg.shared.global [%0], [%1], 16;" :: "r"(s), "l"(g));
}
__device__ __forceinline__ void cp_commit() { asm volatile("cp.async.commit_group;"); }
template<int N> __device__ __forceinline__ void cp_wait() {
    asm volatile("cp.async.wait_group %0;" :: "n"(N));
}

// ---------------- device scratch ----------------
__device__ float g_mf[Bz*Lz];
__device__ float g_U [Bz*Lz*Ez];
__device__ float g_GAV[Bz*Lz*Ez];
__device__ float g_Spart[Bz*Hz*8];
__device__ float g_Gpart[Bz*Lz];
__device__ float g_gs[Bz];
__device__ float g_S[Bz];

__device__ __nv_bfloat16 g_xhi[Bz*Lz*Ez], g_xlo[Bz*Lz*Ez];
__device__ __nv_bfloat16 g_qhi[Bz*Lz*Ez];
__device__ __nv_bfloat16 g_khi[Bz*Lz*Ez];
__device__ __nv_bfloat16 g_wqhi[Ez*Ez], g_wqlo[Ez*Ez];
__device__ __nv_bfloat16 g_wkhi[Ez*Ez], g_wklo[Ez*Ez];
__device__ __nv_bfloat16 g_wvhi[Ez*Ez], g_wvlo[Ez*Ez];
__device__ __nv_bfloat16 g_wohi[Ez*Ez], g_wolo[Ez*Ez];
__device__ __nv_bfloat16 g_acthi[Lz*Lz], g_actlo[Lz*Lz];
__device__ __nv_bfloat16 g_vthi[Bz*Ez*Lz], g_vtlo[Bz*Ez*Lz];
__device__ __nv_bfloat16 g_aohi[Bz*Lz*Ez], g_aolo[Bz*Lz*Ez];

// ---------------- mask convert (detection fused, per-block) ----------------
__global__ void convert_mask(const void* mv) {
    __shared__ int skind;
    const unsigned char* m = (const unsigned char*)mv;
    if (threadIdx.x == 0) {
        bool isInt32 = true;
        for (int i = 0; i < 64; i++) {
            if (m[4*i] > 1) isInt32 = false;
            if (m[4*i+1] | m[4*i+2] | m[4*i+3]) isInt32 = false;
        }
        int kind;
        if (isInt32) kind = 0;
        else {
            const unsigned int* w = (const unsigned int*)m;
            bool isFloat = true;
            for (int i = 0; i < 64; i++) {
                unsigned v = w[i];
                if (v != 0u && v != 0x3F800000u) isFloat = false;
            }
            kind = isFloat ? 2 : 1;
        }
        skind = kind;
    }
    __syncthreads();
    int i = blockIdx.x*256 + threadIdx.x;
    if (i >= Bz*Lz) return;
    int k = skind;
    float v;
    if (k == 0)      v = ((const int*)mv)[i] ? 1.f : 0.f;
    else if (k == 1) v = m[i] ? 1.f : 0.f;
    else             v = ((const float*)mv)[i];
    g_mf[i] = v;
}

// ---------------- splits: x + 4 weights -> hi/lo (float4 vectorized) ----------------
#define NXS4 (Bz*Lz*Ez/4)
#define NWS4 (Ez*Ez/4)
__global__ void split_all(const float4* __restrict__ x,
                          const float4* __restrict__ wq, const float4* __restrict__ wk,
                          const float4* __restrict__ wv, const float4* __restrict__ wo) {
    int i = blockIdx.x*256 + threadIdx.x;
    const float4* s; uint2 *hp, *lp; int idx;
    if (i < NXS4) { s = x; hp = (uint2*)g_xhi; lp = (uint2*)g_xlo; idx = i; }
    else {
        int j = i - NXS4;
        int w = j >> 16;
        idx = j & (NWS4-1);
        if      (w == 0) { s = wq; hp = (uint2*)g_wqhi; lp = (uint2*)g_wqlo; }
        else if (w == 1) { s = wk; hp = (uint2*)g_wkhi; lp = (uint2*)g_wklo; }
        else if (w == 2) { s = wv; hp = (uint2*)g_wvhi; lp = (uint2*)g_wvlo; }
        else             { s = wo; hp = (uint2*)g_wohi; lp = (uint2*)g_wolo; }
    }
    float4 v = s[idx];
    uint32_t h01 = pk2f(v.x, v.y), h23 = pk2f(v.z, v.w);
    uint32_t l01 = pk2f(v.x - bflo(h01), v.y - bfhi(h01));
    uint32_t l23 = pk2f(v.z - bflo(h23), v.w - bfhi(h23));
    hp[idx] = make_uint2(h01, h23);
    lp[idx] = make_uint2(l01, l23);
}

// ---------------- softmax of G rows -> bf16 hi/lo + fused gsum partials ----------------
__global__ __launch_bounds__(256) void softmax_g(const float* __restrict__ G) {
    int q = blockIdx.x, t = threadIdx.x;
    const float* row = G + (size_t)q*Lz;
    __shared__ float red[256];
    __shared__ float part[8][8];
    float mx = -FLT_MAX;
    for (int k = t; k < Lz; k += 256) mx = fmaxf(mx, row[k]);
    red[t] = mx; __syncthreads();
    for (int s = 128; s > 0; s >>= 1) { if (t < s) red[t] = fmaxf(red[t], red[t+s]); __syncthreads(); }
    mx = red[0]; __syncthreads();
    float vals[4]; float sum = 0.f;
    for (int k = t, j = 0; k < Lz; k += 256, j++) { float e = __expf(row[k]-mx); vals[j] = e; sum += e; }
    red[t] = sum; __syncthreads();
    for (int s = 128; s > 0; s >>= 1) { if (t < s) red[t] += red[t+s]; __syncthreads(); }
    float inv = 1.f / red[0];
    float gs[8] = {};
    for (int k = t, j = 0; k < Lz; k += 256, j++) {
        float v = vals[j]*inv;
        __nv_bfloat16 h = __float2bfloat16(v);
        g_acthi[(size_t)q*Lz + k] = h;
        g_actlo[(size_t)q*Lz + k] = __float2bfloat16(v - __bfloat162float(h));
        #pragma unroll
        for (int b2 = 0; b2 < 8; b2++) gs[b2] += v * __ldg(g_mf + b2*Lz + k);
    }
    #pragma unroll
    for (int o = 16; o; o >>= 1)
        #pragma unroll
        for (int b2 = 0; b2 < 8; b2++) gs[b2] += __shfl_down_sync(0xffffffffu, gs[b2], o);
    if ((t & 31) == 0)
        #pragma unroll
        for (int b2 = 0; b2 < 8; b2++) part[t>>5][b2] = gs[b2];
    __syncthreads();
    if (t < 8) {
        float r = 0.f;
        #pragma unroll
        for (int w = 0; w < 8; w++) r += part[w][t];
        g_Gpart[t*Lz + q] = r * __ldg(g_mf + t*Lz + q);
    }
}

__global__ __launch_bounds__(256) void reduce_g() {
    int b = blockIdx.x, t = threadIdx.x;
    __shared__ float red[256];
    float s = 0.f;
    for (int i = t; i < Lz; i += 256) s += g_Gpart[b*Lz + i];
    red[t] = s; __syncthreads();
    for (int st = 128; st > 0; st >>= 1) { if (t < st) red[t] += red[t+st]; __syncthreads(); }
    if (t == 0) g_gs[b] = red[0];
}

__global__ __launch_bounds__(64) void reduce_s() {
    int b = blockIdx.x, t = threadIdx.x;
    __shared__ float red[64];
    float s = (t < Hz*8) ? g_Spart[b*Hz*8 + t] : 0.f;
    red[t] = s; __syncthreads();
    for (int st = 32; st > 0; st >>= 1) { if (t < st) red[t] += red[t+st]; __syncthreads(); }
    if (t == 0) g_S[b] = red[0];
}

// aout = (0.5 mf/S)*U + (0.5 mf/gs)*GAV -> bf16 hi/lo (rowscales fused, float4 vectorized)
__global__ void prep_out() {
    int i = blockIdx.x*256 + threadIdx.x;
    if (i >= Bz*Lz*Ez/4) return;
    int row = i >> 7;
    int b = row >> 10;
    const float TINY = 1.175494351e-38f;
    float mf = g_mf[row];
    float rs0 = 0.5f*mf / fmaxf(g_S[b],  TINY);
    float rs1 = 0.5f*mf / fmaxf(g_gs[b], TINY);
    float4 u = ((const float4*)g_U)[i];
    float4 g = ((const float4*)g_GAV)[i];
    float v0 = rs0*u.x + rs1*g.x;
    float v1 = rs0*u.y + rs1*g.y;
    float v2 = rs0*u.z + rs1*g.z;
    float v3 = rs0*u.w + rs1*g.w;
    uint32_t h01 = pk2f(v0, v1), h23 = pk2f(v2, v3);
    uint32_t l01 = pk2f(v0 - bflo(h01), v1 - bfhi(h01));
    uint32_t l23 = pk2f(v2 - bflo(h23), v3 - bfhi(h23));
    ((uint2*)g_aohi)[i] = make_uint2(h01, h23);
    ((uint2*)g_aolo)[i] = make_uint2(l01, l23);
}

// ---------------- pipelined HMMA GEMM mainloop (3-product) ----------------
#define T_ALO 10240
#define T_BHI 20480
#define T_BLO 30720
#define BUFSZ 40960
#define PIPE_SMEM (2*BUFSZ)

__device__ __forceinline__ void gemm_main(
    char* smc, uint32_t sb,
    const __nv_bfloat16* Ahi, const __nv_bfloat16* Alo,
    const __nv_bfloat16* Bhi, const __nv_bfloat16* Blo,
    int K, int bm, int bn, float acc[4][4][4])
{
    int tid = threadIdx.x, lane = tid & 31, wid = tid >> 5;
    int wm = wid & 1, wn = wid >> 1;
    const char* pAh = (const char*)(Ahi + (size_t)bm*K);
    const char* pAl = (const char*)(Alo + (size_t)bm*K);
    const char* pBh = (const char*)(Bhi + (size_t)bn*K);
    const char* pBl = (const char*)(Blo + (size_t)bn*K);

    uint32_t aRow = wm*64 + (lane & 15);
    uint32_t aK8  = (lane >> 4) * 8;
    uint32_t bRow = wn*32 + (lane & 7) + ((lane >> 4) << 3);
    uint32_t bK8  = ((lane >> 3) & 1) * 8;

    int nChunks = K >> 5;

    auto load_chunk = [&](int kc, int bsel) {
        uint32_t base = sb + bsel*BUFSZ;
        #pragma unroll
        for (int i = tid; i < 512; i += 256) {
            int r = i >> 2, c = i & 3;
            size_t go = (size_t)r*K*2 + (size_t)kc*64 + c*16;
            uint32_t so = r*80 + c*16;
            cp16(base + so,          pAh + go);
            cp16(base + T_ALO + so,  pAl + go);
            cp16(base + T_BHI + so,  pBh + go);
            cp16(base + T_BLO + so,  pBl + go);
        }
        cp_commit();
    };

    load_chunk(0, 0);

    for (int kc = 0; kc < nChunks; kc++) {
        __syncthreads();
        if (kc + 1 < nChunks) { load_chunk(kc+1, (kc+1)&1); cp_wait<1>(); }
        else                  { cp_wait<0>(); }
        __syncthreads();
        uint32_t bofs = sb + (kc&1)*BUFSZ;
        #pragma unroll
        for (int ks = 0; ks < 2; ks++) {
            uint32_t ah[4][4], al[4][4], bh[2][4], bl[2][4];
            #pragma unroll
            for (int mi = 0; mi < 4; mi++) {
                uint32_t ad = bofs + ((aRow + mi*16)*40 + ks*16 + aK8)*2;
                ldmat4(ah[mi], ad);
                ldmat4(al[mi], ad + T_ALO);
            }
            #pragma unroll
            for (int bj = 0; bj < 2; bj++) {
                uint32_t ad = bofs + T_BHI + ((bRow + bj*16)*40 + ks*16 + bK8)*2;
                ldmat4(bh[bj], ad);
                ldmat4(bl[bj], ad + (T_BLO - T_BHI));
            }
            #pragma unroll
            for (int mi = 0; mi < 4; mi++)
                #pragma unroll
                for (int nj = 0; nj < 4; nj++) {
                    int bj = nj >> 1, pr = (nj & 1)*2;
                    mma_bf16(acc[mi][nj], ah[mi], bh[bj][pr], bh[bj][pr+1]);
                    mma_bf16(acc[mi][nj], ah[mi], bl[bj][pr], bl[bj][pr+1]);
                    mma_bf16(acc[mi][nj], al[mi], bh[bj][pr], bh[bj][pr+1]);
                }
        }
    }
}

// fused QKV (3-product): z=0 -> Q (bf16 hi), z=1 -> K (bf16 hi), z=2 -> masked+transposed V split
__global__ __launch_bounds__(256, 1) void qkv_gemm() {
    extern __shared__ char smc[];
    uint32_t sb = smem_u32(smc);
    int z = blockIdx.z;
    int bm = blockIdx.y*128, bn = blockIdx.x*128;
    const __nv_bfloat16 *Bh, *Bl;
    if      (z == 0) { Bh = g_wqhi; Bl = g_wqlo; }
    else if (z == 1) { Bh = g_wkhi; Bl = g_wklo; }
    else             { Bh = g_wvhi; Bl = g_wvlo; }
    float acc[4][4][4] = {};
    gemm_main(smc, sb, g_xhi, g_xlo, Bh, Bl, Ez, bm, bn, acc);

    int lane = threadIdx.x & 31, wid = threadIdx.x >> 5;
    int wm = wid & 1, wn = wid >> 1;
    int r0l = wm*64 + (lane >> 2);
    int c0l = wn*32 + (lane & 3)*2;

    if (z < 2) {
        __nv_bfloat16* Ch = (z == 0) ? g_qhi : g_khi;
        #pragma unroll
        for (int mi = 0; mi < 4; mi++)
            #pragma unroll
            for (int nj = 0; nj < 4; nj++) {
                int r = bm + r0l + mi*16, c = bn + c0l + nj*8;
                *(uint32_t*)(Ch + (size_t)r*Ez + c)     = pk2f(acc[mi][nj][0], acc[mi][nj][1]);
                *(uint32_t*)(Ch + (size_t)(r+8)*Ez + c) = pk2f(acc[mi][nj][2], acc[mi][nj][3]);
            }
    } else {
        __syncthreads();
        #pragma unroll
        for (int mi = 0; mi < 4; mi++) {
            int r = r0l + mi*16;
            float m0 = g_mf[bm + r], m1 = g_mf[bm + r + 8];
            #pragma unroll
            for (int nj = 0; nj < 4; nj++) {
                int c = c0l + nj*8;
                #pragma unroll
                for (int e2 = 0; e2 < 2; e2++) {
                    float v0 = acc[mi][nj][e2]   * m0;
                    float v1 = acc[mi][nj][2+e2] * m1;
                    __nv_bfloat16 h0 = __float2bfloat16(v0);
                    __nv_bfloat16 h1 = __float2bfloat16(v1);
                    __nv_bfloat16 l0 = __float2bfloat16(v0 - __bfloat162float(h0));
                    __nv_bfloat16 l1 = __float2bfloat16(v1 - __bfloat162float(h1));
                    uint32_t o0 = (c+e2)*272 + r*2;
                    uint32_t o1 = (c+e2)*272 + (r+8)*2;
                    *(__nv_bfloat16*)(smc + o0) = h0;
                    *(__nv_bfloat16*)(smc + o1) = h1;
                    *(__nv_bfloat16*)(smc + BUFSZ + o0) = l0;
                    *(__nv_bfloat16*)(smc + BUFSZ + o1) = l1;
                }
            }
        }
        __syncthreads();
        int b = bm >> 10;
        int l0g = bm & 1023;
        for (int i = threadIdx.x; i < 2048; i += 256) {
            int e = i >> 4, l8 = (i & 15)*8;
            size_t go = ((size_t)b*Ez + bn + e)*Lz + l0g + l8;
            *(uint4*)(g_vthi + go) = *(const uint4*)(smc + e*272 + l8*2);
            *(uint4*)(g_vtlo + go) = *(const uint4*)(smc + BUFSZ + e*272 + l8*2);
        }
    }
}

// GAV plain GEMM (3-product, fp32 out) — on stream2 concurrent with attention
__global__ __launch_bounds__(256, 1) void gav_gemm() {
    extern __shared__ char smc[];
    uint32_t sb = smem_u32(smc);
    int z = blockIdx.z;
    int bm = blockIdx.y*128, bn = blockIdx.x*128;
    float acc[4][4][4] = {};
    gemm_main(smc, sb, g_acthi, g_actlo,
              g_vthi + (size_t)z*Ez*Lz, g_vtlo + (size_t)z*Ez*Lz,
              Lz, bm, bn, acc);

    int lane = threadIdx.x & 31, wid = threadIdx.x >> 5;
    int wm = wid & 1, wn = wid >> 1;
    int r0 = bm + wm*64 + (lane >> 2);
    int c0 = bn + wn*32 + (lane & 3)*2;
    float* Cp = g_GAV + (size_t)z*Lz*Ez;
    #pragma unroll
    for (int mi = 0; mi < 4; mi++)
        #pragma unroll
        for (int nj = 0; nj < 4; nj++) {
            float* p = Cp + (size_t)(r0 + mi*16)*Ez + c0 + nj*8;
            *(float2*)p                  = make_float2(acc[mi][nj][0], acc[mi][nj][1]);
            *(float2*)(p + (size_t)8*Ez) = make_float2(acc[mi][nj][2], acc[mi][nj][3]);
        }
}

// out = Aout @ Wo^T (3-product, fp32 epilogue)
__global__ __launch_bounds__(256, 1) void out_gemm(float* __restrict__ C) {
    extern __shared__ char smc[];
    uint32_t sb = smem_u32(smc);
    int bm = blockIdx.y*128, bn = blockIdx.x*128;
    float acc[4][4][4] = {};
    gemm_main(smc, sb, g_aohi, g_aolo, g_wohi, g_wolo, Ez, bm, bn, acc);

    int lane = threadIdx.x & 31, wid = threadIdx.x >> 5;
    int wm = wid & 1, wn = wid >> 1;
    int r0 = bm + wm*64 + (lane >> 2);
    int c0 = bn + wn*32 + (lane & 3)*2;
    #pragma unroll
    for (int mi = 0; mi < 4; mi++)
        #pragma unroll
        for (int nj = 0; nj < 4; nj++) {
            float* p = C + (size_t)(r0 + mi*16)*Ez + c0 + nj*8;
            *(float2*)p                  = make_float2(acc[mi][nj][0], acc[mi][nj][1]);
            *(float2*)(p + (size_t)8*Ez) = make_float2(acc[mi][nj][2], acc[mi][nj][3]);
        }
}

// ---------------- attention: S = Qhi Khi^T (1-product), PV = (Phi+Plo) Vhi^T (2-product) ----------------
#define A_QHI 0
#define A_K0  36864
#define A_KBUF 18432
#define A_VHI 110592
#define A_PHI 145408
#define A_PLO 180224
#define A_MQ  215040
#define A_MK  215552
#define A_RED 216576
#define AT_SMEM (216576 + 2048)

__global__ __launch_bounds__(512, 1) void attn_mma() {
    extern __shared__ char smc[];
    uint32_t sb = smem_u32(smc);
    float* mqf = (float*)(smc + A_MQ);
    float* red = (float*)(smc + A_RED);

    int tid = threadIdx.x, lane = tid & 31, wid = tid >> 5;
    int qt = blockIdx.x, h = blockIdx.y, b = blockIdx.z;

    int wm = wid & 3, wn = wid >> 2;
    int wq = wid & 7, wd = wid >> 3;

    const __nv_bfloat16* Qh = g_qhi + ((size_t)(b*Lz + qt*128))*Ez + h*64;
    const __nv_bfloat16* Kh = g_khi + ((size_t)(b*Lz))*Ez + h*64;
    const __nv_bfloat16* Vth = g_vthi + ((size_t)(b*Ez + h*64))*Lz;

    auto issue_K = [&](int kt, int bsel) {
        uint32_t base = sb + A_K0 + bsel*A_KBUF;
        #pragma unroll
        for (int i = tid; i < 1024; i += 512) {
            int r = i >> 3, c8 = (i & 7)*8;
            cp16(base + r*144 + c8*2, Kh + (size_t)(kt*128 + r)*Ez + c8);
        }
        if (tid < 32) cp16(sb + A_MK + bsel*512 + tid*16, g_mf + b*Lz + kt*128 + tid*4);
        cp_commit();
    };
    auto issue_V = [&](int kt) {
        #pragma unroll
        for (int i = tid; i < 1024; i += 512) {
            int r = i >> 4, c8 = (i & 15)*8;
            cp16(sb + A_VHI + r*272 + c8*2, Vth + (size_t)r*Lz + kt*128 + c8);
        }
        cp_commit();
    };

    // Q hi only
    for (int i = tid; i < 1024; i += 512) {
        int r = i >> 3, c8 = (i & 7)*8;
        *(uint4*)(smc + A_QHI + r*144 + c8*2) = *(const uint4*)(Qh + (size_t)r*Ez + c8);
    }
    if (tid < 128) mqf[tid] = g_mf[b*Lz + qt*128 + tid];

    issue_K(0, 0);
    issue_V(0);

    uint32_t qRow = wm*32 + (lane & 15);
    uint32_t qK8  = (lane >> 4)*8;
    uint32_t kRowB = wn*32 + (lane & 7) + ((lane >> 4) << 3);
    uint32_t kK8  = ((lane >> 3) & 1)*8;
    uint32_t pRow = wq*16 + (lane & 15);
    uint32_t pK8  = (lane >> 4)*8;
    uint32_t vRowB = wd*32 + (lane & 7) + ((lane >> 4) << 3);
    uint32_t vK8  = ((lane >> 3) & 1)*8;

    float U[4][4] = {};
    float partial = 0.f;

    cp_wait<0>();
    __syncthreads();

    for (int kt = 0; kt < 8; kt++) {
        if (kt + 1 < 8) issue_K(kt+1, (kt+1)&1);

        uint32_t kbase = sb + A_K0 + (kt&1)*A_KBUF;
        const float* mkf = (const float*)(smc + A_MK + (kt&1)*512);

        // ---- S = Qhi Khi^T (single product) ----
        float S[2][4][4] = {};
        #pragma unroll
        for (int ks = 0; ks < 4; ks++) {
            uint32_t ah[2][4], bh[2][4];
            #pragma unroll
            for (int mi = 0; mi < 2; mi++) {
                uint32_t ad = sb + A_QHI + (qRow + mi*16)*144 + (ks*16 + qK8)*2;
                ldmat4(ah[mi], ad);
            }
            #pragma unroll
            for (int nb = 0; nb < 2; nb++) {
                uint32_t ad = kbase + (kRowB + nb*16)*144 + (ks*16 + kK8)*2;
                ldmat4(bh[nb], ad);
            }
            #pragma unroll
            for (int mi = 0; mi < 2; mi++)
                #pragma unroll
                for (int nj = 0; nj < 4; nj++) {
                    int nb = nj >> 1, pr = (nj & 1)*2;
                    mma_bf16(S[mi][nj], ah[mi], bh[nb][pr], bh[nb][pr+1]);
                }
        }

        {
            int r0 = wm*32 + (lane >> 2);
            int c0b = wn*32 + (lane & 3)*2;
            #pragma unroll
            for (int mi = 0; mi < 2; mi++) {
                int row0 = r0 + mi*16, row1 = row0 + 8;
                float mq0 = mqf[row0], mq1 = mqf[row1];
                #pragma unroll
                for (int nj = 0; nj < 4; nj++) {
                    int c0 = c0b + nj*8;
                    float mk0 = mkf[c0], mk1 = mkf[c0+1];
                    float p0 = ex2f(tanh_fast(S[mi][nj][0]*0.125f)*L2E)*mk0;
                    float p1 = ex2f(tanh_fast(S[mi][nj][1]*0.125f)*L2E)*mk1;
                    float p2 = ex2f(tanh_fast(S[mi][nj][2]*0.125f)*L2E)*mk0;
                    float p3 = ex2f(tanh_fast(S[mi][nj][3]*0.125f)*L2E)*mk1;
                    partial += mq0*(p0+p1) + mq1*(p2+p3);
                    uint32_t h01 = pk2f(p0, p1), h23 = pk2f(p2, p3);
                    uint32_t l01 = pk2f(p0 - bflo(h01), p1 - bfhi(h01));
                    uint32_t l23 = pk2f(p2 - bflo(h23), p3 - bfhi(h23));
                    uint32_t o0 = row0*272 + c0*2, o1 = row1*272 + c0*2;
                    *(uint32_t*)(smc + A_PHI + o0) = h01;
                    *(uint32_t*)(smc + A_PHI + o1) = h23;
                    *(uint32_t*)(smc + A_PLO + o0) = l01;
                    *(uint32_t*)(smc + A_PLO + o1) = l23;
                }
            }
        }
        __syncthreads();
        if (kt < 7) cp_wait<1>();
        else        cp_wait<0>();

        // ---- U += (Phi + Plo) Vhi^T (2-product) ----
        #pragma unroll
        for (int ch = 0; ch < 8; ch++) {
            uint32_t ph[4], pl[4];
            uint32_t pa = sb + A_PHI + pRow*272 + (ch*16 + pK8)*2;
            ldmat4(ph, pa);
            ldmat4(pl, pa + (A_PLO - A_PHI));
            #pragma unroll
            for (int g = 0; g < 2; g++) {
                uint32_t vh[4];
                uint32_t va = sb + A_VHI + (vRowB + g*16)*272 + (ch*16 + vK8)*2;
                ldmat4(vh, va);
                mma_bf16(U[g*2],   ph, vh[0], vh[1]);
                mma_bf16(U[g*2],   pl, vh[0], vh[1]);
                mma_bf16(U[g*2+1], ph, vh[2], vh[3]);
                mma_bf16(U[g*2+1], pl, vh[2], vh[3]);
            }
        }
        __syncthreads();
        if (kt + 1 < 8) {
            issue_V(kt+1);
            cp_wait<1>();
            __syncthreads();
        }
    }

    {
        int r = wq*16 + (lane >> 2);
        int cb = wd*32 + (lane & 3)*2;
        float* Ug = g_U + ((size_t)(b*Lz + qt*128))*Ez + h*64;
        #pragma unroll
        for (int dj = 0; dj < 4; dj++) {
            int c = cb + dj*8;
            *(float2*)(Ug + (size_t)r*Ez + c)     = make_float2(U[dj][0], U[dj][1]);
            *(float2*)(Ug + (size_t)(r+8)*Ez + c) = make_float2(U[dj][2], U[dj][3]);
        }
    }

    red[tid] = partial; __syncthreads();
    for (int s = 256; s > 0; s >>= 1) { if (tid < s) red[tid] += red[tid+s]; __syncthreads(); }
    if (tid == 0) g_Spart[(b*Hz + h)*8 + qt] = red[0];
}

// ---------------- host launcher ----------------
extern "C" void kernel_launch(void* const* d_in, const int* in_sizes, int n_in,
                              void* d_out, int out_size) {
    const float* x    = (const float*)d_in[0];
    const void*  mask = d_in[1];
    const float* Wq   = (const float*)d_in[2];
    const float* Wk   = (const float*)d_in[3];
    const float* Wv   = (const float*)d_in[4];
    const float* Wo   = (const float*)d_in[5];
    const float* G    = (const float*)d_in[6];
    float* out = (float*)d_out;

    static bool inited = false;
    static cudaStream_t s2;
    static cudaEvent_t evFork, evQKV, evJoin;
    if (!inited) {
        cudaStreamCreateWithFlags(&s2, cudaStreamNonBlocking);
        cudaEventCreateWithFlags(&evFork, cudaEventDisableTiming);
        cudaEventCreateWithFlags(&evQKV, cudaEventDisableTiming);
        cudaEventCreateWithFlags(&evJoin, cudaEventDisableTiming);
        cudaFuncSetAttribute((const void*)attn_mma,
                             cudaFuncAttributeMaxDynamicSharedMemorySize, AT_SMEM);
        cudaFuncSetAttribute((const void*)qkv_gemm,
                             cudaFuncAttributeMaxDynamicSharedMemorySize, PIPE_SMEM);
        cudaFuncSetAttribute((const void*)gav_gemm,
                             cudaFuncAttributeMaxDynamicSharedMemorySize, PIPE_SMEM);
        cudaFuncSetAttribute((const void*)out_gemm,
                             cudaFuncAttributeMaxDynamicSharedMemorySize, PIPE_SMEM);
        inited = true;
    }

    convert_mask<<<32,256>>>(mask);

    // fork G-softmax chain onto s2 (needs only g_mf)
    cudaEventRecord(evFork, 0);
    cudaStreamWaitEvent(s2, evFork, 0);
    softmax_g<<<1024,256,0,s2>>>(G);
    reduce_g<<<8,256,0,s2>>>();

    // main chain
    split_all<<<(NXS4 + 4*NWS4)/256,256>>>((const float4*)x, (const float4*)Wq,
                                           (const float4*)Wk, (const float4*)Wv,
                                           (const float4*)Wo);
    qkv_gemm<<<dim3(4,64,3),256,PIPE_SMEM>>>();
    cudaEventRecord(evQKV, 0);

    // s2: GAV mainloop overlaps with attention
    cudaStreamWaitEvent(s2, evQKV, 0);
    gav_gemm<<<dim3(4,8,Bz),256,PIPE_SMEM,s2>>>();
    cudaEventRecord(evJoin, s2);

    attn_mma<<<dim3(8,Hz,Bz),512,AT_SMEM>>>();

    cudaStreamWaitEvent(0, evJoin, 0);
    reduce_s<<<8,64>>>();
    prep_out<<<(Bz*Lz*Ez/4 + 255)/256,256>>>();
    out_gemm<<<dim3(4,64),256,PIPE_SMEM>>>(out);
}

// round 16
// speedup vs baseline: 3.4964x; 1.0540x over previous
#include <cuda_runtime.h>
#include <cuda_bf16.h>
#include <float.h>
#include <stdint.h>

#define Bz   8
#define Lz   1024
#define Ez   512
#define Hz   8
#define Dz   64

// ---------------- fast-math helpers ----------------
__device__ __forceinline__ float tanh_fast(float x) {
    float y; asm("tanh.approx.f32 %0, %1;" : "=f"(y) : "f"(x)); return y;
}
__device__ __forceinline__ float ex2f(float x) {
    float y; asm("ex2.approx.f32 %0, %1;" : "=f"(y) : "f"(x)); return y;
}
#define L2E 1.4426950408889634f

__device__ __forceinline__ uint32_t smem_u32(const void* p) {
    uint32_t a;
    asm("{ .reg .u64 t; cvta.to.shared.u64 t, %1; cvt.u32.u64 %0, t; }" : "=r"(a) : "l"(p));
    return a;
}
__device__ __forceinline__ uint32_t pk2f(float lo, float hi) {
    uint32_t r; asm("cvt.rn.bf16x2.f32 %0, %1, %2;" : "=r"(r) : "f"(hi), "f"(lo)); return r;
}
__device__ __forceinline__ float bflo(uint32_t v) { return __uint_as_float(v << 16); }
__device__ __forceinline__ float bfhi(uint32_t v) { return __uint_as_float(v & 0xFFFF0000u); }

// ---------------- mma.sync / cp.async helpers ----------------
__device__ __forceinline__ void ldmat4(uint32_t* r, uint32_t a) {
    asm volatile("ldmatrix.sync.aligned.m8n8.x4.shared.b16 {%0,%1,%2,%3}, [%4];"
                 : "=r"(r[0]), "=r"(r[1]), "=r"(r[2]), "=r"(r[3]) : "r"(a));
}
__device__ __forceinline__ void mma_bf16(float* c, const uint32_t* a, uint32_t b0, uint32_t b1) {
    asm volatile("mma.sync.aligned.m16n8k16.row.col.f32.bf16.bf16.f32 "
                 "{%0,%1,%2,%3}, {%4,%5,%6,%7}, {%8,%9}, {%0,%1,%2,%3};"
                 : "+f"(c[0]), "+f"(c[1]), "+f"(c[2]), "+f"(c[3])
                 : "r"(a[0]), "r"(a[1]), "r"(a[2]), "r"(a[3]), "r"(b0), "r"(b1));
}
__device__ __forceinline__ void cp16(uint32_t s, const void* g) {
    asm volatile("cp.async.cg.shared.global [%0], [%1], 16;" :: "r"(s), "l"(g));
}
__device__ __forceinline__ void cp_commit() { asm volatile("cp.async.commit_group;"); }
template<int N> __device__ __forceinline__ void cp_wait() {
    asm volatile("cp.async.wait_group %0;" :: "n"(N));
}

// ---------------- device scratch ----------------
__device__ float g_mf[Bz*Lz];
__device__ float g_U [Bz*Lz*Ez];
__device__ float g_GAV[Bz*Lz*Ez];
__device__ float g_Spart[Bz*Hz*8];
__device__ float g_Gpart[Bz*Lz];
__device__ float g_gs[Bz];
__device__ float g_S[Bz];

__device__ __nv_bfloat16 g_xhi[Bz*Lz*Ez], g_xlo[Bz*Lz*Ez];
__device__ __nv_bfloat16 g_qhi[Bz*Lz*Ez];
__device__ __nv_bfloat16 g_khi[Bz*Lz*Ez];
__device__ __nv_bfloat16 g_wqhi[Ez*Ez], g_wqlo[Ez*Ez];
__device__ __nv_bfloat16 g_wkhi[Ez*Ez], g_wklo[Ez*Ez];
__device__ __nv_bfloat16 g_wvhi[Ez*Ez], g_wvlo[Ez*Ez];
__device__ __nv_bfloat16 g_wohi[Ez*Ez], g_wolo[Ez*Ez];
__device__ __nv_bfloat16 g_acthi[Lz*Lz], g_actlo[Lz*Lz];
__device__ __nv_bfloat16 g_vthi[Bz*Ez*Lz], g_vtlo[Bz*Ez*Lz];
__device__ __nv_bfloat16 g_aohi[Bz*Lz*Ez], g_aolo[Bz*Lz*Ez];

// ---------------- mask convert (detection fused, per-block) ----------------
__global__ void convert_mask(const void* mv) {
    __shared__ int skind;
    const unsigned char* m = (const unsigned char*)mv;
    if (threadIdx.x == 0) {
        bool isInt32 = true;
        for (int i = 0; i < 64; i++) {
            if (m[4*i] > 1) isInt32 = false;
            if (m[4*i+1] | m[4*i+2] | m[4*i+3]) isInt32 = false;
        }
        int kind;
        if (isInt32) kind = 0;
        else {
            const unsigned int* w = (const unsigned int*)m;
            bool isFloat = true;
            for (int i = 0; i < 64; i++) {
                unsigned v = w[i];
                if (v != 0u && v != 0x3F800000u) isFloat = false;
            }
            kind = isFloat ? 2 : 1;
        }
        skind = kind;
    }
    __syncthreads();
    int i = blockIdx.x*256 + threadIdx.x;
    if (i >= Bz*Lz) return;
    int k = skind;
    float v;
    if (k == 0)      v = ((const int*)mv)[i] ? 1.f : 0.f;
    else if (k == 1) v = m[i] ? 1.f : 0.f;
    else             v = ((const float*)mv)[i];
    g_mf[i] = v;
}

// ---------------- splits: x + 4 weights -> hi/lo (float4 vectorized) ----------------
#define NXS4 (Bz*Lz*Ez/4)
#define NWS4 (Ez*Ez/4)
__global__ void split_all(const float4* __restrict__ x,
                          const float4* __restrict__ wq, const float4* __restrict__ wk,
                          const float4* __restrict__ wv, const float4* __restrict__ wo) {
    int i = blockIdx.x*256 + threadIdx.x;
    const float4* s; uint2 *hp, *lp; int idx;
    if (i < NXS4) { s = x; hp = (uint2*)g_xhi; lp = (uint2*)g_xlo; idx = i; }
    else {
        int j = i - NXS4;
        int w = j >> 16;
        idx = j & (NWS4-1);
        if      (w == 0) { s = wq; hp = (uint2*)g_wqhi; lp = (uint2*)g_wqlo; }
        else if (w == 1) { s = wk; hp = (uint2*)g_wkhi; lp = (uint2*)g_wklo; }
        else if (w == 2) { s = wv; hp = (uint2*)g_wvhi; lp = (uint2*)g_wvlo; }
        else             { s = wo; hp = (uint2*)g_wohi; lp = (uint2*)g_wolo; }
    }
    float4 v = s[idx];
    uint32_t h01 = pk2f(v.x, v.y), h23 = pk2f(v.z, v.w);
    uint32_t l01 = pk2f(v.x - bflo(h01), v.y - bfhi(h01));
    uint32_t l23 = pk2f(v.z - bflo(h23), v.w - bfhi(h23));
    hp[idx] = make_uint2(h01, h23);
    lp[idx] = make_uint2(l01, l23);
}

// ---------------- softmax of G rows -> bf16 hi/lo + fused gsum partials ----------------
__global__ __launch_bounds__(256) void softmax_g(const float* __restrict__ G) {
    int q = blockIdx.x, t = threadIdx.x;
    const float* row = G + (size_t)q*Lz;
    __shared__ float red[256];
    __shared__ float part[8][8];
    float mx = -FLT_MAX;
    for (int k = t; k < Lz; k += 256) mx = fmaxf(mx, row[k]);
    red[t] = mx; __syncthreads();
    for (int s = 128; s > 0; s >>= 1) { if (t < s) red[t] = fmaxf(red[t], red[t+s]); __syncthreads(); }
    mx = red[0]; __syncthreads();
    float vals[4]; float sum = 0.f;
    for (int k = t, j = 0; k < Lz; k += 256, j++) { float e = __expf(row[k]-mx); vals[j] = e; sum += e; }
    red[t] = sum; __syncthreads();
    for (int s = 128; s > 0; s >>= 1) { if (t < s) red[t] += red[t+s]; __syncthreads(); }
    float inv = 1.f / red[0];
    float gs[8] = {};
    for (int k = t, j = 0; k < Lz; k += 256, j++) {
        float v = vals[j]*inv;
        __nv_bfloat16 h = __float2bfloat16(v);
        g_acthi[(size_t)q*Lz + k] = h;
        g_actlo[(size_t)q*Lz + k] = __float2bfloat16(v - __bfloat162float(h));
        #pragma unroll
        for (int b2 = 0; b2 < 8; b2++) gs[b2] += v * __ldg(g_mf + b2*Lz + k);
    }
    #pragma unroll
    for (int o = 16; o; o >>= 1)
        #pragma unroll
        for (int b2 = 0; b2 < 8; b2++) gs[b2] += __shfl_down_sync(0xffffffffu, gs[b2], o);
    if ((t & 31) == 0)
        #pragma unroll
        for (int b2 = 0; b2 < 8; b2++) part[t>>5][b2] = gs[b2];
    __syncthreads();
    if (t < 8) {
        float r = 0.f;
        #pragma unroll
        for (int w = 0; w < 8; w++) r += part[w][t];
        g_Gpart[t*Lz + q] = r * __ldg(g_mf + t*Lz + q);
    }
}

__global__ __launch_bounds__(256) void reduce_g() {
    int b = blockIdx.x, t = threadIdx.x;
    __shared__ float red[256];
    float s = 0.f;
    for (int i = t; i < Lz; i += 256) s += g_Gpart[b*Lz + i];
    red[t] = s; __syncthreads();
    for (int st = 128; st > 0; st >>= 1) { if (t < st) red[t] += red[t+st]; __syncthreads(); }
    if (t == 0) g_gs[b] = red[0];
}

__global__ __launch_bounds__(64) void reduce_s() {
    int b = blockIdx.x, t = threadIdx.x;
    __shared__ float red[64];
    float s = (t < Hz*8) ? g_Spart[b*Hz*8 + t] : 0.f;
    red[t] = s; __syncthreads();
    for (int st = 32; st > 0; st >>= 1) { if (t < st) red[t] += red[t+st]; __syncthreads(); }
    if (t == 0) g_S[b] = red[0];
}

// aout = (0.5 mf/S)*U + (0.5 mf/gs)*GAV -> bf16 hi/lo (rowscales fused)
__global__ void prep_out() {
    int i = blockIdx.x*256 + threadIdx.x;
    if (i >= Bz*Lz*Ez/4) return;
    int row = i >> 7;
    int b = row >> 10;
    const float TINY = 1.175494351e-38f;
    float mf = g_mf[row];
    float rs0 = 0.5f*mf / fmaxf(g_S[b],  TINY);
    float rs1 = 0.5f*mf / fmaxf(g_gs[b], TINY);
    float4 u = ((const float4*)g_U)[i];
    float4 g = ((const float4*)g_GAV)[i];
    float v0 = rs0*u.x + rs1*g.x;
    float v1 = rs0*u.y + rs1*g.y;
    float v2 = rs0*u.z + rs1*g.z;
    float v3 = rs0*u.w + rs1*g.w;
    uint32_t h01 = pk2f(v0, v1), h23 = pk2f(v2, v3);
    uint32_t l01 = pk2f(v0 - bflo(h01), v1 - bfhi(h01));
    uint32_t l23 = pk2f(v2 - bflo(h23), v3 - bfhi(h23));
    ((uint2*)g_aohi)[i] = make_uint2(h01, h23);
    ((uint2*)g_aolo)[i] = make_uint2(l01, l23);
}

// ---------------- pipelined HMMA GEMM mainloop (3-product) ----------------
#define T_ALO 10240
#define T_BHI 20480
#define T_BLO 30720
#define BUFSZ 40960
#define PIPE_SMEM (2*BUFSZ)

__device__ __forceinline__ void gemm_main(
    char* smc, uint32_t sb,
    const __nv_bfloat16* Ahi, const __nv_bfloat16* Alo,
    const __nv_bfloat16* Bhi, const __nv_bfloat16* Blo,
    int K, int bm, int bn, float acc[4][4][4])
{
    int tid = threadIdx.x, lane = tid & 31, wid = tid >> 5;
    int wm = wid & 1, wn = wid >> 1;
    const char* pAh = (const char*)(Ahi + (size_t)bm*K);
    const char* pAl = (const char*)(Alo + (size_t)bm*K);
    const char* pBh = (const char*)(Bhi + (size_t)bn*K);
    const char* pBl = (const char*)(Blo + (size_t)bn*K);

    uint32_t aRow = wm*64 + (lane & 15);
    uint32_t aK8  = (lane >> 4) * 8;
    uint32_t bRow = wn*32 + (lane & 7) + ((lane >> 4) << 3);
    uint32_t bK8  = ((lane >> 3) & 1) * 8;

    int nChunks = K >> 5;

    auto load_chunk = [&](int kc, int bsel) {
        uint32_t base = sb + bsel*BUFSZ;
        #pragma unroll
        for (int i = tid; i < 512; i += 256) {
            int r = i >> 2, c = i & 3;
            size_t go = (size_t)r*K*2 + (size_t)kc*64 + c*16;
            uint32_t so = r*80 + c*16;
            cp16(base + so,          pAh + go);
            cp16(base + T_ALO + so,  pAl + go);
            cp16(base + T_BHI + so,  pBh + go);
            cp16(base + T_BLO + so,  pBl + go);
        }
        cp_commit();
    };

    load_chunk(0, 0);

    for (int kc = 0; kc < nChunks; kc++) {
        __syncthreads();
        if (kc + 1 < nChunks) { load_chunk(kc+1, (kc+1)&1); cp_wait<1>(); }
        else                  { cp_wait<0>(); }
        __syncthreads();
        uint32_t bofs = sb + (kc&1)*BUFSZ;
        #pragma unroll
        for (int ks = 0; ks < 2; ks++) {
            uint32_t ah[4][4], al[4][4], bh[2][4], bl[2][4];
            #pragma unroll
            for (int mi = 0; mi < 4; mi++) {
                uint32_t ad = bofs + ((aRow + mi*16)*40 + ks*16 + aK8)*2;
                ldmat4(ah[mi], ad);
                ldmat4(al[mi], ad + T_ALO);
            }
            #pragma unroll
            for (int bj = 0; bj < 2; bj++) {
                uint32_t ad = bofs + T_BHI + ((bRow + bj*16)*40 + ks*16 + bK8)*2;
                ldmat4(bh[bj], ad);
                ldmat4(bl[bj], ad + (T_BLO - T_BHI));
            }
            #pragma unroll
            for (int mi = 0; mi < 4; mi++)
                #pragma unroll
                for (int nj = 0; nj < 4; nj++) {
                    int bj = nj >> 1, pr = (nj & 1)*2;
                    mma_bf16(acc[mi][nj], ah[mi], bh[bj][pr], bh[bj][pr+1]);
                    mma_bf16(acc[mi][nj], ah[mi], bl[bj][pr], bl[bj][pr+1]);
                    mma_bf16(acc[mi][nj], al[mi], bh[bj][pr], bh[bj][pr+1]);
                }
        }
    }
}

// fused QKV (3-product): z=0 -> Q (bf16 hi), z=1 -> K (bf16 hi), z=2 -> masked+transposed V split
__global__ __launch_bounds__(256, 1) void qkv_gemm() {
    extern __shared__ char smc[];
    uint32_t sb = smem_u32(smc);
    int z = blockIdx.z;
    int bm = blockIdx.y*128, bn = blockIdx.x*128;
    const __nv_bfloat16 *Bh, *Bl;
    if      (z == 0) { Bh = g_wqhi; Bl = g_wqlo; }
    else if (z == 1) { Bh = g_wkhi; Bl = g_wklo; }
    else             { Bh = g_wvhi; Bl = g_wvlo; }
    float acc[4][4][4] = {};
    gemm_main(smc, sb, g_xhi, g_xlo, Bh, Bl, Ez, bm, bn, acc);

    int lane = threadIdx.x & 31, wid = threadIdx.x >> 5;
    int wm = wid & 1, wn = wid >> 1;
    int r0l = wm*64 + (lane >> 2);
    int c0l = wn*32 + (lane & 3)*2;

    if (z < 2) {
        __nv_bfloat16* Ch = (z == 0) ? g_qhi : g_khi;
        #pragma unroll
        for (int mi = 0; mi < 4; mi++)
            #pragma unroll
            for (int nj = 0; nj < 4; nj++) {
                int r = bm + r0l + mi*16, c = bn + c0l + nj*8;
                *(uint32_t*)(Ch + (size_t)r*Ez + c)     = pk2f(acc[mi][nj][0], acc[mi][nj][1]);
                *(uint32_t*)(Ch + (size_t)(r+8)*Ez + c) = pk2f(acc[mi][nj][2], acc[mi][nj][3]);
            }
    } else {
        __syncthreads();
        #pragma unroll
        for (int mi = 0; mi < 4; mi++) {
            int r = r0l + mi*16;
            float m0 = g_mf[bm + r], m1 = g_mf[bm + r + 8];
            #pragma unroll
            for (int nj = 0; nj < 4; nj++) {
                int c = c0l + nj*8;
                #pragma unroll
                for (int e2 = 0; e2 < 2; e2++) {
                    float v0 = acc[mi][nj][e2]   * m0;
                    float v1 = acc[mi][nj][2+e2] * m1;
                    __nv_bfloat16 h0 = __float2bfloat16(v0);
                    __nv_bfloat16 h1 = __float2bfloat16(v1);
                    __nv_bfloat16 l0 = __float2bfloat16(v0 - __bfloat162float(h0));
                    __nv_bfloat16 l1 = __float2bfloat16(v1 - __bfloat162float(h1));
                    uint32_t o0 = (c+e2)*272 + r*2;
                    uint32_t o1 = (c+e2)*272 + (r+8)*2;
                    *(__nv_bfloat16*)(smc + o0) = h0;
                    *(__nv_bfloat16*)(smc + o1) = h1;
                    *(__nv_bfloat16*)(smc + BUFSZ + o0) = l0;
                    *(__nv_bfloat16*)(smc + BUFSZ + o1) = l1;
                }
            }
        }
        __syncthreads();
        int b = bm >> 10;
        int l0g = bm & 1023;
        for (int i = threadIdx.x; i < 2048; i += 256) {
            int e = i >> 4, l8 = (i & 15)*8;
            size_t go = ((size_t)b*Ez + bn + e)*Lz + l0g + l8;
            *(uint4*)(g_vthi + go) = *(const uint4*)(smc + e*272 + l8*2);
            *(uint4*)(g_vtlo + go) = *(const uint4*)(smc + BUFSZ + e*272 + l8*2);
        }
    }
}

// GAV plain GEMM (3-product, fp32 out) — on stream2 concurrent with attention
__global__ __launch_bounds__(256, 1) void gav_gemm() {
    extern __shared__ char smc[];
    uint32_t sb = smem_u32(smc);
    int z = blockIdx.z;
    int bm = blockIdx.y*128, bn = blockIdx.x*128;
    float acc[4][4][4] = {};
    gemm_main(smc, sb, g_acthi, g_actlo,
              g_vthi + (size_t)z*Ez*Lz, g_vtlo + (size_t)z*Ez*Lz,
              Lz, bm, bn, acc);

    int lane = threadIdx.x & 31, wid = threadIdx.x >> 5;
    int wm = wid & 1, wn = wid >> 1;
    int r0 = bm + wm*64 + (lane >> 2);
    int c0 = bn + wn*32 + (lane & 3)*2;
    float* Cp = g_GAV + (size_t)z*Lz*Ez;
    #pragma unroll
    for (int mi = 0; mi < 4; mi++)
        #pragma unroll
        for (int nj = 0; nj < 4; nj++) {
            float* p = Cp + (size_t)(r0 + mi*16)*Ez + c0 + nj*8;
            *(float2*)p                  = make_float2(acc[mi][nj][0], acc[mi][nj][1]);
            *(float2*)(p + (size_t)8*Ez) = make_float2(acc[mi][nj][2], acc[mi][nj][3]);
        }
}

// out = Aout @ Wo^T (3-product, fp32 epilogue)
__global__ __launch_bounds__(256, 1) void out_gemm(float* __restrict__ C) {
    extern __shared__ char smc[];
    uint32_t sb = smem_u32(smc);
    int bm = blockIdx.y*128, bn = blockIdx.x*128;
    float acc[4][4][4] = {};
    gemm_main(smc, sb, g_aohi, g_aolo, g_wohi, g_wolo, Ez, bm, bn, acc);

    int lane = threadIdx.x & 31, wid = threadIdx.x >> 5;
    int wm = wid & 1, wn = wid >> 1;
    int r0 = bm + wm*64 + (lane >> 2);
    int c0 = bn + wn*32 + (lane & 3)*2;
    #pragma unroll
    for (int mi = 0; mi < 4; mi++)
        #pragma unroll
        for (int nj = 0; nj < 4; nj++) {
            float* p = C + (size_t)(r0 + mi*16)*Ez + c0 + nj*8;
            *(float2*)p                  = make_float2(acc[mi][nj][0], acc[mi][nj][1]);
            *(float2*)(p + (size_t)8*Ez) = make_float2(acc[mi][nj][2], acc[mi][nj][3]);
        }
}

// ---------------- attention: S = Qhi Khi^T (1-product), PV = Phi Vhi^T (1-product) ----------------
#define A_QHI 0
#define A_K0  36864
#define A_KBUF 18432
#define A_VHI 110592
#define A_PHI 145408
#define A_MQ  215040
#define A_MK  215552
#define A_RED 216576
#define AT_SMEM (216576 + 2048)

__global__ __launch_bounds__(512, 1) void attn_mma() {
    extern __shared__ char smc[];
    uint32_t sb = smem_u32(smc);
    float* mqf = (float*)(smc + A_MQ);
    float* red = (float*)(smc + A_RED);

    int tid = threadIdx.x, lane = tid & 31, wid = tid >> 5;
    int qt = blockIdx.x, h = blockIdx.y, b = blockIdx.z;

    int wm = wid & 3, wn = wid >> 2;
    int wq = wid & 7, wd = wid >> 3;

    const __nv_bfloat16* Qh = g_qhi + ((size_t)(b*Lz + qt*128))*Ez + h*64;
    const __nv_bfloat16* Kh = g_khi + ((size_t)(b*Lz))*Ez + h*64;
    const __nv_bfloat16* Vth = g_vthi + ((size_t)(b*Ez + h*64))*Lz;

    auto issue_K = [&](int kt, int bsel) {
        uint32_t base = sb + A_K0 + bsel*A_KBUF;
        #pragma unroll
        for (int i = tid; i < 1024; i += 512) {
            int r = i >> 3, c8 = (i & 7)*8;
            cp16(base + r*144 + c8*2, Kh + (size_t)(kt*128 + r)*Ez + c8);
        }
        if (tid < 32) cp16(sb + A_MK + bsel*512 + tid*16, g_mf + b*Lz + kt*128 + tid*4);
        cp_commit();
    };
    auto issue_V = [&](int kt) {
        #pragma unroll
        for (int i = tid; i < 1024; i += 512) {
            int r = i >> 4, c8 = (i & 15)*8;
            cp16(sb + A_VHI + r*272 + c8*2, Vth + (size_t)r*Lz + kt*128 + c8);
        }
        cp_commit();
    };

    // Q hi only
    for (int i = tid; i < 1024; i += 512) {
        int r = i >> 3, c8 = (i & 7)*8;
        *(uint4*)(smc + A_QHI + r*144 + c8*2) = *(const uint4*)(Qh + (size_t)r*Ez + c8);
    }
    if (tid < 128) mqf[tid] = g_mf[b*Lz + qt*128 + tid];

    issue_K(0, 0);
    issue_V(0);

    uint32_t qRow = wm*32 + (lane & 15);
    uint32_t qK8  = (lane >> 4)*8;
    uint32_t kRowB = wn*32 + (lane & 7) + ((lane >> 4) << 3);
    uint32_t kK8  = ((lane >> 3) & 1)*8;
    uint32_t pRow = wq*16 + (lane & 15);
    uint32_t pK8  = (lane >> 4)*8;
    uint32_t vRowB = wd*32 + (lane & 7) + ((lane >> 4) << 3);
    uint32_t vK8  = ((lane >> 3) & 1)*8;

    float U[4][4] = {};
    float partial = 0.f;

    cp_wait<0>();
    __syncthreads();

    for (int kt = 0; kt < 8; kt++) {
        if (kt + 1 < 8) issue_K(kt+1, (kt+1)&1);

        uint32_t kbase = sb + A_K0 + (kt&1)*A_KBUF;
        const float* mkf = (const float*)(smc + A_MK + (kt&1)*512);

        // ---- S = Qhi Khi^T (single product) ----
        float S[2][4][4] = {};
        #pragma unroll
        for (int ks = 0; ks < 4; ks++) {
            uint32_t ah[2][4], bh[2][4];
            #pragma unroll
            for (int mi = 0; mi < 2; mi++) {
                uint32_t ad = sb + A_QHI + (qRow + mi*16)*144 + (ks*16 + qK8)*2;
                ldmat4(ah[mi], ad);
            }
            #pragma unroll
            for (int nb = 0; nb < 2; nb++) {
                uint32_t ad = kbase + (kRowB + nb*16)*144 + (ks*16 + kK8)*2;
                ldmat4(bh[nb], ad);
            }
            #pragma unroll
            for (int mi = 0; mi < 2; mi++)
                #pragma unroll
                for (int nj = 0; nj < 4; nj++) {
                    int nb = nj >> 1, pr = (nj & 1)*2;
                    mma_bf16(S[mi][nj], ah[mi], bh[nb][pr], bh[nb][pr+1]);
                }
        }

        // ---- P = ex2(tanh(S/8)*L2E)*mk -> smem (bf16 hi only) ----
        {
            int r0 = wm*32 + (lane >> 2);
            int c0b = wn*32 + (lane & 3)*2;
            #pragma unroll
            for (int mi = 0; mi < 2; mi++) {
                int row0 = r0 + mi*16, row1 = row0 + 8;
                float mq0 = mqf[row0], mq1 = mqf[row1];
                #pragma unroll
                for (int nj = 0; nj < 4; nj++) {
                    int c0 = c0b + nj*8;
                    float mk0 = mkf[c0], mk1 = mkf[c0+1];
                    float p0 = ex2f(tanh_fast(S[mi][nj][0]*0.125f)*L2E)*mk0;
                    float p1 = ex2f(tanh_fast(S[mi][nj][1]*0.125f)*L2E)*mk1;
                    float p2 = ex2f(tanh_fast(S[mi][nj][2]*0.125f)*L2E)*mk0;
                    float p3 = ex2f(tanh_fast(S[mi][nj][3]*0.125f)*L2E)*mk1;
                    partial += mq0*(p0+p1) + mq1*(p2+p3);
                    *(uint32_t*)(smc + A_PHI + row0*272 + c0*2) = pk2f(p0, p1);
                    *(uint32_t*)(smc + A_PHI + row1*272 + c0*2) = pk2f(p2, p3);
                }
            }
        }
        __syncthreads();
        if (kt < 7) cp_wait<1>();
        else        cp_wait<0>();

        // ---- U += Phi Vhi^T (single product) ----
        #pragma unroll
        for (int ch = 0; ch < 8; ch++) {
            uint32_t ph[4];
            ldmat4(ph, sb + A_PHI + pRow*272 + (ch*16 + pK8)*2);
            #pragma unroll
            for (int g = 0; g < 2; g++) {
                uint32_t vh[4];
                ldmat4(vh, sb + A_VHI + (vRowB + g*16)*272 + (ch*16 + vK8)*2);
                mma_bf16(U[g*2],   ph, vh[0], vh[1]);
                mma_bf16(U[g*2+1], ph, vh[2], vh[3]);
            }
        }
        __syncthreads();
        if (kt + 1 < 8) {
            issue_V(kt+1);
            cp_wait<1>();
            __syncthreads();
        }
    }

    {
        int r = wq*16 + (lane >> 2);
        int cb = wd*32 + (lane & 3)*2;
        float* Ug = g_U + ((size_t)(b*Lz + qt*128))*Ez + h*64;
        #pragma unroll
        for (int dj = 0; dj < 4; dj++) {
            int c = cb + dj*8;
            *(float2*)(Ug + (size_t)r*Ez + c)     = make_float2(U[dj][0], U[dj][1]);
            *(float2*)(Ug + (size_t)(r+8)*Ez + c) = make_float2(U[dj][2], U[dj][3]);
        }
    }

    red[tid] = partial; __syncthreads();
    for (int s = 256; s > 0; s >>= 1) { if (tid < s) red[tid] += red[tid+s]; __syncthreads(); }
    if (tid == 0) g_Spart[(b*Hz + h)*8 + qt] = red[0];
}

// ---------------- host launcher ----------------
extern "C" void kernel_launch(void* const* d_in, const int* in_sizes, int n_in,
                              void* d_out, int out_size) {
    const float* x    = (const float*)d_in[0];
    const void*  mask = d_in[1];
    const float* Wq   = (const float*)d_in[2];
    const float* Wk   = (const float*)d_in[3];
    const float* Wv   = (const float*)d_in[4];
    const float* Wo   = (const float*)d_in[5];
    const float* G    = (const float*)d_in[6];
    float* out = (float*)d_out;

    static bool inited = false;
    static cudaStream_t s2;
    static cudaEvent_t evFork, evQKV, evJoin;
    if (!inited) {
        cudaStreamCreateWithFlags(&s2, cudaStreamNonBlocking);
        cudaEventCreateWithFlags(&evFork, cudaEventDisableTiming);
        cudaEventCreateWithFlags(&evQKV, cudaEventDisableTiming);
        cudaEventCreateWithFlags(&evJoin, cudaEventDisableTiming);
        cudaFuncSetAttribute((const void*)attn_mma,
                             cudaFuncAttributeMaxDynamicSharedMemorySize, AT_SMEM);
        cudaFuncSetAttribute((const void*)qkv_gemm,
                             cudaFuncAttributeMaxDynamicSharedMemorySize, PIPE_SMEM);
        cudaFuncSetAttribute((const void*)gav_gemm,
                             cudaFuncAttributeMaxDynamicSharedMemorySize, PIPE_SMEM);
        cudaFuncSetAttribute((const void*)out_gemm,
                             cudaFuncAttributeMaxDynamicSharedMemorySize, PIPE_SMEM);
        inited = true;
    }

    convert_mask<<<32,256>>>(mask);

    // fork G-softmax chain onto s2 (needs only g_mf)
    cudaEventRecord(evFork, 0);
    cudaStreamWaitEvent(s2, evFork, 0);
    softmax_g<<<1024,256,0,s2>>>(G);
    reduce_g<<<8,256,0,s2>>>();

    // main chain
    split_all<<<(NXS4 + 4*NWS4)/256,256>>>((const float4*)x, (const float4*)Wq,
                                           (const float4*)Wk, (const float4*)Wv,
                                           (const float4*)Wo);
    qkv_gemm<<<dim3(4,64,3),256,PIPE_SMEM>>>();
    cudaEventRecord(evQKV, 0);

    // s2: GAV mainloop overlaps with attention
    cudaStreamWaitEvent(s2, evQKV, 0);
    gav_gemm<<<dim3(4,8,Bz),256,PIPE_SMEM,s2>>>();
    cudaEventRecord(evJoin, s2);

    attn_mma<<<dim3(8,Hz,Bz),512,AT_SMEM>>>();

    cudaStreamWaitEvent(0, evJoin, 0);
    reduce_s<<<8,64>>>();
    prep_out<<<(Bz*Lz*Ez/4 + 255)/256,256>>>();
    out_gemm<<<dim3(4,64),256,PIPE_SMEM>>>(out);
}

// round 17
// speedup vs baseline: 3.5540x; 1.0165x over previous
#include <cuda_runtime.h>
#include <cuda_bf16.h>
#include <float.h>
#include <stdint.h>

#define Bz   8
#define Lz   1024
#define Ez   512
#define Hz   8
#define Dz   64

// ---------------- fast-math helpers ----------------
__device__ __forceinline__ float tanh_fast(float x) {
    float y; asm("tanh.approx.f32 %0, %1;" : "=f"(y) : "f"(x)); return y;
}
__device__ __forceinline__ float ex2f(float x) {
    float y; asm("ex2.approx.f32 %0, %1;" : "=f"(y) : "f"(x)); return y;
}
#define L2E 1.4426950408889634f

__device__ __forceinline__ uint32_t smem_u32(const void* p) {
    uint32_t a;
    asm("{ .reg .u64 t; cvta.to.shared.u64 t, %1; cvt.u32.u64 %0, t; }" : "=r"(a) : "l"(p));
    return a;
}
__device__ __forceinline__ uint32_t pk2f(float lo, float hi) {
    uint32_t r; asm("cvt.rn.bf16x2.f32 %0, %1, %2;" : "=r"(r) : "f"(hi), "f"(lo)); return r;
}
__device__ __forceinline__ float bflo(uint32_t v) { return __uint_as_float(v << 16); }
__device__ __forceinline__ float bfhi(uint32_t v) { return __uint_as_float(v & 0xFFFF0000u); }

// ---------------- mma.sync / cp.async helpers ----------------
__device__ __forceinline__ void ldmat4(uint32_t* r, uint32_t a) {
    asm volatile("ldmatrix.sync.aligned.m8n8.x4.shared.b16 {%0,%1,%2,%3}, [%4];"
                 : "=r"(r[0]), "=r"(r[1]), "=r"(r[2]), "=r"(r[3]) : "r"(a));
}
__device__ __forceinline__ void mma_bf16(float* c, const uint32_t* a, uint32_t b0, uint32_t b1) {
    asm volatile("mma.sync.aligned.m16n8k16.row.col.f32.bf16.bf16.f32 "
                 "{%0,%1,%2,%3}, {%4,%5,%6,%7}, {%8,%9}, {%0,%1,%2,%3};"
                 : "+f"(c[0]), "+f"(c[1]), "+f"(c[2]), "+f"(c[3])
                 : "r"(a[0]), "r"(a[1]), "r"(a[2]), "r"(a[3]), "r"(b0), "r"(b1));
}
__device__ __forceinline__ void cp16(uint32_t s, const void* g) {
    asm volatile("cp.async.cg.shared.global [%0], [%1], 16;" :: "r"(s), "l"(g));
}
__device__ __forceinline__ void cp_commit() { asm volatile("cp.async.commit_group;"); }
template<int N> __device__ __forceinline__ void cp_wait() {
    asm volatile("cp.async.wait_group %0;" :: "n"(N));
}

// ---------------- device scratch ----------------
__device__ float g_mf[Bz*Lz];
__device__ float g_U [Bz*Lz*Ez];
__device__ float g_GAV[Bz*Lz*Ez];
__device__ float g_Spart[Bz*Hz*8];
__device__ float g_Gpart[Bz*Lz];
__device__ float g_gs[Bz];
__device__ float g_S[Bz];

__device__ __nv_bfloat16 g_xhi[Bz*Lz*Ez], g_xlo[Bz*Lz*Ez];
__device__ __nv_bfloat16 g_qhi[Bz*Lz*Ez];
__device__ __nv_bfloat16 g_khi[Bz*Lz*Ez];
__device__ __nv_bfloat16 g_wqhi[Ez*Ez], g_wqlo[Ez*Ez];
__device__ __nv_bfloat16 g_wkhi[Ez*Ez], g_wklo[Ez*Ez];
__device__ __nv_bfloat16 g_wvhi[Ez*Ez], g_wvlo[Ez*Ez];
__device__ __nv_bfloat16 g_wohi[Ez*Ez], g_wolo[Ez*Ez];
__device__ __nv_bfloat16 g_acthi[Lz*Lz], g_actlo[Lz*Lz];
__device__ __nv_bfloat16 g_vthi[Bz*Ez*Lz], g_vtlo[Bz*Ez*Lz];
__device__ __nv_bfloat16 g_aohi[Bz*Lz*Ez], g_aolo[Bz*Lz*Ez];

// ---------------- mask convert (detection fused, per-block) ----------------
__global__ void convert_mask(const void* mv) {
    __shared__ int skind;
    const unsigned char* m = (const unsigned char*)mv;
    if (threadIdx.x == 0) {
        bool isInt32 = true;
        for (int i = 0; i < 64; i++) {
            if (m[4*i] > 1) isInt32 = false;
            if (m[4*i+1] | m[4*i+2] | m[4*i+3]) isInt32 = false;
        }
        int kind;
        if (isInt32) kind = 0;
        else {
            const unsigned int* w = (const unsigned int*)m;
            bool isFloat = true;
            for (int i = 0; i < 64; i++) {
                unsigned v = w[i];
                if (v != 0u && v != 0x3F800000u) isFloat = false;
            }
            kind = isFloat ? 2 : 1;
        }
        skind = kind;
    }
    __syncthreads();
    int i = blockIdx.x*256 + threadIdx.x;
    if (i >= Bz*Lz) return;
    int k = skind;
    float v;
    if (k == 0)      v = ((const int*)mv)[i] ? 1.f : 0.f;
    else if (k == 1) v = m[i] ? 1.f : 0.f;
    else             v = ((const float*)mv)[i];
    g_mf[i] = v;
}

// ---------------- splits: x + 4 weights -> hi/lo (float4 vectorized) ----------------
#define NXS4 (Bz*Lz*Ez/4)
#define NWS4 (Ez*Ez/4)
__global__ void split_all(const float4* __restrict__ x,
                          const float4* __restrict__ wq, const float4* __restrict__ wk,
                          const float4* __restrict__ wv, const float4* __restrict__ wo) {
    int i = blockIdx.x*256 + threadIdx.x;
    const float4* s; uint2 *hp, *lp; int idx;
    if (i < NXS4) { s = x; hp = (uint2*)g_xhi; lp = (uint2*)g_xlo; idx = i; }
    else {
        int j = i - NXS4;
        int w = j >> 16;
        idx = j & (NWS4-1);
        if      (w == 0) { s = wq; hp = (uint2*)g_wqhi; lp = (uint2*)g_wqlo; }
        else if (w == 1) { s = wk; hp = (uint2*)g_wkhi; lp = (uint2*)g_wklo; }
        else if (w == 2) { s = wv; hp = (uint2*)g_wvhi; lp = (uint2*)g_wvlo; }
        else             { s = wo; hp = (uint2*)g_wohi; lp = (uint2*)g_wolo; }
    }
    float4 v = s[idx];
    uint32_t h01 = pk2f(v.x, v.y), h23 = pk2f(v.z, v.w);
    uint32_t l01 = pk2f(v.x - bflo(h01), v.y - bfhi(h01));
    uint32_t l23 = pk2f(v.z - bflo(h23), v.w - bfhi(h23));
    hp[idx] = make_uint2(h01, h23);
    lp[idx] = make_uint2(l01, l23);
}

// ---------------- softmax of G rows -> bf16 hi/lo + fused gsum partials ----------------
__global__ __launch_bounds__(256) void softmax_g(const float* __restrict__ G) {
    int q = blockIdx.x, t = threadIdx.x;
    const float* row = G + (size_t)q*Lz;
    __shared__ float red[256];
    __shared__ float part[8][8];
    float mx = -FLT_MAX;
    for (int k = t; k < Lz; k += 256) mx = fmaxf(mx, row[k]);
    red[t] = mx; __syncthreads();
    for (int s = 128; s > 0; s >>= 1) { if (t < s) red[t] = fmaxf(red[t], red[t+s]); __syncthreads(); }
    mx = red[0]; __syncthreads();
    float vals[4]; float sum = 0.f;
    for (int k = t, j = 0; k < Lz; k += 256, j++) { float e = __expf(row[k]-mx); vals[j] = e; sum += e; }
    red[t] = sum; __syncthreads();
    for (int s = 128; s > 0; s >>= 1) { if (t < s) red[t] += red[t+s]; __syncthreads(); }
    float inv = 1.f / red[0];
    float gs[8] = {};
    for (int k = t, j = 0; k < Lz; k += 256, j++) {
        float v = vals[j]*inv;
        __nv_bfloat16 h = __float2bfloat16(v);
        g_acthi[(size_t)q*Lz + k] = h;
        g_actlo[(size_t)q*Lz + k] = __float2bfloat16(v - __bfloat162float(h));
        #pragma unroll
        for (int b2 = 0; b2 < 8; b2++) gs[b2] += v * __ldg(g_mf + b2*Lz + k);
    }
    #pragma unroll
    for (int o = 16; o; o >>= 1)
        #pragma unroll
        for (int b2 = 0; b2 < 8; b2++) gs[b2] += __shfl_down_sync(0xffffffffu, gs[b2], o);
    if ((t & 31) == 0)
        #pragma unroll
        for (int b2 = 0; b2 < 8; b2++) part[t>>5][b2] = gs[b2];
    __syncthreads();
    if (t < 8) {
        float r = 0.f;
        #pragma unroll
        for (int w = 0; w < 8; w++) r += part[w][t];
        g_Gpart[t*Lz + q] = r * __ldg(g_mf + t*Lz + q);
    }
}

__global__ __launch_bounds__(256) void reduce_g() {
    int b = blockIdx.x, t = threadIdx.x;
    __shared__ float red[256];
    float s = 0.f;
    for (int i = t; i < Lz; i += 256) s += g_Gpart[b*Lz + i];
    red[t] = s; __syncthreads();
    for (int st = 128; st > 0; st >>= 1) { if (t < st) red[t] += red[t+st]; __syncthreads(); }
    if (t == 0) g_gs[b] = red[0];
}

__global__ __launch_bounds__(64) void reduce_s() {
    int b = blockIdx.x, t = threadIdx.x;
    __shared__ float red[64];
    float s = (t < Hz*8) ? g_Spart[b*Hz*8 + t] : 0.f;
    red[t] = s; __syncthreads();
    for (int st = 32; st > 0; st >>= 1) { if (t < st) red[t] += red[t+st]; __syncthreads(); }
    if (t == 0) g_S[b] = red[0];
}

// aout = (0.5 mf/S)*U + (0.5 mf/gs)*GAV -> bf16 hi/lo (rowscales fused)
__global__ void prep_out() {
    int i = blockIdx.x*256 + threadIdx.x;
    if (i >= Bz*Lz*Ez/4) return;
    int row = i >> 7;
    int b = row >> 10;
    const float TINY = 1.175494351e-38f;
    float mf = g_mf[row];
    float rs0 = 0.5f*mf / fmaxf(g_S[b],  TINY);
    float rs1 = 0.5f*mf / fmaxf(g_gs[b], TINY);
    float4 u = ((const float4*)g_U)[i];
    float4 g = ((const float4*)g_GAV)[i];
    float v0 = rs0*u.x + rs1*g.x;
    float v1 = rs0*u.y + rs1*g.y;
    float v2 = rs0*u.z + rs1*g.z;
    float v3 = rs0*u.w + rs1*g.w;
    uint32_t h01 = pk2f(v0, v1), h23 = pk2f(v2, v3);
    uint32_t l01 = pk2f(v0 - bflo(h01), v1 - bfhi(h01));
    uint32_t l23 = pk2f(v2 - bflo(h23), v3 - bfhi(h23));
    ((uint2*)g_aohi)[i] = make_uint2(h01, h23);
    ((uint2*)g_aolo)[i] = make_uint2(l01, l23);
}

// ---------------- pipelined HMMA GEMM mainloop (3-product) ----------------
#define T_ALO 10240
#define T_BHI 20480
#define T_BLO 30720
#define BUFSZ 40960
#define PIPE_SMEM (2*BUFSZ)

__device__ __forceinline__ void gemm_main(
    char* smc, uint32_t sb,
    const __nv_bfloat16* Ahi, const __nv_bfloat16* Alo,
    const __nv_bfloat16* Bhi, const __nv_bfloat16* Blo,
    int K, int bm, int bn, float acc[4][4][4])
{
    int tid = threadIdx.x, lane = tid & 31, wid = tid >> 5;
    int wm = wid & 1, wn = wid >> 1;
    const char* pAh = (const char*)(Ahi + (size_t)bm*K);
    const char* pAl = (const char*)(Alo + (size_t)bm*K);
    const char* pBh = (const char*)(Bhi + (size_t)bn*K);
    const char* pBl = (const char*)(Blo + (size_t)bn*K);

    uint32_t aRow = wm*64 + (lane & 15);
    uint32_t aK8  = (lane >> 4) * 8;
    uint32_t bRow = wn*32 + (lane & 7) + ((lane >> 4) << 3);
    uint32_t bK8  = ((lane >> 3) & 1) * 8;

    int nChunks = K >> 5;

    auto load_chunk = [&](int kc, int bsel) {
        uint32_t base = sb + bsel*BUFSZ;
        #pragma unroll
        for (int i = tid; i < 512; i += 256) {
            int r = i >> 2, c = i & 3;
            size_t go = (size_t)r*K*2 + (size_t)kc*64 + c*16;
            uint32_t so = r*80 + c*16;
            cp16(base + so,          pAh + go);
            cp16(base + T_ALO + so,  pAl + go);
            cp16(base + T_BHI + so,  pBh + go);
            cp16(base + T_BLO + so,  pBl + go);
        }
        cp_commit();
    };

    load_chunk(0, 0);

    for (int kc = 0; kc < nChunks; kc++) {
        __syncthreads();
        if (kc + 1 < nChunks) { load_chunk(kc+1, (kc+1)&1); cp_wait<1>(); }
        else                  { cp_wait<0>(); }
        __syncthreads();
        uint32_t bofs = sb + (kc&1)*BUFSZ;
        #pragma unroll
        for (int ks = 0; ks < 2; ks++) {
            uint32_t ah[4][4], al[4][4], bh[2][4], bl[2][4];
            #pragma unroll
            for (int mi = 0; mi < 4; mi++) {
                uint32_t ad = bofs + ((aRow + mi*16)*40 + ks*16 + aK8)*2;
                ldmat4(ah[mi], ad);
                ldmat4(al[mi], ad + T_ALO);
            }
            #pragma unroll
            for (int bj = 0; bj < 2; bj++) {
                uint32_t ad = bofs + T_BHI + ((bRow + bj*16)*40 + ks*16 + bK8)*2;
                ldmat4(bh[bj], ad);
                ldmat4(bl[bj], ad + (T_BLO - T_BHI));
            }
            #pragma unroll
            for (int mi = 0; mi < 4; mi++)
                #pragma unroll
                for (int nj = 0; nj < 4; nj++) {
                    int bj = nj >> 1, pr = (nj & 1)*2;
                    mma_bf16(acc[mi][nj], ah[mi], bh[bj][pr], bh[bj][pr+1]);
                    mma_bf16(acc[mi][nj], ah[mi], bl[bj][pr], bl[bj][pr+1]);
                    mma_bf16(acc[mi][nj], al[mi], bh[bj][pr], bh[bj][pr+1]);
                }
        }
    }
}

// fused QKV (3-product): z=0 -> Q (bf16 hi), z=1 -> K (bf16 hi), z=2 -> masked+transposed V split
__global__ __launch_bounds__(256, 1) void qkv_gemm() {
    extern __shared__ char smc[];
    uint32_t sb = smem_u32(smc);
    int z = blockIdx.z;
    int bm = blockIdx.y*128, bn = blockIdx.x*128;
    const __nv_bfloat16 *Bh, *Bl;
    if      (z == 0) { Bh = g_wqhi; Bl = g_wqlo; }
    else if (z == 1) { Bh = g_wkhi; Bl = g_wklo; }
    else             { Bh = g_wvhi; Bl = g_wvlo; }
    float acc[4][4][4] = {};
    gemm_main(smc, sb, g_xhi, g_xlo, Bh, Bl, Ez, bm, bn, acc);

    int lane = threadIdx.x & 31, wid = threadIdx.x >> 5;
    int wm = wid & 1, wn = wid >> 1;
    int r0l = wm*64 + (lane >> 2);
    int c0l = wn*32 + (lane & 3)*2;

    if (z < 2) {
        __nv_bfloat16* Ch = (z == 0) ? g_qhi : g_khi;
        #pragma unroll
        for (int mi = 0; mi < 4; mi++)
            #pragma unroll
            for (int nj = 0; nj < 4; nj++) {
                int r = bm + r0l + mi*16, c = bn + c0l + nj*8;
                *(uint32_t*)(Ch + (size_t)r*Ez + c)     = pk2f(acc[mi][nj][0], acc[mi][nj][1]);
                *(uint32_t*)(Ch + (size_t)(r+8)*Ez + c) = pk2f(acc[mi][nj][2], acc[mi][nj][3]);
            }
    } else {
        __syncthreads();
        #pragma unroll
        for (int mi = 0; mi < 4; mi++) {
            int r = r0l + mi*16;
            float m0 = g_mf[bm + r], m1 = g_mf[bm + r + 8];
            #pragma unroll
            for (int nj = 0; nj < 4; nj++) {
                int c = c0l + nj*8;
                #pragma unroll
                for (int e2 = 0; e2 < 2; e2++) {
                    float v0 = acc[mi][nj][e2]   * m0;
                    float v1 = acc[mi][nj][2+e2] * m1;
                    __nv_bfloat16 h0 = __float2bfloat16(v0);
                    __nv_bfloat16 h1 = __float2bfloat16(v1);
                    __nv_bfloat16 l0 = __float2bfloat16(v0 - __bfloat162float(h0));
                    __nv_bfloat16 l1 = __float2bfloat16(v1 - __bfloat162float(h1));
                    uint32_t o0 = (c+e2)*272 + r*2;
                    uint32_t o1 = (c+e2)*272 + (r+8)*2;
                    *(__nv_bfloat16*)(smc + o0) = h0;
                    *(__nv_bfloat16*)(smc + o1) = h1;
                    *(__nv_bfloat16*)(smc + BUFSZ + o0) = l0;
                    *(__nv_bfloat16*)(smc + BUFSZ + o1) = l1;
                }
            }
        }
        __syncthreads();
        int b = bm >> 10;
        int l0g = bm & 1023;
        for (int i = threadIdx.x; i < 2048; i += 256) {
            int e = i >> 4, l8 = (i & 15)*8;
            size_t go = ((size_t)b*Ez + bn + e)*Lz + l0g + l8;
            *(uint4*)(g_vthi + go) = *(const uint4*)(smc + e*272 + l8*2);
            *(uint4*)(g_vtlo + go) = *(const uint4*)(smc + BUFSZ + e*272 + l8*2);
        }
    }
}

// GAV plain GEMM (3-product, fp32 out) — on stream2 concurrent with attention
__global__ __launch_bounds__(256, 1) void gav_gemm() {
    extern __shared__ char smc[];
    uint32_t sb = smem_u32(smc);
    int z = blockIdx.z;
    int bm = blockIdx.y*128, bn = blockIdx.x*128;
    float acc[4][4][4] = {};
    gemm_main(smc, sb, g_acthi, g_actlo,
              g_vthi + (size_t)z*Ez*Lz, g_vtlo + (size_t)z*Ez*Lz,
              Lz, bm, bn, acc);

    int lane = threadIdx.x & 31, wid = threadIdx.x >> 5;
    int wm = wid & 1, wn = wid >> 1;
    int r0 = bm + wm*64 + (lane >> 2);
    int c0 = bn + wn*32 + (lane & 3)*2;
    float* Cp = g_GAV + (size_t)z*Lz*Ez;
    #pragma unroll
    for (int mi = 0; mi < 4; mi++)
        #pragma unroll
        for (int nj = 0; nj < 4; nj++) {
            float* p = Cp + (size_t)(r0 + mi*16)*Ez + c0 + nj*8;
            *(float2*)p                  = make_float2(acc[mi][nj][0], acc[mi][nj][1]);
            *(float2*)(p + (size_t)8*Ez) = make_float2(acc[mi][nj][2], acc[mi][nj][3]);
        }
}

// out = Aout @ Wo^T (3-product, fp32 epilogue)
__global__ __launch_bounds__(256, 1) void out_gemm(float* __restrict__ C) {
    extern __shared__ char smc[];
    uint32_t sb = smem_u32(smc);
    int bm = blockIdx.y*128, bn = blockIdx.x*128;
    float acc[4][4][4] = {};
    gemm_main(smc, sb, g_aohi, g_aolo, g_wohi, g_wolo, Ez, bm, bn, acc);

    int lane = threadIdx.x & 31, wid = threadIdx.x >> 5;
    int wm = wid & 1, wn = wid >> 1;
    int r0 = bm + wm*64 + (lane >> 2);
    int c0 = bn + wn*32 + (lane & 3)*2;
    #pragma unroll
    for (int mi = 0; mi < 4; mi++)
        #pragma unroll
        for (int nj = 0; nj < 4; nj++) {
            float* p = C + (size_t)(r0 + mi*16)*Ez + c0 + nj*8;
            *(float2*)p                  = make_float2(acc[mi][nj][0], acc[mi][nj][1]);
            *(float2*)(p + (size_t)8*Ez) = make_float2(acc[mi][nj][2], acc[mi][nj][3]);
        }
}

// ---------------- attention: S = Qhi Khi^T, PV = Phi Vhi^T; compacted smem, 2 CTAs/SM ----------------
#define A_QHI 0
#define A_K0  18432
#define A_KBUF 18432
#define A_VHI 55296
#define A_PHI 72704
#define A_MQ  107520
#define A_MK  108032
#define A_RED 109056
#define AT_SMEM (109056 + 2048)

__global__ __launch_bounds__(512, 2) void attn_mma() {
    extern __shared__ char smc[];
    uint32_t sb = smem_u32(smc);
    float* mqf = (float*)(smc + A_MQ);
    float* red = (float*)(smc + A_RED);

    int tid = threadIdx.x, lane = tid & 31, wid = tid >> 5;
    int qt = blockIdx.x, h = blockIdx.y, b = blockIdx.z;

    int wm = wid & 3, wn = wid >> 2;
    int wq = wid & 7, wd = wid >> 3;

    const __nv_bfloat16* Qh = g_qhi + ((size_t)(b*Lz + qt*128))*Ez + h*64;
    const __nv_bfloat16* Kh = g_khi + ((size_t)(b*Lz))*Ez + h*64;
    const __nv_bfloat16* Vth = g_vthi + ((size_t)(b*Ez + h*64))*Lz;

    auto issue_K = [&](int kt, int bsel) {
        uint32_t base = sb + A_K0 + bsel*A_KBUF;
        #pragma unroll
        for (int i = tid; i < 1024; i += 512) {
            int r = i >> 3, c8 = (i & 7)*8;
            cp16(base + r*144 + c8*2, Kh + (size_t)(kt*128 + r)*Ez + c8);
        }
        if (tid < 32) cp16(sb + A_MK + bsel*512 + tid*16, g_mf + b*Lz + kt*128 + tid*4);
        cp_commit();
    };
    auto issue_V = [&](int kt) {
        #pragma unroll
        for (int i = tid; i < 1024; i += 512) {
            int r = i >> 4, c8 = (i & 15)*8;
            cp16(sb + A_VHI + r*272 + c8*2, Vth + (size_t)r*Lz + kt*128 + c8);
        }
        cp_commit();
    };

    // Q hi only
    for (int i = tid; i < 1024; i += 512) {
        int r = i >> 3, c8 = (i & 7)*8;
        *(uint4*)(smc + A_QHI + r*144 + c8*2) = *(const uint4*)(Qh + (size_t)r*Ez + c8);
    }
    if (tid < 128) mqf[tid] = g_mf[b*Lz + qt*128 + tid];

    issue_K(0, 0);
    issue_V(0);

    uint32_t qRow = wm*32 + (lane & 15);
    uint32_t qK8  = (lane >> 4)*8;
    uint32_t kRowB = wn*32 + (lane & 7) + ((lane >> 4) << 3);
    uint32_t kK8  = ((lane >> 3) & 1)*8;
    uint32_t pRow = wq*16 + (lane & 15);
    uint32_t pK8  = (lane >> 4)*8;
    uint32_t vRowB = wd*32 + (lane & 7) + ((lane >> 4) << 3);
    uint32_t vK8  = ((lane >> 3) & 1)*8;

    float U[4][4] = {};
    float partial = 0.f;

    cp_wait<0>();
    __syncthreads();

    for (int kt = 0; kt < 8; kt++) {
        if (kt + 1 < 8) issue_K(kt+1, (kt+1)&1);

        uint32_t kbase = sb + A_K0 + (kt&1)*A_KBUF;
        const float* mkf = (const float*)(smc + A_MK + (kt&1)*512);

        // ---- S = Qhi Khi^T (single product) ----
        float S[2][4][4] = {};
        #pragma unroll
        for (int ks = 0; ks < 4; ks++) {
            uint32_t ah[2][4], bh[2][4];
            #pragma unroll
            for (int mi = 0; mi < 2; mi++) {
                uint32_t ad = sb + A_QHI + (qRow + mi*16)*144 + (ks*16 + qK8)*2;
                ldmat4(ah[mi], ad);
            }
            #pragma unroll
            for (int nb = 0; nb < 2; nb++) {
                uint32_t ad = kbase + (kRowB + nb*16)*144 + (ks*16 + kK8)*2;
                ldmat4(bh[nb], ad);
            }
            #pragma unroll
            for (int mi = 0; mi < 2; mi++)
                #pragma unroll
                for (int nj = 0; nj < 4; nj++) {
                    int nb = nj >> 1, pr = (nj & 1)*2;
                    mma_bf16(S[mi][nj], ah[mi], bh[nb][pr], bh[nb][pr+1]);
                }
        }

        // ---- P = ex2(tanh(S/8)*L2E)*mk -> smem (bf16 hi only) ----
        {
            int r0 = wm*32 + (lane >> 2);
            int c0b = wn*32 + (lane & 3)*2;
            #pragma unroll
            for (int mi = 0; mi < 2; mi++) {
                int row0 = r0 + mi*16, row1 = row0 + 8;
                float mq0 = mqf[row0], mq1 = mqf[row1];
                #pragma unroll
                for (int nj = 0; nj < 4; nj++) {
                    int c0 = c0b + nj*8;
                    float mk0 = mkf[c0], mk1 = mkf[c0+1];
                    float p0 = ex2f(tanh_fast(S[mi][nj][0]*0.125f)*L2E)*mk0;
                    float p1 = ex2f(tanh_fast(S[mi][nj][1]*0.125f)*L2E)*mk1;
                    float p2 = ex2f(tanh_fast(S[mi][nj][2]*0.125f)*L2E)*mk0;
                    float p3 = ex2f(tanh_fast(S[mi][nj][3]*0.125f)*L2E)*mk1;
                    partial += mq0*(p0+p1) + mq1*(p2+p3);
                    *(uint32_t*)(smc + A_PHI + row0*272 + c0*2) = pk2f(p0, p1);
                    *(uint32_t*)(smc + A_PHI + row1*272 + c0*2) = pk2f(p2, p3);
                }
            }
        }
        __syncthreads();
        if (kt < 7) cp_wait<1>();
        else        cp_wait<0>();

        // ---- U += Phi Vhi^T (single product) ----
        #pragma unroll
        for (int ch = 0; ch < 8; ch++) {
            uint32_t ph[4];
            ldmat4(ph, sb + A_PHI + pRow*272 + (ch*16 + pK8)*2);
            #pragma unroll
            for (int g = 0; g < 2; g++) {
                uint32_t vh[4];
                ldmat4(vh, sb + A_VHI + (vRowB + g*16)*272 + (ch*16 + vK8)*2);
                mma_bf16(U[g*2],   ph, vh[0], vh[1]);
                mma_bf16(U[g*2+1], ph, vh[2], vh[3]);
            }
        }
        __syncthreads();
        if (kt + 1 < 8) {
            issue_V(kt+1);
            cp_wait<1>();
            __syncthreads();
        }
    }

    {
        int r = wq*16 + (lane >> 2);
        int cb = wd*32 + (lane & 3)*2;
        float* Ug = g_U + ((size_t)(b*Lz + qt*128))*Ez + h*64;
        #pragma unroll
        for (int dj = 0; dj < 4; dj++) {
            int c = cb + dj*8;
            *(float2*)(Ug + (size_t)r*Ez + c)     = make_float2(U[dj][0], U[dj][1]);
            *(float2*)(Ug + (size_t)(r+8)*Ez + c) = make_float2(U[dj][2], U[dj][3]);
        }
    }

    red[tid] = partial; __syncthreads();
    for (int s = 256; s > 0; s >>= 1) { if (tid < s) red[tid] += red[tid+s]; __syncthreads(); }
    if (tid == 0) g_Spart[(b*Hz + h)*8 + qt] = red[0];
}

// ---------------- host launcher ----------------
extern "C" void kernel_launch(void* const* d_in, const int* in_sizes, int n_in,
                              void* d_out, int out_size) {
    const float* x    = (const float*)d_in[0];
    const void*  mask = d_in[1];
    const float* Wq   = (const float*)d_in[2];
    const float* Wk   = (const float*)d_in[3];
    const float* Wv   = (const float*)d_in[4];
    const float* Wo   = (const float*)d_in[5];
    const float* G    = (const float*)d_in[6];
    float* out = (float*)d_out;

    static bool inited = false;
    static cudaStream_t s2;
    static cudaEvent_t evFork, evQKV, evJoin;
    if (!inited) {
        cudaStreamCreateWithFlags(&s2, cudaStreamNonBlocking);
        cudaEventCreateWithFlags(&evFork, cudaEventDisableTiming);
        cudaEventCreateWithFlags(&evQKV, cudaEventDisableTiming);
        cudaEventCreateWithFlags(&evJoin, cudaEventDisableTiming);
        cudaFuncSetAttribute((const void*)attn_mma,
                             cudaFuncAttributeMaxDynamicSharedMemorySize, AT_SMEM);
        cudaFuncSetAttribute((const void*)qkv_gemm,
                             cudaFuncAttributeMaxDynamicSharedMemorySize, PIPE_SMEM);
        cudaFuncSetAttribute((const void*)gav_gemm,
                             cudaFuncAttributeMaxDynamicSharedMemorySize, PIPE_SMEM);
        cudaFuncSetAttribute((const void*)out_gemm,
                             cudaFuncAttributeMaxDynamicSharedMemorySize, PIPE_SMEM);
        inited = true;
    }

    convert_mask<<<32,256>>>(mask);

    // fork G-softmax chain onto s2 (needs only g_mf)
    cudaEventRecord(evFork, 0);
    cudaStreamWaitEvent(s2, evFork, 0);
    softmax_g<<<1024,256,0,s2>>>(G);
    reduce_g<<<8,256,0,s2>>>();

    // main chain
    split_all<<<(NXS4 + 4*NWS4)/256,256>>>((const float4*)x, (const float4*)Wq,
                                           (const float4*)Wk, (const float4*)Wv,
                                           (const float4*)Wo);
    qkv_gemm<<<dim3(4,64,3),256,PIPE_SMEM>>>();
    cudaEventRecord(evQKV, 0);

    // s2: GAV mainloop overlaps with attention
    cudaStreamWaitEvent(s2, evQKV, 0);
    gav_gemm<<<dim3(4,8,Bz),256,PIPE_SMEM,s2>>>();
    cudaEventRecord(evJoin, s2);

    attn_mma<<<dim3(8,Hz,Bz),512,AT_SMEM>>>();

    cudaStreamWaitEvent(0, evJoin, 0);
    reduce_s<<<8,64>>>();
    prep_out<<<(Bz*Lz*Ez/4 + 255)/256,256>>>();
    out_gemm<<<dim3(4,64),256,PIPE_SMEM>>>(out);
}